// round 1
// baseline (speedup 1.0000x reference)
#include <cuda_runtime.h>
#include <cuda_bf16.h>
#include <math.h>

// ---------------- problem constants ----------------
#define BATCH   2
#define SEQ     2048
#define NTOK    (BATCH * SEQ)        // 4096
#define DMODEL  2048
#define HEADS   16
#define DQK     192                  // NOPE + ROPE
#define DNOPE   128
#define DROPE   64
#define DV      128
#define DQA     1536
#define DKVA    576                  // 512 + 64
#define DKVLAT  512
#define QDIM    (HEADS * DQK)        // 3072
#define KVDIM   (HEADS * (DNOPE + DV)) // 4096
#define ODIM    (HEADS * DV)         // 2048
#define ATT_SCALE 0.07216878364870322f  // 192^-0.5

// ---------------- scratch (device globals; no allocation allowed) ----------
__device__ float g_qa  [(size_t)NTOK * DQA];     // q_a output / normed (in place)
__device__ float g_ckv [(size_t)NTOK * DKVA];    // kv_a output; rope slice roped in place
__device__ float g_kvn [(size_t)NTOK * DKVLAT];  // rmsnormed latent kv
__device__ float g_q   [(size_t)NTOK * QDIM];    // q_b output; rope slices roped in place
__device__ float g_kv  [(size_t)NTOK * KVDIM];   // kv_b output (k_pass | v per head)
__device__ float g_attn[(size_t)NTOK * ODIM];    // attention output [tok][h*128+d]

// ---------------- SGEMM: C[M,N] = A[M,K] @ B[N,K]^T (both row-major) -------
#define GBM 128
#define GBN 128
#define GBK 16

__global__ __launch_bounds__(256) void sgemm_nt(
    const float* __restrict__ A, const float* __restrict__ Bw,
    float* __restrict__ C, int M, int N, int K)
{
    __shared__ float As[GBK][GBM + 4];
    __shared__ float Bs[GBK][GBN + 4];
    const int bm = blockIdx.y * GBM;
    const int bn = blockIdx.x * GBN;
    const int tid = threadIdx.x;
    const int tx = tid & 15, ty = tid >> 4;

    float acc[8][8];
#pragma unroll
    for (int i = 0; i < 8; i++)
#pragma unroll
        for (int j = 0; j < 8; j++) acc[i][j] = 0.f;

    for (int k0 = 0; k0 < K; k0 += GBK) {
#pragma unroll
        for (int t = 0; t < 2; t++) {
            int idx = tid + t * 256;       // 0..511
            int row = idx >> 2;            // 0..127
            int kq  = (idx & 3) << 2;      // 0,4,8,12
            float4 a = *(const float4*)(A + (size_t)(bm + row) * K + k0 + kq);
            As[kq + 0][row] = a.x; As[kq + 1][row] = a.y;
            As[kq + 2][row] = a.z; As[kq + 3][row] = a.w;
            int nrow = bn + row;
            float4 b = make_float4(0.f, 0.f, 0.f, 0.f);
            if (nrow < N) b = *(const float4*)(Bw + (size_t)nrow * K + k0 + kq);
            Bs[kq + 0][row] = b.x; Bs[kq + 1][row] = b.y;
            Bs[kq + 2][row] = b.z; Bs[kq + 3][row] = b.w;
        }
        __syncthreads();
#pragma unroll
        for (int kk = 0; kk < GBK; kk++) {
            float a[8], b[8];
            *(float4*)&a[0] = *(const float4*)&As[kk][ty * 8];
            *(float4*)&a[4] = *(const float4*)&As[kk][ty * 8 + 4];
            *(float4*)&b[0] = *(const float4*)&Bs[kk][tx * 8];
            *(float4*)&b[4] = *(const float4*)&Bs[kk][tx * 8 + 4];
#pragma unroll
            for (int i = 0; i < 8; i++)
#pragma unroll
                for (int j = 0; j < 8; j++)
                    acc[i][j] = fmaf(a[i], b[j], acc[i][j]);
        }
        __syncthreads();
    }
#pragma unroll
    for (int i = 0; i < 8; i++) {
        int row = bm + ty * 8 + i;
#pragma unroll
        for (int j = 0; j < 8; j += 4) {
            int col = bn + tx * 8 + j;
            if (col + 3 < N) {
                float4 v = make_float4(acc[i][j], acc[i][j + 1], acc[i][j + 2], acc[i][j + 3]);
                *(float4*)(C + (size_t)row * N + col) = v;
            } else {
#pragma unroll
                for (int jj = 0; jj < 4; jj++)
                    if (col + jj < N) C[(size_t)row * N + col + jj] = acc[i][j + jj];
            }
        }
    }
}

// ---------------- RMSNorm: one block per row ------------------------------
__global__ __launch_bounds__(256) void rmsnorm_kernel(
    const float* __restrict__ in, float* __restrict__ out,
    const float* __restrict__ w, int N, int in_stride, int out_stride)
{
    const int row = blockIdx.x;
    const float* x = in + (size_t)row * in_stride;
    const int cnt = N >> 8;   // N/256: 6 or 2
    float v[6];
    float ss = 0.f;
    for (int i = 0; i < cnt; i++) {
        v[i] = x[threadIdx.x + (i << 8)];
        ss += v[i] * v[i];
    }
#pragma unroll
    for (int o = 16; o > 0; o >>= 1) ss += __shfl_xor_sync(0xffffffffu, ss, o);
    __shared__ float red[8];
    if ((threadIdx.x & 31) == 0) red[threadIdx.x >> 5] = ss;
    __syncthreads();
    float tot = 0.f;
#pragma unroll
    for (int i = 0; i < 8; i++) tot += red[i];
    const float r = rsqrtf(tot / (float)N + 1e-6f);
    float* y = out + (size_t)row * out_stride;
    for (int i = 0; i < cnt; i++) {
        int c = threadIdx.x + (i << 8);
        y[c] = w[c] * v[i] * r;
    }
}

// ---------------- RoPE (in place on q rot-slices and ckv rot slice) -------
__global__ __launch_bounds__(512) void rope_kernel(
    float* __restrict__ q, float* __restrict__ ckv,
    const float* __restrict__ cosb, const float* __restrict__ sinb)
{
    const int tok = blockIdx.x;
    const int t = threadIdx.x;
    const int h = t >> 5;
    const int d = t & 31;
    const float c0 = cosb[(size_t)tok * DROPE + d];
    const float s0 = sinb[(size_t)tok * DROPE + d];
    const float c1 = cosb[(size_t)tok * DROPE + d + 32];
    const float s1 = sinb[(size_t)tok * DROPE + d + 32];
    {
        float* qr = q + (size_t)tok * QDIM + h * DQK + DNOPE;
        float a = qr[d], b = qr[d + 32];
        qr[d]      = a * c0 - b * s0;
        qr[d + 32] = b * c1 + a * s1;
    }
    if (t < 32) {
        float* kr = ckv + (size_t)tok * DKVA + DKVLAT;
        float a = kr[d], b = kr[d + 32];
        kr[d]      = a * c0 - b * s0;
        kr[d + 32] = b * c1 + a * s1;
    }
}

// ---------------- Flash attention (causal, fp32, online softmax) ----------
#define FBM 64
#define FBN 64
#define QSTR 196     // 192 + 4 pad (16B-aligned rows, bank offset 4)
#define VSTR 132
#define PSTR 65

extern __shared__ float fsmem[];

__global__ __launch_bounds__(256) void flash_kernel(
    const float* __restrict__ q, const float* __restrict__ kvbuf,
    const float* __restrict__ ckv, float* __restrict__ attn_out)
{
    float* sQ = fsmem;                   // 64 x 196
    float* sK = sQ + FBM * QSTR;         // 64 x 196
    float* sV = sK + FBN * QSTR;         // 64 x 132
    float* sP = sV + FBN * VSTR;         // 64 x 65

    const int qt = blockIdx.x;
    const int h  = blockIdx.y;
    const int b  = blockIdx.z;
    const int q0 = qt * FBM;
    const int tid = threadIdx.x;
    const int tx = tid & 15, ty = tid >> 4;

    // Q tile, pre-scaled (rope slice already rotated in place)
    const size_t qbase = ((size_t)(b * SEQ + q0)) * QDIM + (size_t)h * DQK;
    for (int e = tid; e < FBM * DQK; e += 256) {
        int r = e / DQK, c = e - r * DQK;
        sQ[r * QSTR + c] = q[qbase + (size_t)r * QDIM + c] * ATT_SCALE;
    }

    float m_i[4], l_i[4], o[4][8];
#pragma unroll
    for (int i = 0; i < 4; i++) {
        m_i[i] = -1e30f; l_i[i] = 0.f;
#pragma unroll
        for (int j = 0; j < 8; j++) o[i][j] = 0.f;
    }

    for (int kt = 0; kt <= qt; kt++) {
        __syncthreads();   // previous PV done; smem free (also covers Q-load visibility path)
        const size_t kvb = ((size_t)(b * SEQ + kt * FBN)) * KVDIM + (size_t)h * (DNOPE + DV);
        const size_t ckb = ((size_t)(b * SEQ + kt * FBN)) * DKVA + DKVLAT;
        for (int e = tid; e < FBN * DQK; e += 256) {
            int r = e / DQK, c = e - r * DQK;
            float v;
            if (c < DNOPE) v = kvbuf[kvb + (size_t)r * KVDIM + c];
            else           v = ckv[ckb + (size_t)r * DKVA + (c - DNOPE)];
            sK[r * QSTR + c] = v;
        }
        for (int e = tid; e < FBN * DV; e += 256) {
            int r = e >> 7, c = e & 127;
            sV[r * VSTR + c] = kvbuf[kvb + (size_t)r * KVDIM + DNOPE + c];
        }
        __syncthreads();

        // scores S = Q K^T  (each thread 4x4; rows ty+16i, cols tx+16j)
        float s[4][4];
#pragma unroll
        for (int i = 0; i < 4; i++)
#pragma unroll
            for (int j = 0; j < 4; j++) s[i][j] = 0.f;

#pragma unroll 4
        for (int d = 0; d < DQK; d += 4) {
            float4 qv[4], kv4[4];
#pragma unroll
            for (int i = 0; i < 4; i++)
                qv[i] = *(const float4*)&sQ[(ty + 16 * i) * QSTR + d];
#pragma unroll
            for (int j = 0; j < 4; j++)
                kv4[j] = *(const float4*)&sK[(tx + 16 * j) * QSTR + d];
#pragma unroll
            for (int i = 0; i < 4; i++)
#pragma unroll
                for (int j = 0; j < 4; j++) {
                    s[i][j] = fmaf(qv[i].x, kv4[j].x, s[i][j]);
                    s[i][j] = fmaf(qv[i].y, kv4[j].y, s[i][j]);
                    s[i][j] = fmaf(qv[i].z, kv4[j].z, s[i][j]);
                    s[i][j] = fmaf(qv[i].w, kv4[j].w, s[i][j]);
                }
        }

        if (kt == qt) {   // causal mask on diagonal tile (global offsets equal)
#pragma unroll
            for (int i = 0; i < 4; i++)
#pragma unroll
                for (int j = 0; j < 4; j++)
                    if (tx + 16 * j > ty + 16 * i) s[i][j] = -1e30f;
        }

        // online softmax update (row groups = 16 lanes sharing ty)
#pragma unroll
        for (int i = 0; i < 4; i++) {
            float mx = fmaxf(fmaxf(s[i][0], s[i][1]), fmaxf(s[i][2], s[i][3]));
#pragma unroll
            for (int o_ = 1; o_ < 16; o_ <<= 1)
                mx = fmaxf(mx, __shfl_xor_sync(0xffffffffu, mx, o_));
            const float mnew = fmaxf(m_i[i], mx);
            const float scale = __expf(m_i[i] - mnew);
            float rs = 0.f;
#pragma unroll
            for (int j = 0; j < 4; j++) {
                float p = __expf(s[i][j] - mnew);
                s[i][j] = p;
                rs += p;
            }
#pragma unroll
            for (int o_ = 1; o_ < 16; o_ <<= 1)
                rs += __shfl_xor_sync(0xffffffffu, rs, o_);
            l_i[i] = l_i[i] * scale + rs;
            m_i[i] = mnew;
#pragma unroll
            for (int j = 0; j < 8; j++) o[i][j] *= scale;
#pragma unroll
            for (int j = 0; j < 4; j++)
                sP[(ty + 16 * i) * PSTR + tx + 16 * j] = s[i][j];
        }
        __syncthreads();

        // O += P @ V  (rows ty+16i, cols tx+16j)
#pragma unroll 2
        for (int kk = 0; kk < FBN; kk++) {
            float pv[4];
#pragma unroll
            for (int i = 0; i < 4; i++) pv[i] = sP[(ty + 16 * i) * PSTR + kk];
#pragma unroll
            for (int j = 0; j < 8; j++) {
                float vv = sV[kk * VSTR + tx + 16 * j];
#pragma unroll
                for (int i = 0; i < 4; i++) o[i][j] = fmaf(pv[i], vv, o[i][j]);
            }
        }
    }

    const size_t obase = ((size_t)(b * SEQ + q0)) * ODIM + (size_t)h * DV;
#pragma unroll
    for (int i = 0; i < 4; i++) {
        const float inv = 1.f / l_i[i];
#pragma unroll
        for (int j = 0; j < 8; j++)
            attn_out[obase + (size_t)(ty + 16 * i) * ODIM + tx + 16 * j] = o[i][j] * inv;
    }
}

// ---------------- launch ---------------------------------------------------
extern "C" void kernel_launch(void* const* d_in, const int* in_sizes, int n_in,
                              void* d_out, int out_size)
{
    (void)in_sizes; (void)n_in; (void)out_size;
    const float* hidden  = (const float*)d_in[0];
    const float* cosb    = (const float*)d_in[1];
    const float* sinb    = (const float*)d_in[2];
    const float* q_a_W   = (const float*)d_in[3];
    const float* q_a_nw  = (const float*)d_in[4];
    const float* q_b_W   = (const float*)d_in[5];
    const float* kv_a_W  = (const float*)d_in[6];
    const float* kv_a_nw = (const float*)d_in[7];
    const float* kv_b_W  = (const float*)d_in[8];
    const float* o_W     = (const float*)d_in[9];
    float* out = (float*)d_out;

    float *qa, *ckv, *kvn, *qbuf, *kvbuf, *attn;
    cudaGetSymbolAddress((void**)&qa,    g_qa);
    cudaGetSymbolAddress((void**)&ckv,   g_ckv);
    cudaGetSymbolAddress((void**)&kvn,   g_kvn);
    cudaGetSymbolAddress((void**)&qbuf,  g_q);
    cudaGetSymbolAddress((void**)&kvbuf, g_kv);
    cudaGetSymbolAddress((void**)&attn,  g_attn);

    // 1) q_a = hidden @ q_a_W^T            [4096,1536]
    sgemm_nt<<<dim3(DQA / GBN, NTOK / GBM), 256>>>(hidden, q_a_W, qa, NTOK, DQA, DMODEL);
    // 2) ckv = hidden @ kv_a_W^T           [4096,576]
    sgemm_nt<<<dim3((DKVA + GBN - 1) / GBN, NTOK / GBM), 256>>>(hidden, kv_a_W, ckv, NTOK, DKVA, DMODEL);
    // 3) rmsnorm q_a (in place)
    rmsnorm_kernel<<<NTOK, 256>>>(qa, qa, q_a_nw, DQA, DQA, DQA);
    // 4) rmsnorm kv latent -> kvn
    rmsnorm_kernel<<<NTOK, 256>>>(ckv, kvn, kv_a_nw, DKVLAT, DKVA, DKVLAT);
    // 5) q = qa_norm @ q_b_W^T             [4096,3072]
    sgemm_nt<<<dim3(QDIM / GBN, NTOK / GBM), 256>>>(qa, q_b_W, qbuf, NTOK, QDIM, DQA);
    // 6) kv = kvn @ kv_b_W^T               [4096,4096]
    sgemm_nt<<<dim3(KVDIM / GBN, NTOK / GBM), 256>>>(kvn, kv_b_W, kvbuf, NTOK, KVDIM, DKVLAT);
    // 7) RoPE in place (q rot slices, ckv rot slice)
    rope_kernel<<<NTOK, 512>>>(qbuf, ckv, cosb, sinb);
    // 8) flash attention -> attn [tok][h*128+d]
    {
        const int smem = (FBM * QSTR + FBN * QSTR + FBN * VSTR + FBN * PSTR) * (int)sizeof(float);
        cudaFuncSetAttribute(flash_kernel, cudaFuncAttributeMaxDynamicSharedMemorySize, smem);
        flash_kernel<<<dim3(SEQ / FBM, HEADS, BATCH), 256, smem>>>(qbuf, kvbuf, ckv, attn);
    }
    // 9) out = attn @ o_W^T                [4096,2048]
    sgemm_nt<<<dim3(DMODEL / GBN, NTOK / GBM), 256>>>(attn, o_W, out, NTOK, DMODEL, ODIM);
}

// round 2
// speedup vs baseline: 4.6011x; 4.6011x over previous
#include <cuda_runtime.h>
#include <cuda_bf16.h>
#include <math.h>
#include <stdint.h>

// ---------------- problem constants ----------------
#define BATCH   2
#define SEQ     2048
#define NTOK    (BATCH * SEQ)        // 4096
#define DMODEL  2048
#define HEADS   16
#define DQK     192
#define DNOPE   128
#define DROPE   64
#define DV      128
#define DQA     1536
#define DKVA    576
#define DKVLAT  512
#define QDIM    (HEADS * DQK)        // 3072
#define KVDIM   (HEADS * (DNOPE + DV)) // 4096
#define ODIM    (HEADS * DV)         // 2048
#define ATT_SCALE 0.07216878364870322f

// ---------------- scratch ----------------
__device__ float g_qa  [(size_t)NTOK * DQA];
__device__ float g_ckv [(size_t)NTOK * DKVA];
__device__ float g_kvn [(size_t)NTOK * DKVLAT];
__device__ float g_q   [(size_t)NTOK * QDIM];
__device__ float g_kv  [(size_t)NTOK * KVDIM];
__device__ float g_attn[(size_t)NTOK * ODIM];

// ---------------- tf32 helpers ----------------
__device__ __forceinline__ float to_tf32(float x) {
    float y;
    asm("cvt.rna.tf32.f32 %0, %1;" : "=f"(y) : "f"(x));
    return y;
}

__device__ __forceinline__ void mma_tf32(float c[4], const uint32_t a[4], const uint32_t b[2]) {
    asm volatile(
        "mma.sync.aligned.m16n8k8.row.col.f32.tf32.tf32.f32 "
        "{%0,%1,%2,%3}, {%4,%5,%6,%7}, {%8,%9}, {%0,%1,%2,%3};\n"
        : "+f"(c[0]), "+f"(c[1]), "+f"(c[2]), "+f"(c[3])
        : "r"(a[0]), "r"(a[1]), "r"(a[2]), "r"(a[3]), "r"(b[0]), "r"(b[1]));
}

// ---------------- TF32 GEMM: C[M,N] = A[M,K] @ B[N,K]^T ----------------
#define TBM 128
#define TBN 128
#define TBK 32
#define ASTR 36   // (ASTR % 32) == 4 -> conflict-free fragment reads (banks 4g+tg)

__global__ __launch_bounds__(256) void gemm_tf32(
    const float* __restrict__ A, const float* __restrict__ Bw,
    float* __restrict__ C, int M, int N, int K)
{
    __shared__ float As[TBM][ASTR];
    __shared__ float Bs[TBN][ASTR];
    const int bm = blockIdx.y * TBM;
    const int bn = blockIdx.x * TBN;
    const int tid = threadIdx.x;
    const int wid = tid >> 5, lane = tid & 31;
    const int g = lane >> 2, tg = lane & 3;
    const int wm = (wid >> 2) * 64, wn = (wid & 3) * 32;

    const int lr = tid >> 3;        // row step (32 rows per pass, 4 passes)
    const int lc = (tid & 7) * 4;   // float col 0..28

    float c[4][4][4];
#pragma unroll
    for (int mt = 0; mt < 4; mt++)
#pragma unroll
        for (int nt = 0; nt < 4; nt++)
#pragma unroll
            for (int i = 0; i < 4; i++) c[mt][nt][i] = 0.f;

    float4 pa[4], pb[4];

    // first tile load
#pragma unroll
    for (int i = 0; i < 4; i++) {
        int row = lr + i * 32;
        pa[i] = *(const float4*)(A + (size_t)(bm + row) * K + lc);
        int nrow = bn + row;
        pb[i] = (nrow < N) ? *(const float4*)(Bw + (size_t)nrow * K + lc)
                           : make_float4(0.f, 0.f, 0.f, 0.f);
    }
#pragma unroll
    for (int i = 0; i < 4; i++) {
        int row = lr + i * 32;
        As[row][lc + 0] = to_tf32(pa[i].x); As[row][lc + 1] = to_tf32(pa[i].y);
        As[row][lc + 2] = to_tf32(pa[i].z); As[row][lc + 3] = to_tf32(pa[i].w);
        Bs[row][lc + 0] = to_tf32(pb[i].x); Bs[row][lc + 1] = to_tf32(pb[i].y);
        Bs[row][lc + 2] = to_tf32(pb[i].z); Bs[row][lc + 3] = to_tf32(pb[i].w);
    }
    __syncthreads();

    for (int k0 = TBK; k0 <= K; k0 += TBK) {
        if (k0 < K) {
#pragma unroll
            for (int i = 0; i < 4; i++) {
                int row = lr + i * 32;
                pa[i] = *(const float4*)(A + (size_t)(bm + row) * K + k0 + lc);
                int nrow = bn + row;
                pb[i] = (nrow < N) ? *(const float4*)(Bw + (size_t)nrow * K + k0 + lc)
                                   : make_float4(0.f, 0.f, 0.f, 0.f);
            }
        }
#pragma unroll
        for (int ks = 0; ks < 4; ks++) {
            const int kb = ks * 8;
            uint32_t a[4][4], b[4][2];
#pragma unroll
            for (int mt = 0; mt < 4; mt++) {
                int r = wm + mt * 16;
                a[mt][0] = __float_as_uint(As[r + g    ][kb + tg]);
                a[mt][1] = __float_as_uint(As[r + g + 8][kb + tg]);
                a[mt][2] = __float_as_uint(As[r + g    ][kb + tg + 4]);
                a[mt][3] = __float_as_uint(As[r + g + 8][kb + tg + 4]);
            }
#pragma unroll
            for (int nt = 0; nt < 4; nt++) {
                int r = wn + nt * 8;
                b[nt][0] = __float_as_uint(Bs[r + g][kb + tg]);
                b[nt][1] = __float_as_uint(Bs[r + g][kb + tg + 4]);
            }
#pragma unroll
            for (int mt = 0; mt < 4; mt++)
#pragma unroll
                for (int nt = 0; nt < 4; nt++)
                    mma_tf32(c[mt][nt], a[mt], b[nt]);
        }
        __syncthreads();
        if (k0 < K) {
#pragma unroll
            for (int i = 0; i < 4; i++) {
                int row = lr + i * 32;
                As[row][lc + 0] = to_tf32(pa[i].x); As[row][lc + 1] = to_tf32(pa[i].y);
                As[row][lc + 2] = to_tf32(pa[i].z); As[row][lc + 3] = to_tf32(pa[i].w);
                Bs[row][lc + 0] = to_tf32(pb[i].x); Bs[row][lc + 1] = to_tf32(pb[i].y);
                Bs[row][lc + 2] = to_tf32(pb[i].z); Bs[row][lc + 3] = to_tf32(pb[i].w);
            }
            __syncthreads();
        }
    }

#pragma unroll
    for (int mt = 0; mt < 4; mt++) {
        int r0 = bm + wm + mt * 16 + g;
#pragma unroll
        for (int nt = 0; nt < 4; nt++) {
            int cc = bn + wn + nt * 8 + 2 * tg;
            if (cc < N) {
                *(float2*)(C + (size_t)r0 * N + cc)       = make_float2(c[mt][nt][0], c[mt][nt][1]);
                *(float2*)(C + (size_t)(r0 + 8) * N + cc) = make_float2(c[mt][nt][2], c[mt][nt][3]);
            }
        }
    }
}

// ---------------- RMSNorm ----------------
__global__ __launch_bounds__(256) void rmsnorm_kernel(
    const float* __restrict__ in, float* __restrict__ out,
    const float* __restrict__ w, int N, int in_stride, int out_stride)
{
    const int row = blockIdx.x;
    const float* x = in + (size_t)row * in_stride;
    const int cnt = N >> 8;
    float v[6];
    float ss = 0.f;
    for (int i = 0; i < cnt; i++) {
        v[i] = x[threadIdx.x + (i << 8)];
        ss += v[i] * v[i];
    }
#pragma unroll
    for (int o = 16; o > 0; o >>= 1) ss += __shfl_xor_sync(0xffffffffu, ss, o);
    __shared__ float red[8];
    if ((threadIdx.x & 31) == 0) red[threadIdx.x >> 5] = ss;
    __syncthreads();
    float tot = 0.f;
#pragma unroll
    for (int i = 0; i < 8; i++) tot += red[i];
    const float r = rsqrtf(tot / (float)N + 1e-6f);
    float* y = out + (size_t)row * out_stride;
    for (int i = 0; i < cnt; i++) {
        int c = threadIdx.x + (i << 8);
        y[c] = w[c] * v[i] * r;
    }
}

// ---------------- RoPE ----------------
__global__ __launch_bounds__(512) void rope_kernel(
    float* __restrict__ q, float* __restrict__ ckv,
    const float* __restrict__ cosb, const float* __restrict__ sinb)
{
    const int tok = blockIdx.x;
    const int t = threadIdx.x;
    const int h = t >> 5;
    const int d = t & 31;
    const float c0 = cosb[(size_t)tok * DROPE + d];
    const float s0 = sinb[(size_t)tok * DROPE + d];
    const float c1 = cosb[(size_t)tok * DROPE + d + 32];
    const float s1 = sinb[(size_t)tok * DROPE + d + 32];
    {
        float* qr = q + (size_t)tok * QDIM + h * DQK + DNOPE;
        float a = qr[d], b = qr[d + 32];
        qr[d]      = a * c0 - b * s0;
        qr[d + 32] = b * c1 + a * s1;
    }
    if (t < 32) {
        float* kr = ckv + (size_t)tok * DKVA + DKVLAT;
        float a = kr[d], b = kr[d + 32];
        kr[d]      = a * c0 - b * s0;
        kr[d + 32] = b * c1 + a * s1;
    }
}

// ---------------- Flash attention (tf32 mma, causal) ----------------
#define FM 128
#define FN 64
#define SQ_STR 196   // %32 == 4
#define SK_STR 196
#define SV_STR 136   // %32 == 8
#define SP_STR 68    // %32 == 4

extern __shared__ float fsmem[];

__global__ __launch_bounds__(256) void flash_tf32_kernel(
    const float* __restrict__ q, const float* __restrict__ kvbuf,
    const float* __restrict__ ckv, float* __restrict__ attn_out)
{
    float* sQ = fsmem;                      // 128 x 196
    float* sK = sQ + FM * SQ_STR;           // 64 x 196
    float* sV = sK + FN * SK_STR;           // 64 x 136
    float* sP = sV + FN * SV_STR;           // 128 x 68

    const int bq = blockIdx.x;              // q tile (128 rows)
    const int h  = blockIdx.y;
    const int b  = blockIdx.z;
    const int q0 = bq * FM;
    const int tid = threadIdx.x;
    const int wid = tid >> 5, lane = tid & 31;
    const int g = lane >> 2, tg = lane & 3;
    const int wrow = wid * 16;              // warp's 16 q-rows within tile

    // load Q tile (pre-scaled, tf32-rounded)
    const size_t qbase = ((size_t)(b * SEQ + q0)) * QDIM + (size_t)h * DQK;
    for (int e = tid; e < FM * (DQK / 4); e += 256) {
        int r = e / (DQK / 4), c4 = (e - r * (DQK / 4)) * 4;
        float4 v = *(const float4*)(q + qbase + (size_t)r * QDIM + c4);
        sQ[r * SQ_STR + c4 + 0] = to_tf32(v.x * ATT_SCALE);
        sQ[r * SQ_STR + c4 + 1] = to_tf32(v.y * ATT_SCALE);
        sQ[r * SQ_STR + c4 + 2] = to_tf32(v.z * ATT_SCALE);
        sQ[r * SQ_STR + c4 + 3] = to_tf32(v.w * ATT_SCALE);
    }

    float o[16][4];   // 16 n-tiles of 8 over DV=128
#pragma unroll
    for (int nt = 0; nt < 16; nt++)
#pragma unroll
        for (int i = 0; i < 4; i++) o[nt][i] = 0.f;
    float m0 = -1e30f, m1 = -1e30f, l0 = 0.f, l1 = 0.f;

    const int nkt = (q0 + FM) / FN;   // key tiles: 0..nkt-1
    for (int kt = 0; kt < nkt; kt++) {
        __syncthreads();
        const size_t kvb = ((size_t)(b * SEQ + kt * FN)) * KVDIM + (size_t)h * (DNOPE + DV);
        const size_t ckb = ((size_t)(b * SEQ + kt * FN)) * DKVA + DKVLAT;
        // K tile: [64][192] = kv_nope(128) | roped rot(64)
        for (int e = tid; e < FN * (DQK / 4); e += 256) {
            int r = e / (DQK / 4), c4 = (e - r * (DQK / 4)) * 4;
            float4 v;
            if (c4 < DNOPE) v = *(const float4*)(kvbuf + kvb + (size_t)r * KVDIM + c4);
            else            v = *(const float4*)(ckv + ckb + (size_t)r * DKVA + (c4 - DNOPE));
            sK[r * SK_STR + c4 + 0] = to_tf32(v.x);
            sK[r * SK_STR + c4 + 1] = to_tf32(v.y);
            sK[r * SK_STR + c4 + 2] = to_tf32(v.z);
            sK[r * SK_STR + c4 + 3] = to_tf32(v.w);
        }
        // V tile: [64][128]
        for (int e = tid; e < FN * (DV / 4); e += 256) {
            int r = e >> 5, c4 = (e & 31) * 4;
            float4 v = *(const float4*)(kvbuf + kvb + (size_t)r * KVDIM + DNOPE + c4);
            sV[r * SV_STR + c4 + 0] = to_tf32(v.x);
            sV[r * SV_STR + c4 + 1] = to_tf32(v.y);
            sV[r * SV_STR + c4 + 2] = to_tf32(v.z);
            sV[r * SV_STR + c4 + 3] = to_tf32(v.w);
        }
        __syncthreads();

        // ---- S = Q K^T : warp computes 16 x 64 (8 n-tiles) ----
        float s[8][4];
#pragma unroll
        for (int nt = 0; nt < 8; nt++)
#pragma unroll
            for (int i = 0; i < 4; i++) s[nt][i] = 0.f;

#pragma unroll 4
        for (int ks = 0; ks < DQK / 8; ks++) {
            const int kb = ks * 8;
            uint32_t a[4], bb[8][2];
            a[0] = __float_as_uint(sQ[(wrow + g    ) * SQ_STR + kb + tg]);
            a[1] = __float_as_uint(sQ[(wrow + g + 8) * SQ_STR + kb + tg]);
            a[2] = __float_as_uint(sQ[(wrow + g    ) * SQ_STR + kb + tg + 4]);
            a[3] = __float_as_uint(sQ[(wrow + g + 8) * SQ_STR + kb + tg + 4]);
#pragma unroll
            for (int nt = 0; nt < 8; nt++) {
                bb[nt][0] = __float_as_uint(sK[(nt * 8 + g) * SK_STR + kb + tg]);
                bb[nt][1] = __float_as_uint(sK[(nt * 8 + g) * SK_STR + kb + tg + 4]);
            }
#pragma unroll
            for (int nt = 0; nt < 8; nt++)
                mma_tf32(s[nt], a, bb[nt]);
        }

        // causal mask (only tiles overlapping the diagonal region)
        if (kt * FN + FN - 1 > q0) {
            const int gr0 = q0 + wrow + g;
            const int gr1 = gr0 + 8;
#pragma unroll
            for (int nt = 0; nt < 8; nt++) {
                int gc = kt * FN + nt * 8 + 2 * tg;
                if (gc     > gr0) s[nt][0] = -1e30f;
                if (gc + 1 > gr0) s[nt][1] = -1e30f;
                if (gc     > gr1) s[nt][2] = -1e30f;
                if (gc + 1 > gr1) s[nt][3] = -1e30f;
            }
        }

        // ---- online softmax (rows g and g+8; reduce over 4 tg lanes) ----
        float mx0 = -1e30f, mx1 = -1e30f;
#pragma unroll
        for (int nt = 0; nt < 8; nt++) {
            mx0 = fmaxf(mx0, fmaxf(s[nt][0], s[nt][1]));
            mx1 = fmaxf(mx1, fmaxf(s[nt][2], s[nt][3]));
        }
#pragma unroll
        for (int o_ = 1; o_ < 4; o_ <<= 1) {
            mx0 = fmaxf(mx0, __shfl_xor_sync(0xffffffffu, mx0, o_));
            mx1 = fmaxf(mx1, __shfl_xor_sync(0xffffffffu, mx1, o_));
        }
        const float mn0 = fmaxf(m0, mx0);
        const float mn1 = fmaxf(m1, mx1);
        const float sc0 = __expf(m0 - mn0);
        const float sc1 = __expf(m1 - mn1);
        float rs0 = 0.f, rs1 = 0.f;
#pragma unroll
        for (int nt = 0; nt < 8; nt++) {
            s[nt][0] = __expf(s[nt][0] - mn0);
            s[nt][1] = __expf(s[nt][1] - mn0);
            s[nt][2] = __expf(s[nt][2] - mn1);
            s[nt][3] = __expf(s[nt][3] - mn1);
            rs0 += s[nt][0] + s[nt][1];
            rs1 += s[nt][2] + s[nt][3];
        }
#pragma unroll
        for (int o_ = 1; o_ < 4; o_ <<= 1) {
            rs0 += __shfl_xor_sync(0xffffffffu, rs0, o_);
            rs1 += __shfl_xor_sync(0xffffffffu, rs1, o_);
        }
        l0 = l0 * sc0 + rs0;  m0 = mn0;
        l1 = l1 * sc1 + rs1;  m1 = mn1;
#pragma unroll
        for (int nt = 0; nt < 16; nt++) {
            o[nt][0] *= sc0; o[nt][1] *= sc0;
            o[nt][2] *= sc1; o[nt][3] *= sc1;
        }
        // write P to smem (own warp rows only; tf32-rounded)
#pragma unroll
        for (int nt = 0; nt < 8; nt++) {
            int col = nt * 8 + 2 * tg;
            sP[(wrow + g    ) * SP_STR + col]     = to_tf32(s[nt][0]);
            sP[(wrow + g    ) * SP_STR + col + 1] = to_tf32(s[nt][1]);
            sP[(wrow + g + 8) * SP_STR + col]     = to_tf32(s[nt][2]);
            sP[(wrow + g + 8) * SP_STR + col + 1] = to_tf32(s[nt][3]);
        }
        __syncwarp();

        // ---- O += P V : warp computes 16 x 128 (16 n-tiles), K=64 ----
#pragma unroll 2
        for (int ks = 0; ks < FN / 8; ks++) {
            const int kb = ks * 8;
            uint32_t a[4];
            a[0] = __float_as_uint(sP[(wrow + g    ) * SP_STR + kb + tg]);
            a[1] = __float_as_uint(sP[(wrow + g + 8) * SP_STR + kb + tg]);
            a[2] = __float_as_uint(sP[(wrow + g    ) * SP_STR + kb + tg + 4]);
            a[3] = __float_as_uint(sP[(wrow + g + 8) * SP_STR + kb + tg + 4]);
#pragma unroll
            for (int nt = 0; nt < 16; nt++) {
                uint32_t bb[2];
                bb[0] = __float_as_uint(sV[(kb + tg    ) * SV_STR + nt * 8 + g]);
                bb[1] = __float_as_uint(sV[(kb + tg + 4) * SV_STR + nt * 8 + g]);
                mma_tf32(o[nt], a, bb);
            }
        }
    }

    // ---- epilogue ----
    const float inv0 = 1.f / l0, inv1 = 1.f / l1;
    const size_t obase = ((size_t)(b * SEQ + q0)) * ODIM + (size_t)h * DV;
    const size_t r0 = obase + (size_t)(wrow + g) * ODIM;
    const size_t r1 = obase + (size_t)(wrow + g + 8) * ODIM;
#pragma unroll
    for (int nt = 0; nt < 16; nt++) {
        int col = nt * 8 + 2 * tg;
        *(float2*)(attn_out + r0 + col) = make_float2(o[nt][0] * inv0, o[nt][1] * inv0);
        *(float2*)(attn_out + r1 + col) = make_float2(o[nt][2] * inv1, o[nt][3] * inv1);
    }
}

// ---------------- launch ----------------
extern "C" void kernel_launch(void* const* d_in, const int* in_sizes, int n_in,
                              void* d_out, int out_size)
{
    (void)in_sizes; (void)n_in; (void)out_size;
    const float* hidden  = (const float*)d_in[0];
    const float* cosb    = (const float*)d_in[1];
    const float* sinb    = (const float*)d_in[2];
    const float* q_a_W   = (const float*)d_in[3];
    const float* q_a_nw  = (const float*)d_in[4];
    const float* q_b_W   = (const float*)d_in[5];
    const float* kv_a_W  = (const float*)d_in[6];
    const float* kv_a_nw = (const float*)d_in[7];
    const float* kv_b_W  = (const float*)d_in[8];
    const float* o_W     = (const float*)d_in[9];
    float* out = (float*)d_out;

    float *qa, *ckv, *kvn, *qbuf, *kvbuf, *attn;
    cudaGetSymbolAddress((void**)&qa,    g_qa);
    cudaGetSymbolAddress((void**)&ckv,   g_ckv);
    cudaGetSymbolAddress((void**)&kvn,   g_kvn);
    cudaGetSymbolAddress((void**)&qbuf,  g_q);
    cudaGetSymbolAddress((void**)&kvbuf, g_kv);
    cudaGetSymbolAddress((void**)&attn,  g_attn);

    // 1) q_a = hidden @ q_a_W^T
    gemm_tf32<<<dim3(DQA / TBN, NTOK / TBM), 256>>>(hidden, q_a_W, qa, NTOK, DQA, DMODEL);
    // 2) ckv = hidden @ kv_a_W^T
    gemm_tf32<<<dim3((DKVA + TBN - 1) / TBN, NTOK / TBM), 256>>>(hidden, kv_a_W, ckv, NTOK, DKVA, DMODEL);
    // 3) rmsnorm q_a (in place)
    rmsnorm_kernel<<<NTOK, 256>>>(qa, qa, q_a_nw, DQA, DQA, DQA);
    // 4) rmsnorm kv latent
    rmsnorm_kernel<<<NTOK, 256>>>(ckv, kvn, kv_a_nw, DKVLAT, DKVA, DKVLAT);
    // 5) q = qa_norm @ q_b_W^T
    gemm_tf32<<<dim3(QDIM / TBN, NTOK / TBM), 256>>>(qa, q_b_W, qbuf, NTOK, QDIM, DQA);
    // 6) kv = kvn @ kv_b_W^T
    gemm_tf32<<<dim3(KVDIM / TBN, NTOK / TBM), 256>>>(kvn, kv_b_W, kvbuf, NTOK, KVDIM, DKVLAT);
    // 7) RoPE in place
    rope_kernel<<<NTOK, 512>>>(qbuf, ckv, cosb, sinb);
    // 8) flash attention
    {
        const int smem = (FM * SQ_STR + FN * SK_STR + FN * SV_STR + FM * SP_STR) * (int)sizeof(float);
        cudaFuncSetAttribute(flash_tf32_kernel, cudaFuncAttributeMaxDynamicSharedMemorySize, smem);
        flash_tf32_kernel<<<dim3(SEQ / FM, HEADS, BATCH), 256, smem>>>(qbuf, kvbuf, ckv, attn);
    }
    // 9) out = attn @ o_W^T
    gemm_tf32<<<dim3(DMODEL / TBN, NTOK / TBM), 256>>>(attn, o_W, out, NTOK, DMODEL, ODIM);
}

// round 7
// speedup vs baseline: 5.1706x; 1.1238x over previous
#include <cuda_runtime.h>
#include <cuda_bf16.h>
#include <math.h>
#include <stdint.h>

// ---------------- problem constants ----------------
#define BATCH   2
#define SEQ     2048
#define NTOK    (BATCH * SEQ)        // 4096
#define DMODEL  2048
#define HEADS   16
#define DQK     192
#define DNOPE   128
#define DROPE   64
#define DV      128
#define DQA     1536
#define DKVA    576
#define DKVLAT  512
#define QDIM    (HEADS * DQK)        // 3072
#define KVDIM   (HEADS * (DNOPE + DV)) // 4096
#define ODIM    (HEADS * DV)         // 2048
#define ATT_SCALE 0.07216878364870322f

// ---------------- scratch ----------------
__device__ float g_qa  [(size_t)NTOK * DQA];
__device__ float g_ckv [(size_t)NTOK * DKVA];
__device__ float g_kvn [(size_t)NTOK * DKVLAT];
__device__ float g_q   [(size_t)NTOK * QDIM];
__device__ float g_kv  [(size_t)NTOK * KVDIM];
__device__ float g_attn[(size_t)NTOK * ODIM];

// ---------------- helpers ----------------
__device__ __forceinline__ float to_tf32(float x) {
    float y;
    asm("cvt.rna.tf32.f32 %0, %1;" : "=f"(y) : "f"(x));
    return y;
}

__device__ __forceinline__ uint32_t smem_u32(const void* p) {
    uint32_t a;
    asm("{ .reg .u64 t; cvta.to.shared.u64 t, %1; cvt.u32.u64 %0, t; }" : "=r"(a) : "l"(p));
    return a;
}

__device__ __forceinline__ void mma_tf32(float c[4], const uint32_t a[4], const uint32_t b[2]) {
    asm volatile(
        "mma.sync.aligned.m16n8k8.row.col.f32.tf32.tf32.f32 "
        "{%0,%1,%2,%3}, {%4,%5,%6,%7}, {%8,%9}, {%0,%1,%2,%3};\n"
        : "+f"(c[0]), "+f"(c[1]), "+f"(c[2]), "+f"(c[3])
        : "r"(a[0]), "r"(a[1]), "r"(a[2]), "r"(a[3]), "r"(b[0]), "r"(b[1]));
}

// ---------------- unified dynamic smem ----------------
extern __shared__ char dynsm[];

// ============================================================================
// TF32 GEMM (mma.sync) with 3-stage cp.async pipeline
// C[M,N] = A[M,K] @ B[N,K]^T, tile 128x128, K-chunk 32
// ============================================================================
#define TBM 128
#define TBN 128
#define TBK 32
#define ASTR 36                          // stride %32==4 -> conflict-free frag reads
#define NSTG 3
#define STG_FLOATS (TBM * ASTR + TBN * ASTR)   // 9216 floats per stage
#define GEMM_SMEM (NSTG * STG_FLOATS * (int)sizeof(float))  // 110592 B

__global__ __launch_bounds__(256) void gemm_tf32(
    const float* __restrict__ A, const float* __restrict__ Bw,
    float* __restrict__ C, int M, int N, int K)
{
    float* sm = (float*)dynsm;
    const int tid = threadIdx.x;
    const int wid = tid >> 5, lane = tid & 31;
    const int g = lane >> 2, tg = lane & 3;
    const int wm = (wid >> 2) * 64, wn = (wid & 3) * 32;
    const int bm = blockIdx.y * TBM, bn = blockIdx.x * TBN;
    const int NK = K / TBK;

#define LOAD_STAGE(c)                                                             \
    {                                                                             \
        const int s_ = (c) % NSTG;                                                \
        float* as_ = sm + s_ * STG_FLOATS;                                        \
        float* bs_ = as_ + TBM * ASTR;                                            \
        _Pragma("unroll")                                                         \
        for (int t_ = 0; t_ < 4; t_++) {                                          \
            int idx_ = tid + t_ * 256;                                            \
            int row_ = idx_ >> 3;                                                 \
            int c4_ = (idx_ & 7) * 4;                                             \
            uint32_t d_ = smem_u32(as_ + row_ * ASTR + c4_);                      \
            const float* s1_ = A + (size_t)(bm + row_) * K + (size_t)(c) * TBK + c4_; \
            asm volatile("cp.async.cg.shared.global [%0], [%1], 16;"              \
                         :: "r"(d_), "l"(s1_));                                   \
        }                                                                         \
        _Pragma("unroll")                                                         \
        for (int t_ = 0; t_ < 4; t_++) {                                          \
            int idx_ = tid + t_ * 256;                                            \
            int row_ = idx_ >> 3;                                                 \
            int c4_ = (idx_ & 7) * 4;                                             \
            int nr_ = bn + row_;                                                  \
            uint32_t d_ = smem_u32(bs_ + row_ * ASTR + c4_);                      \
            const float* s1_ = Bw + (size_t)(nr_ < N ? nr_ : 0) * K + (size_t)(c) * TBK + c4_; \
            unsigned sz_ = (nr_ < N) ? 16u : 0u;                                  \
            asm volatile("cp.async.cg.shared.global [%0], [%1], 16, %2;"          \
                         :: "r"(d_), "l"(s1_), "r"(sz_));                         \
        }                                                                         \
        asm volatile("cp.async.commit_group;" ::: "memory");                      \
    }

    float acc[4][4][4];
#pragma unroll
    for (int mt = 0; mt < 4; mt++)
#pragma unroll
        for (int nt = 0; nt < 4; nt++)
#pragma unroll
            for (int i = 0; i < 4; i++) acc[mt][nt][i] = 0.f;

    LOAD_STAGE(0);
    LOAD_STAGE(1);

    for (int cc = 0; cc < NK; cc++) {
        asm volatile("cp.async.wait_group 1;" ::: "memory");
        __syncthreads();
        if (cc + 2 < NK) LOAD_STAGE(cc + 2);

        const int s = cc % NSTG;
        const float* as_ = sm + s * STG_FLOATS;
        const float* bs_ = as_ + TBM * ASTR;

#pragma unroll
        for (int ks = 0; ks < 4; ks++) {
            const int kb = ks * 8;
            uint32_t a[4][4], b[4][2];
#pragma unroll
            for (int mt = 0; mt < 4; mt++) {
                int r = wm + mt * 16;
                a[mt][0] = __float_as_uint(to_tf32(as_[(r + g    ) * ASTR + kb + tg]));
                a[mt][1] = __float_as_uint(to_tf32(as_[(r + g + 8) * ASTR + kb + tg]));
                a[mt][2] = __float_as_uint(to_tf32(as_[(r + g    ) * ASTR + kb + tg + 4]));
                a[mt][3] = __float_as_uint(to_tf32(as_[(r + g + 8) * ASTR + kb + tg + 4]));
            }
#pragma unroll
            for (int nt = 0; nt < 4; nt++) {
                int r = wn + nt * 8;
                b[nt][0] = __float_as_uint(to_tf32(bs_[(r + g) * ASTR + kb + tg]));
                b[nt][1] = __float_as_uint(to_tf32(bs_[(r + g) * ASTR + kb + tg + 4]));
            }
#pragma unroll
            for (int mt = 0; mt < 4; mt++)
#pragma unroll
                for (int nt = 0; nt < 4; nt++)
                    mma_tf32(acc[mt][nt], a[mt], b[nt]);
        }
    }

#pragma unroll
    for (int mt = 0; mt < 4; mt++) {
        int r0 = bm + wm + mt * 16 + g;
#pragma unroll
        for (int nt = 0; nt < 4; nt++) {
            int cc = bn + wn + nt * 8 + 2 * tg;
            if (cc < N) {
                *(float2*)(C + (size_t)r0 * N + cc)       = make_float2(acc[mt][nt][0], acc[mt][nt][1]);
                *(float2*)(C + (size_t)(r0 + 8) * N + cc) = make_float2(acc[mt][nt][2], acc[mt][nt][3]);
            }
        }
    }
}

// ---------------- RMSNorm ----------------
__global__ __launch_bounds__(256) void rmsnorm_kernel(
    const float* __restrict__ in, float* __restrict__ out,
    const float* __restrict__ w, int N, int in_stride, int out_stride)
{
    const int row = blockIdx.x;
    const float* x = in + (size_t)row * in_stride;
    const int cnt = N >> 8;
    float v[6];
    float ss = 0.f;
    for (int i = 0; i < cnt; i++) {
        v[i] = x[threadIdx.x + (i << 8)];
        ss += v[i] * v[i];
    }
#pragma unroll
    for (int o = 16; o > 0; o >>= 1) ss += __shfl_xor_sync(0xffffffffu, ss, o);
    __shared__ float red[8];
    if ((threadIdx.x & 31) == 0) red[threadIdx.x >> 5] = ss;
    __syncthreads();
    float tot = 0.f;
#pragma unroll
    for (int i = 0; i < 8; i++) tot += red[i];
    const float r = rsqrtf(tot / (float)N + 1e-6f);
    float* y = out + (size_t)row * out_stride;
    for (int i = 0; i < cnt; i++) {
        int c = threadIdx.x + (i << 8);
        y[c] = w[c] * v[i] * r;
    }
}

// ---------------- RoPE ----------------
__global__ __launch_bounds__(512) void rope_kernel(
    float* __restrict__ q, float* __restrict__ ckv,
    const float* __restrict__ cosb, const float* __restrict__ sinb)
{
    const int tok = blockIdx.x;
    const int t = threadIdx.x;
    const int h = t >> 5;
    const int d = t & 31;
    const float c0 = cosb[(size_t)tok * DROPE + d];
    const float s0 = sinb[(size_t)tok * DROPE + d];
    const float c1 = cosb[(size_t)tok * DROPE + d + 32];
    const float s1 = sinb[(size_t)tok * DROPE + d + 32];
    {
        float* qr = q + (size_t)tok * QDIM + h * DQK + DNOPE;
        float a = qr[d], b = qr[d + 32];
        qr[d]      = a * c0 - b * s0;
        qr[d + 32] = b * c1 + a * s1;
    }
    if (t < 32) {
        float* kr = ckv + (size_t)tok * DKVA + DKVLAT;
        float a = kr[d], b = kr[d + 32];
        kr[d]      = a * c0 - b * s0;
        kr[d + 32] = b * c1 + a * s1;
    }
}

// ---------------- Flash attention (tf32 mma.sync, causal) ----------------
#define FM 128
#define FN 64
#define SQ_STR 196
#define SK_STR 196
#define SV_STR 136
#define SP_STR 68
#define FLASH_SMEM ((FM * SQ_STR + FN * SK_STR + FN * SV_STR + FM * SP_STR) * (int)sizeof(float))

__global__ __launch_bounds__(256) void flash_tf32_kernel(
    const float* __restrict__ q, const float* __restrict__ kvbuf,
    const float* __restrict__ ckv, float* __restrict__ attn_out)
{
    float* fsmem = (float*)dynsm;
    float* sQ = fsmem;
    float* sK = sQ + FM * SQ_STR;
    float* sV = sK + FN * SK_STR;
    float* sP = sV + FN * SV_STR;

    // longest tiles first: trims the multi-wave straggler tail (work ∝ bq+1)
    const int bq = gridDim.x - 1 - blockIdx.x;
    const int h  = blockIdx.y;
    const int b  = blockIdx.z;
    const int q0 = bq * FM;
    const int tid = threadIdx.x;
    const int wid = tid >> 5, lane = tid & 31;
    const int g = lane >> 2, tg = lane & 3;
    const int wrow = wid * 16;

    const size_t qbase = ((size_t)(b * SEQ + q0)) * QDIM + (size_t)h * DQK;
    for (int e = tid; e < FM * (DQK / 4); e += 256) {
        int r = e / (DQK / 4), c4 = (e - r * (DQK / 4)) * 4;
        float4 v = *(const float4*)(q + qbase + (size_t)r * QDIM + c4);
        sQ[r * SQ_STR + c4 + 0] = to_tf32(v.x * ATT_SCALE);
        sQ[r * SQ_STR + c4 + 1] = to_tf32(v.y * ATT_SCALE);
        sQ[r * SQ_STR + c4 + 2] = to_tf32(v.z * ATT_SCALE);
        sQ[r * SQ_STR + c4 + 3] = to_tf32(v.w * ATT_SCALE);
    }

    float o[16][4];
#pragma unroll
    for (int nt = 0; nt < 16; nt++)
#pragma unroll
        for (int i = 0; i < 4; i++) o[nt][i] = 0.f;
    float m0 = -1e30f, m1 = -1e30f, l0 = 0.f, l1 = 0.f;

    const int nkt = (q0 + FM) / FN;
    for (int kt = 0; kt < nkt; kt++) {
        __syncthreads();
        const size_t kvb = ((size_t)(b * SEQ + kt * FN)) * KVDIM + (size_t)h * (DNOPE + DV);
        const size_t ckb = ((size_t)(b * SEQ + kt * FN)) * DKVA + DKVLAT;
        for (int e = tid; e < FN * (DQK / 4); e += 256) {
            int r = e / (DQK / 4), c4 = (e - r * (DQK / 4)) * 4;
            float4 v;
            if (c4 < DNOPE) v = *(const float4*)(kvbuf + kvb + (size_t)r * KVDIM + c4);
            else            v = *(const float4*)(ckv + ckb + (size_t)r * DKVA + (c4 - DNOPE));
            sK[r * SK_STR + c4 + 0] = to_tf32(v.x);
            sK[r * SK_STR + c4 + 1] = to_tf32(v.y);
            sK[r * SK_STR + c4 + 2] = to_tf32(v.z);
            sK[r * SK_STR + c4 + 3] = to_tf32(v.w);
        }
        for (int e = tid; e < FN * (DV / 4); e += 256) {
            int r = e >> 5, c4 = (e & 31) * 4;
            float4 v = *(const float4*)(kvbuf + kvb + (size_t)r * KVDIM + DNOPE + c4);
            sV[r * SV_STR + c4 + 0] = to_tf32(v.x);
            sV[r * SV_STR + c4 + 1] = to_tf32(v.y);
            sV[r * SV_STR + c4 + 2] = to_tf32(v.z);
            sV[r * SV_STR + c4 + 3] = to_tf32(v.w);
        }
        __syncthreads();

        float s[8][4];
#pragma unroll
        for (int nt = 0; nt < 8; nt++)
#pragma unroll
            for (int i = 0; i < 4; i++) s[nt][i] = 0.f;

#pragma unroll 4
        for (int ks = 0; ks < DQK / 8; ks++) {
            const int kb = ks * 8;
            uint32_t a[4], bb[8][2];
            a[0] = __float_as_uint(sQ[(wrow + g    ) * SQ_STR + kb + tg]);
            a[1] = __float_as_uint(sQ[(wrow + g + 8) * SQ_STR + kb + tg]);
            a[2] = __float_as_uint(sQ[(wrow + g    ) * SQ_STR + kb + tg + 4]);
            a[3] = __float_as_uint(sQ[(wrow + g + 8) * SQ_STR + kb + tg + 4]);
#pragma unroll
            for (int nt = 0; nt < 8; nt++) {
                bb[nt][0] = __float_as_uint(sK[(nt * 8 + g) * SK_STR + kb + tg]);
                bb[nt][1] = __float_as_uint(sK[(nt * 8 + g) * SK_STR + kb + tg + 4]);
            }
#pragma unroll
            for (int nt = 0; nt < 8; nt++)
                mma_tf32(s[nt], a, bb[nt]);
        }

        if (kt * FN + FN - 1 > q0) {
            const int gr0 = q0 + wrow + g;
            const int gr1 = gr0 + 8;
#pragma unroll
            for (int nt = 0; nt < 8; nt++) {
                int gc = kt * FN + nt * 8 + 2 * tg;
                if (gc     > gr0) s[nt][0] = -1e30f;
                if (gc + 1 > gr0) s[nt][1] = -1e30f;
                if (gc     > gr1) s[nt][2] = -1e30f;
                if (gc + 1 > gr1) s[nt][3] = -1e30f;
            }
        }

        float mx0 = -1e30f, mx1 = -1e30f;
#pragma unroll
        for (int nt = 0; nt < 8; nt++) {
            mx0 = fmaxf(mx0, fmaxf(s[nt][0], s[nt][1]));
            mx1 = fmaxf(mx1, fmaxf(s[nt][2], s[nt][3]));
        }
#pragma unroll
        for (int o_ = 1; o_ < 4; o_ <<= 1) {
            mx0 = fmaxf(mx0, __shfl_xor_sync(0xffffffffu, mx0, o_));
            mx1 = fmaxf(mx1, __shfl_xor_sync(0xffffffffu, mx1, o_));
        }
        const float mn0 = fmaxf(m0, mx0);
        const float mn1 = fmaxf(m1, mx1);
        const float sc0 = __expf(m0 - mn0);
        const float sc1 = __expf(m1 - mn1);
        float rs0 = 0.f, rs1 = 0.f;
#pragma unroll
        for (int nt = 0; nt < 8; nt++) {
            s[nt][0] = __expf(s[nt][0] - mn0);
            s[nt][1] = __expf(s[nt][1] - mn0);
            s[nt][2] = __expf(s[nt][2] - mn1);
            s[nt][3] = __expf(s[nt][3] - mn1);
            rs0 += s[nt][0] + s[nt][1];
            rs1 += s[nt][2] + s[nt][3];
        }
#pragma unroll
        for (int o_ = 1; o_ < 4; o_ <<= 1) {
            rs0 += __shfl_xor_sync(0xffffffffu, rs0, o_);
            rs1 += __shfl_xor_sync(0xffffffffu, rs1, o_);
        }
        l0 = l0 * sc0 + rs0;  m0 = mn0;
        l1 = l1 * sc1 + rs1;  m1 = mn1;
#pragma unroll
        for (int nt = 0; nt < 16; nt++) {
            o[nt][0] *= sc0; o[nt][1] *= sc0;
            o[nt][2] *= sc1; o[nt][3] *= sc1;
        }
#pragma unroll
        for (int nt = 0; nt < 8; nt++) {
            int col = nt * 8 + 2 * tg;
            sP[(wrow + g    ) * SP_STR + col]     = to_tf32(s[nt][0]);
            sP[(wrow + g    ) * SP_STR + col + 1] = to_tf32(s[nt][1]);
            sP[(wrow + g + 8) * SP_STR + col]     = to_tf32(s[nt][2]);
            sP[(wrow + g + 8) * SP_STR + col + 1] = to_tf32(s[nt][3]);
        }
        __syncwarp();

#pragma unroll 2
        for (int ks = 0; ks < FN / 8; ks++) {
            const int kb = ks * 8;
            uint32_t a[4];
            a[0] = __float_as_uint(sP[(wrow + g    ) * SP_STR + kb + tg]);
            a[1] = __float_as_uint(sP[(wrow + g + 8) * SP_STR + kb + tg]);
            a[2] = __float_as_uint(sP[(wrow + g    ) * SP_STR + kb + tg + 4]);
            a[3] = __float_as_uint(sP[(wrow + g + 8) * SP_STR + kb + tg + 4]);
#pragma unroll
            for (int nt = 0; nt < 16; nt++) {
                uint32_t bb[2];
                bb[0] = __float_as_uint(sV[(kb + tg    ) * SV_STR + nt * 8 + g]);
                bb[1] = __float_as_uint(sV[(kb + tg + 4) * SV_STR + nt * 8 + g]);
                mma_tf32(o[nt], a, bb);
            }
        }
    }

    const float inv0 = 1.f / l0, inv1 = 1.f / l1;
    const size_t obase = ((size_t)(b * SEQ + q0)) * ODIM + (size_t)h * DV;
    const size_t r0 = obase + (size_t)(wrow + g) * ODIM;
    const size_t r1 = obase + (size_t)(wrow + g + 8) * ODIM;
#pragma unroll
    for (int nt = 0; nt < 16; nt++) {
        int col = nt * 8 + 2 * tg;
        *(float2*)(attn_out + r0 + col) = make_float2(o[nt][0] * inv0, o[nt][1] * inv0);
        *(float2*)(attn_out + r1 + col) = make_float2(o[nt][2] * inv1, o[nt][3] * inv1);
    }
}

// ---------------- launch ----------------
extern "C" void kernel_launch(void* const* d_in, const int* in_sizes, int n_in,
                              void* d_out, int out_size)
{
    (void)in_sizes; (void)n_in; (void)out_size;
    const float* hidden  = (const float*)d_in[0];
    const float* cosb    = (const float*)d_in[1];
    const float* sinb    = (const float*)d_in[2];
    const float* q_a_W   = (const float*)d_in[3];
    const float* q_a_nw  = (const float*)d_in[4];
    const float* q_b_W   = (const float*)d_in[5];
    const float* kv_a_W  = (const float*)d_in[6];
    const float* kv_a_nw = (const float*)d_in[7];
    const float* kv_b_W  = (const float*)d_in[8];
    const float* o_W     = (const float*)d_in[9];
    float* out = (float*)d_out;

    float *qa, *ckv, *kvn, *qbuf, *kvbuf, *attn;
    cudaGetSymbolAddress((void**)&qa,    g_qa);
    cudaGetSymbolAddress((void**)&ckv,   g_ckv);
    cudaGetSymbolAddress((void**)&kvn,   g_kvn);
    cudaGetSymbolAddress((void**)&qbuf,  g_q);
    cudaGetSymbolAddress((void**)&kvbuf, g_kv);
    cudaGetSymbolAddress((void**)&attn,  g_attn);

    cudaFuncSetAttribute(gemm_tf32, cudaFuncAttributeMaxDynamicSharedMemorySize, GEMM_SMEM);
    cudaFuncSetAttribute(flash_tf32_kernel, cudaFuncAttributeMaxDynamicSharedMemorySize, FLASH_SMEM);

    // 1) q_a = hidden @ q_a_W^T
    gemm_tf32<<<dim3(DQA / TBN, NTOK / TBM), 256, GEMM_SMEM>>>(hidden, q_a_W, qa, NTOK, DQA, DMODEL);
    // 2) ckv = hidden @ kv_a_W^T  (N=576, edge tile guarded)
    gemm_tf32<<<dim3((DKVA + TBN - 1) / TBN, NTOK / TBM), 256, GEMM_SMEM>>>(hidden, kv_a_W, ckv, NTOK, DKVA, DMODEL);
    // 3) rmsnorm q_a (in place)
    rmsnorm_kernel<<<NTOK, 256>>>(qa, qa, q_a_nw, DQA, DQA, DQA);
    // 4) rmsnorm kv latent
    rmsnorm_kernel<<<NTOK, 256>>>(ckv, kvn, kv_a_nw, DKVLAT, DKVA, DKVLAT);
    // 5) q = qa_norm @ q_b_W^T
    gemm_tf32<<<dim3(QDIM / TBN, NTOK / TBM), 256, GEMM_SMEM>>>(qa, q_b_W, qbuf, NTOK, QDIM, DQA);
    // 6) kv = kvn @ kv_b_W^T
    gemm_tf32<<<dim3(KVDIM / TBN, NTOK / TBM), 256, GEMM_SMEM>>>(kvn, kv_b_W, kvbuf, NTOK, KVDIM, DKVLAT);
    // 7) RoPE in place
    rope_kernel<<<NTOK, 512>>>(qbuf, ckv, cosb, sinb);
    // 8) flash attention
    flash_tf32_kernel<<<dim3(SEQ / FM, HEADS, BATCH), 256, FLASH_SMEM>>>(qbuf, kvbuf, ckv, attn);
    // 9) out = attn @ o_W^T
    gemm_tf32<<<dim3(DMODEL / TBN, NTOK / TBM), 256, GEMM_SMEM>>>(attn, o_W, out, NTOK, DMODEL, ODIM);
}

// round 9
// speedup vs baseline: 5.6263x; 1.0881x over previous
#include <cuda_runtime.h>
#include <cuda_bf16.h>
#include <math.h>
#include <stdint.h>

// ---------------- problem constants ----------------
#define BATCH   2
#define SEQ     2048
#define NTOK    (BATCH * SEQ)        // 4096
#define DMODEL  2048
#define HEADS   16
#define DQK     192
#define DNOPE   128
#define DROPE   64
#define DV      128
#define DQA     1536
#define DKVA    576
#define DKVLAT  512
#define QDIM    (HEADS * DQK)        // 3072
#define KVDIM   (HEADS * (DNOPE + DV)) // 4096
#define ODIM    (HEADS * DV)         // 2048
#define ATT_SCALE 0.07216878364870322f

// ---------------- scratch ----------------
__device__ float g_qa  [(size_t)NTOK * DQA];
__device__ float g_ckv [(size_t)NTOK * DKVA];
__device__ float g_kvn [(size_t)NTOK * DKVLAT];
__device__ float g_q   [(size_t)NTOK * QDIM];
__device__ float g_kv  [(size_t)NTOK * KVDIM];
__device__ float g_attn[(size_t)NTOK * ODIM];
// tf32-rounded copies (GEMM inner loop consumes raw bits; round upstream)
__device__ float g_hid_r [(size_t)NTOK * DMODEL];
__device__ float g_w_qa  [(size_t)DQA * DMODEL];
__device__ float g_w_kva [(size_t)DKVA * DMODEL];
__device__ float g_w_qb  [(size_t)QDIM * DQA];
__device__ float g_w_kvb [(size_t)KVDIM * DKVLAT];
__device__ float g_w_o   [(size_t)DMODEL * ODIM];

// ---------------- helpers ----------------
__device__ __forceinline__ float to_tf32(float x) {
    float y;
    asm("cvt.rna.tf32.f32 %0, %1;" : "=f"(y) : "f"(x));
    return y;
}

__device__ __forceinline__ uint32_t smem_u32(const void* p) {
    uint32_t a;
    asm("{ .reg .u64 t; cvta.to.shared.u64 t, %1; cvt.u32.u64 %0, t; }" : "=r"(a) : "l"(p));
    return a;
}

__device__ __forceinline__ void mma_tf32(float c[4], const uint32_t a[4], const uint32_t b[2]) {
    asm volatile(
        "mma.sync.aligned.m16n8k8.row.col.f32.tf32.tf32.f32 "
        "{%0,%1,%2,%3}, {%4,%5,%6,%7}, {%8,%9}, {%0,%1,%2,%3};\n"
        : "+f"(c[0]), "+f"(c[1]), "+f"(c[2]), "+f"(c[3])
        : "r"(a[0]), "r"(a[1]), "r"(a[2]), "r"(a[3]), "r"(b[0]), "r"(b[1]));
}

__device__ __forceinline__ void ldsm_x4(uint32_t r[4], uint32_t addr) {
    asm volatile("ldmatrix.sync.aligned.m8n8.x4.shared.b16 {%0,%1,%2,%3}, [%4];"
        : "=r"(r[0]), "=r"(r[1]), "=r"(r[2]), "=r"(r[3]) : "r"(addr));
}

// ---------------- unified dynamic smem ----------------
extern __shared__ char dynsm[];

// ============================================================================
// TF32 GEMM (mma.sync + ldmatrix) with 3-stage cp.async pipeline
// C[M,N] = A[M,K] @ B[N,K]^T, tile 128x128, K-chunk 32
// Inputs MUST be pre-rounded to tf32 (rna).
// ============================================================================
#define TBM 128
#define TBN 128
#define TBK 32
#define ASTR 36                          // row stride 144B -> ldmatrix conflict-free
#define NSTG 3
#define STG_FLOATS (TBM * ASTR + TBN * ASTR)   // 9216 floats per stage
#define GEMM_SMEM (NSTG * STG_FLOATS * (int)sizeof(float))  // 110592 B

__global__ __launch_bounds__(256) void gemm_tf32(
    const float* __restrict__ A, const float* __restrict__ Bw,
    float* __restrict__ C, int M, int N, int K)
{
    float* sm = (float*)dynsm;
    const int tid = threadIdx.x;
    const int wid = tid >> 5, lane = tid & 31;
    const int g = lane >> 2, tg = lane & 3;
    const int wm = (wid >> 2) * 64, wn = (wid & 3) * 32;
    const int bm = blockIdx.y * TBM, bn = blockIdx.x * TBN;
    const int NK = K / TBK;

    // ldmatrix per-lane source rows (in floats, within stage-local tiles)
    // A: row = wm + mt*16 + ((lane>>3)&1)*8 + (lane&7); col = (lane>>4)*4
    const int aRowOff = (wm + ((lane >> 3) & 1) * 8 + (lane & 7)) * ASTR + (lane >> 4) * 4;
    // B: row = wn + p*16 + (lane>>4)*8 + (lane&7); col = ((lane>>3)&1)*4
    const int bRowOff = (wn + (lane >> 4) * 8 + (lane & 7)) * ASTR + ((lane >> 3) & 1) * 4;

#define LOAD_STAGE(c)                                                             \
    {                                                                             \
        const int s_ = (c) % NSTG;                                                \
        float* as_ = sm + s_ * STG_FLOATS;                                        \
        float* bs_ = as_ + TBM * ASTR;                                            \
        _Pragma("unroll")                                                         \
        for (int t_ = 0; t_ < 4; t_++) {                                          \
            int idx_ = tid + t_ * 256;                                            \
            int row_ = idx_ >> 3;                                                 \
            int c4_ = (idx_ & 7) * 4;                                             \
            uint32_t d_ = smem_u32(as_ + row_ * ASTR + c4_);                      \
            const float* s1_ = A + (size_t)(bm + row_) * K + (size_t)(c) * TBK + c4_; \
            asm volatile("cp.async.cg.shared.global [%0], [%1], 16;"              \
                         :: "r"(d_), "l"(s1_));                                   \
        }                                                                         \
        _Pragma("unroll")                                                         \
        for (int t_ = 0; t_ < 4; t_++) {                                          \
            int idx_ = tid + t_ * 256;                                            \
            int row_ = idx_ >> 3;                                                 \
            int c4_ = (idx_ & 7) * 4;                                             \
            int nr_ = bn + row_;                                                  \
            uint32_t d_ = smem_u32(bs_ + row_ * ASTR + c4_);                      \
            const float* s1_ = Bw + (size_t)(nr_ < N ? nr_ : 0) * K + (size_t)(c) * TBK + c4_; \
            unsigned sz_ = (nr_ < N) ? 16u : 0u;                                  \
            asm volatile("cp.async.cg.shared.global [%0], [%1], 16, %2;"          \
                         :: "r"(d_), "l"(s1_), "r"(sz_));                         \
        }                                                                         \
        asm volatile("cp.async.commit_group;" ::: "memory");                      \
    }

    float acc[4][4][4];
#pragma unroll
    for (int mt = 0; mt < 4; mt++)
#pragma unroll
        for (int nt = 0; nt < 4; nt++)
#pragma unroll
            for (int i = 0; i < 4; i++) acc[mt][nt][i] = 0.f;

    LOAD_STAGE(0);
    LOAD_STAGE(1);

    for (int cc = 0; cc < NK; cc++) {
        asm volatile("cp.async.wait_group 1;" ::: "memory");
        __syncthreads();
        if (cc + 2 < NK) LOAD_STAGE(cc + 2);

        const int s = cc % NSTG;
        float* as_ = sm + s * STG_FLOATS;
        float* bs_ = as_ + TBM * ASTR;
        const uint32_t aBase = smem_u32(as_ + aRowOff);
        const uint32_t bBase = smem_u32(bs_ + bRowOff);

#pragma unroll
        for (int ks = 0; ks < 4; ks++) {
            const uint32_t kOff = ks * 32;   // 8 floats = 32 bytes
            uint32_t a[4][4], b[8];
#pragma unroll
            for (int mt = 0; mt < 4; mt++)
                ldsm_x4(a[mt], aBase + mt * (16 * ASTR * 4) + kOff);
            ldsm_x4(&b[0], bBase + kOff);                       // nt 0,1
            ldsm_x4(&b[4], bBase + 16 * ASTR * 4 + kOff);       // nt 2,3
#pragma unroll
            for (int mt = 0; mt < 4; mt++)
#pragma unroll
                for (int nt = 0; nt < 4; nt++)
                    mma_tf32(acc[mt][nt], a[mt], &b[nt * 2]);
        }
    }

#pragma unroll
    for (int mt = 0; mt < 4; mt++) {
        int r0 = bm + wm + mt * 16 + g;
#pragma unroll
        for (int nt = 0; nt < 4; nt++) {
            int cc = bn + wn + nt * 8 + 2 * tg;
            if (cc < N) {
                *(float2*)(C + (size_t)r0 * N + cc)       = make_float2(acc[mt][nt][0], acc[mt][nt][1]);
                *(float2*)(C + (size_t)(r0 + 8) * N + cc) = make_float2(acc[mt][nt][2], acc[mt][nt][3]);
            }
        }
    }
}

// ---------------- tf32 pre-rounding pass ----------------
__global__ __launch_bounds__(256) void round_tf32_kernel(
    const float* __restrict__ in, float* __restrict__ out, int n4)
{
    int i = blockIdx.x * 256 + threadIdx.x;
    if (i < n4) {
        float4 v = ((const float4*)in)[i];
        v.x = to_tf32(v.x); v.y = to_tf32(v.y);
        v.z = to_tf32(v.z); v.w = to_tf32(v.w);
        ((float4*)out)[i] = v;
    }
}

// ---------------- RMSNorm (tf32-rounded output: feeds GEMM) ----------------
__global__ __launch_bounds__(256) void rmsnorm_kernel(
    const float* __restrict__ in, float* __restrict__ out,
    const float* __restrict__ w, int N, int in_stride, int out_stride)
{
    const int row = blockIdx.x;
    const float* x = in + (size_t)row * in_stride;
    const int cnt = N >> 8;
    float v[6];
    float ss = 0.f;
    for (int i = 0; i < cnt; i++) {
        v[i] = x[threadIdx.x + (i << 8)];
        ss += v[i] * v[i];
    }
#pragma unroll
    for (int o = 16; o > 0; o >>= 1) ss += __shfl_xor_sync(0xffffffffu, ss, o);
    __shared__ float red[8];
    if ((threadIdx.x & 31) == 0) red[threadIdx.x >> 5] = ss;
    __syncthreads();
    float tot = 0.f;
#pragma unroll
    for (int i = 0; i < 8; i++) tot += red[i];
    const float r = rsqrtf(tot / (float)N + 1e-6f);
    float* y = out + (size_t)row * out_stride;
    for (int i = 0; i < cnt; i++) {
        int c = threadIdx.x + (i << 8);
        y[c] = to_tf32(w[c] * v[i] * r);
    }
}

// ---------------- RoPE ----------------
__global__ __launch_bounds__(512) void rope_kernel(
    float* __restrict__ q, float* __restrict__ ckv,
    const float* __restrict__ cosb, const float* __restrict__ sinb)
{
    const int tok = blockIdx.x;
    const int t = threadIdx.x;
    const int h = t >> 5;
    const int d = t & 31;
    const float c0 = cosb[(size_t)tok * DROPE + d];
    const float s0 = sinb[(size_t)tok * DROPE + d];
    const float c1 = cosb[(size_t)tok * DROPE + d + 32];
    const float s1 = sinb[(size_t)tok * DROPE + d + 32];
    {
        float* qr = q + (size_t)tok * QDIM + h * DQK + DNOPE;
        float a = qr[d], b = qr[d + 32];
        qr[d]      = a * c0 - b * s0;
        qr[d + 32] = b * c1 + a * s1;
    }
    if (t < 32) {
        float* kr = ckv + (size_t)tok * DKVA + DKVLAT;
        float a = kr[d], b = kr[d + 32];
        kr[d]      = a * c0 - b * s0;
        kr[d + 32] = b * c1 + a * s1;
    }
}

// ---------------- Flash attention (tf32 mma.sync, causal) ----------------
#define FM 128
#define FN 64
#define SQ_STR 196
#define SK_STR 196
#define SV_STR 136
#define SP_STR 68
#define FLASH_SMEM ((FM * SQ_STR + FN * SK_STR + FN * SV_STR + FM * SP_STR) * (int)sizeof(float))

__global__ __launch_bounds__(256) void flash_tf32_kernel(
    const float* __restrict__ q, const float* __restrict__ kvbuf,
    const float* __restrict__ ckv, float* __restrict__ attn_out)
{
    float* fsmem = (float*)dynsm;
    float* sQ = fsmem;
    float* sK = sQ + FM * SQ_STR;
    float* sV = sK + FN * SK_STR;
    float* sP = sV + FN * SV_STR;

    // longest tiles first: trims the multi-wave straggler tail (work ∝ bq+1)
    const int bq = gridDim.x - 1 - blockIdx.x;
    const int h  = blockIdx.y;
    const int b  = blockIdx.z;
    const int q0 = bq * FM;
    const int tid = threadIdx.x;
    const int wid = tid >> 5, lane = tid & 31;
    const int g = lane >> 2, tg = lane & 3;
    const int wrow = wid * 16;

    const size_t qbase = ((size_t)(b * SEQ + q0)) * QDIM + (size_t)h * DQK;
    for (int e = tid; e < FM * (DQK / 4); e += 256) {
        int r = e / (DQK / 4), c4 = (e - r * (DQK / 4)) * 4;
        float4 v = *(const float4*)(q + qbase + (size_t)r * QDIM + c4);
        sQ[r * SQ_STR + c4 + 0] = to_tf32(v.x * ATT_SCALE);
        sQ[r * SQ_STR + c4 + 1] = to_tf32(v.y * ATT_SCALE);
        sQ[r * SQ_STR + c4 + 2] = to_tf32(v.z * ATT_SCALE);
        sQ[r * SQ_STR + c4 + 3] = to_tf32(v.w * ATT_SCALE);
    }

    float o[16][4];
#pragma unroll
    for (int nt = 0; nt < 16; nt++)
#pragma unroll
        for (int i = 0; i < 4; i++) o[nt][i] = 0.f;
    float m0 = -1e30f, m1 = -1e30f, l0 = 0.f, l1 = 0.f;

    const int nkt = (q0 + FM) / FN;
    for (int kt = 0; kt < nkt; kt++) {
        __syncthreads();
        const size_t kvb = ((size_t)(b * SEQ + kt * FN)) * KVDIM + (size_t)h * (DNOPE + DV);
        const size_t ckb = ((size_t)(b * SEQ + kt * FN)) * DKVA + DKVLAT;
        for (int e = tid; e < FN * (DQK / 4); e += 256) {
            int r = e / (DQK / 4), c4 = (e - r * (DQK / 4)) * 4;
            float4 v;
            if (c4 < DNOPE) v = *(const float4*)(kvbuf + kvb + (size_t)r * KVDIM + c4);
            else            v = *(const float4*)(ckv + ckb + (size_t)r * DKVA + (c4 - DNOPE));
            sK[r * SK_STR + c4 + 0] = to_tf32(v.x);
            sK[r * SK_STR + c4 + 1] = to_tf32(v.y);
            sK[r * SK_STR + c4 + 2] = to_tf32(v.z);
            sK[r * SK_STR + c4 + 3] = to_tf32(v.w);
        }
        for (int e = tid; e < FN * (DV / 4); e += 256) {
            int r = e >> 5, c4 = (e & 31) * 4;
            float4 v = *(const float4*)(kvbuf + kvb + (size_t)r * KVDIM + DNOPE + c4);
            sV[r * SV_STR + c4 + 0] = to_tf32(v.x);
            sV[r * SV_STR + c4 + 1] = to_tf32(v.y);
            sV[r * SV_STR + c4 + 2] = to_tf32(v.z);
            sV[r * SV_STR + c4 + 3] = to_tf32(v.w);
        }
        __syncthreads();

        float s[8][4];
#pragma unroll
        for (int nt = 0; nt < 8; nt++)
#pragma unroll
            for (int i = 0; i < 4; i++) s[nt][i] = 0.f;

#pragma unroll 4
        for (int ks = 0; ks < DQK / 8; ks++) {
            const int kb = ks * 8;
            uint32_t a[4], bb[8][2];
            a[0] = __float_as_uint(sQ[(wrow + g    ) * SQ_STR + kb + tg]);
            a[1] = __float_as_uint(sQ[(wrow + g + 8) * SQ_STR + kb + tg]);
            a[2] = __float_as_uint(sQ[(wrow + g    ) * SQ_STR + kb + tg + 4]);
            a[3] = __float_as_uint(sQ[(wrow + g + 8) * SQ_STR + kb + tg + 4]);
#pragma unroll
            for (int nt = 0; nt < 8; nt++) {
                bb[nt][0] = __float_as_uint(sK[(nt * 8 + g) * SK_STR + kb + tg]);
                bb[nt][1] = __float_as_uint(sK[(nt * 8 + g) * SK_STR + kb + tg + 4]);
            }
#pragma unroll
            for (int nt = 0; nt < 8; nt++)
                mma_tf32(s[nt], a, bb[nt]);
        }

        if (kt * FN + FN - 1 > q0) {
            const int gr0 = q0 + wrow + g;
            const int gr1 = gr0 + 8;
#pragma unroll
            for (int nt = 0; nt < 8; nt++) {
                int gc = kt * FN + nt * 8 + 2 * tg;
                if (gc     > gr0) s[nt][0] = -1e30f;
                if (gc + 1 > gr0) s[nt][1] = -1e30f;
                if (gc     > gr1) s[nt][2] = -1e30f;
                if (gc + 1 > gr1) s[nt][3] = -1e30f;
            }
        }

        float mx0 = -1e30f, mx1 = -1e30f;
#pragma unroll
        for (int nt = 0; nt < 8; nt++) {
            mx0 = fmaxf(mx0, fmaxf(s[nt][0], s[nt][1]));
            mx1 = fmaxf(mx1, fmaxf(s[nt][2], s[nt][3]));
        }
#pragma unroll
        for (int o_ = 1; o_ < 4; o_ <<= 1) {
            mx0 = fmaxf(mx0, __shfl_xor_sync(0xffffffffu, mx0, o_));
            mx1 = fmaxf(mx1, __shfl_xor_sync(0xffffffffu, mx1, o_));
        }
        const float mn0 = fmaxf(m0, mx0);
        const float mn1 = fmaxf(m1, mx1);
        const float sc0 = __expf(m0 - mn0);
        const float sc1 = __expf(m1 - mn1);
        float rs0 = 0.f, rs1 = 0.f;
#pragma unroll
        for (int nt = 0; nt < 8; nt++) {
            s[nt][0] = __expf(s[nt][0] - mn0);
            s[nt][1] = __expf(s[nt][1] - mn0);
            s[nt][2] = __expf(s[nt][2] - mn1);
            s[nt][3] = __expf(s[nt][3] - mn1);
            rs0 += s[nt][0] + s[nt][1];
            rs1 += s[nt][2] + s[nt][3];
        }
#pragma unroll
        for (int o_ = 1; o_ < 4; o_ <<= 1) {
            rs0 += __shfl_xor_sync(0xffffffffu, rs0, o_);
            rs1 += __shfl_xor_sync(0xffffffffu, rs1, o_);
        }
        l0 = l0 * sc0 + rs0;  m0 = mn0;
        l1 = l1 * sc1 + rs1;  m1 = mn1;
#pragma unroll
        for (int nt = 0; nt < 16; nt++) {
            o[nt][0] *= sc0; o[nt][1] *= sc0;
            o[nt][2] *= sc1; o[nt][3] *= sc1;
        }
#pragma unroll
        for (int nt = 0; nt < 8; nt++) {
            int col = nt * 8 + 2 * tg;
            sP[(wrow + g    ) * SP_STR + col]     = to_tf32(s[nt][0]);
            sP[(wrow + g    ) * SP_STR + col + 1] = to_tf32(s[nt][1]);
            sP[(wrow + g + 8) * SP_STR + col]     = to_tf32(s[nt][2]);
            sP[(wrow + g + 8) * SP_STR + col + 1] = to_tf32(s[nt][3]);
        }
        __syncwarp();

#pragma unroll 2
        for (int ks = 0; ks < FN / 8; ks++) {
            const int kb = ks * 8;
            uint32_t a[4];
            a[0] = __float_as_uint(sP[(wrow + g    ) * SP_STR + kb + tg]);
            a[1] = __float_as_uint(sP[(wrow + g + 8) * SP_STR + kb + tg]);
            a[2] = __float_as_uint(sP[(wrow + g    ) * SP_STR + kb + tg + 4]);
            a[3] = __float_as_uint(sP[(wrow + g + 8) * SP_STR + kb + tg + 4]);
#pragma unroll
            for (int nt = 0; nt < 16; nt++) {
                uint32_t bb[2];
                bb[0] = __float_as_uint(sV[(kb + tg    ) * SV_STR + nt * 8 + g]);
                bb[1] = __float_as_uint(sV[(kb + tg + 4) * SV_STR + nt * 8 + g]);
                mma_tf32(o[nt], a, bb);
            }
        }
    }

    // epilogue: tf32-rounded (feeds o-proj GEMM which consumes raw bits)
    const float inv0 = 1.f / l0, inv1 = 1.f / l1;
    const size_t obase = ((size_t)(b * SEQ + q0)) * ODIM + (size_t)h * DV;
    const size_t r0 = obase + (size_t)(wrow + g) * ODIM;
    const size_t r1 = obase + (size_t)(wrow + g + 8) * ODIM;
#pragma unroll
    for (int nt = 0; nt < 16; nt++) {
        int col = nt * 8 + 2 * tg;
        *(float2*)(attn_out + r0 + col) = make_float2(to_tf32(o[nt][0] * inv0), to_tf32(o[nt][1] * inv0));
        *(float2*)(attn_out + r1 + col) = make_float2(to_tf32(o[nt][2] * inv1), to_tf32(o[nt][3] * inv1));
    }
}

// ---------------- launch ----------------
static inline void round_buf(const float* in, float* out, size_t n) {
    int n4 = (int)(n / 4);
    round_tf32_kernel<<<(n4 + 255) / 256, 256>>>(in, out, n4);
}

extern "C" void kernel_launch(void* const* d_in, const int* in_sizes, int n_in,
                              void* d_out, int out_size)
{
    (void)in_sizes; (void)n_in; (void)out_size;
    const float* hidden  = (const float*)d_in[0];
    const float* cosb    = (const float*)d_in[1];
    const float* sinb    = (const float*)d_in[2];
    const float* q_a_W   = (const float*)d_in[3];
    const float* q_a_nw  = (const float*)d_in[4];
    const float* q_b_W   = (const float*)d_in[5];
    const float* kv_a_W  = (const float*)d_in[6];
    const float* kv_a_nw = (const float*)d_in[7];
    const float* kv_b_W  = (const float*)d_in[8];
    const float* o_W     = (const float*)d_in[9];
    float* out = (float*)d_out;

    float *qa, *ckv, *kvn, *qbuf, *kvbuf, *attn;
    float *hid_r, *w_qa, *w_kva, *w_qb, *w_kvb, *w_o;
    cudaGetSymbolAddress((void**)&qa,    g_qa);
    cudaGetSymbolAddress((void**)&ckv,   g_ckv);
    cudaGetSymbolAddress((void**)&kvn,   g_kvn);
    cudaGetSymbolAddress((void**)&qbuf,  g_q);
    cudaGetSymbolAddress((void**)&kvbuf, g_kv);
    cudaGetSymbolAddress((void**)&attn,  g_attn);
    cudaGetSymbolAddress((void**)&hid_r, g_hid_r);
    cudaGetSymbolAddress((void**)&w_qa,  g_w_qa);
    cudaGetSymbolAddress((void**)&w_kva, g_w_kva);
    cudaGetSymbolAddress((void**)&w_qb,  g_w_qb);
    cudaGetSymbolAddress((void**)&w_kvb, g_w_kvb);
    cudaGetSymbolAddress((void**)&w_o,   g_w_o);

    cudaFuncSetAttribute(gemm_tf32, cudaFuncAttributeMaxDynamicSharedMemorySize, GEMM_SMEM);
    cudaFuncSetAttribute(flash_tf32_kernel, cudaFuncAttributeMaxDynamicSharedMemorySize, FLASH_SMEM);

    // one-time tf32 rna-rounding of GEMM inputs
    round_buf(hidden, hid_r, (size_t)NTOK * DMODEL);
    round_buf(q_a_W,  w_qa,  (size_t)DQA * DMODEL);
    round_buf(kv_a_W, w_kva, (size_t)DKVA * DMODEL);
    round_buf(q_b_W,  w_qb,  (size_t)QDIM * DQA);
    round_buf(kv_b_W, w_kvb, (size_t)KVDIM * DKVLAT);
    round_buf(o_W,    w_o,   (size_t)DMODEL * ODIM);

    // 1) q_a = hidden @ q_a_W^T
    gemm_tf32<<<dim3(DQA / TBN, NTOK / TBM), 256, GEMM_SMEM>>>(hid_r, w_qa, qa, NTOK, DQA, DMODEL);
    // 2) ckv = hidden @ kv_a_W^T  (N=576, edge tile guarded)
    gemm_tf32<<<dim3((DKVA + TBN - 1) / TBN, NTOK / TBM), 256, GEMM_SMEM>>>(hid_r, w_kva, ckv, NTOK, DKVA, DMODEL);
    // 3) rmsnorm q_a (in place, tf32-rounded out)
    rmsnorm_kernel<<<NTOK, 256>>>(qa, qa, q_a_nw, DQA, DQA, DQA);
    // 4) rmsnorm kv latent (tf32-rounded out)
    rmsnorm_kernel<<<NTOK, 256>>>(ckv, kvn, kv_a_nw, DKVLAT, DKVA, DKVLAT);
    // 5) q = qa_norm @ q_b_W^T
    gemm_tf32<<<dim3(QDIM / TBN, NTOK / TBM), 256, GEMM_SMEM>>>(qa, w_qb, qbuf, NTOK, QDIM, DQA);
    // 6) kv = kvn @ kv_b_W^T
    gemm_tf32<<<dim3(KVDIM / TBN, NTOK / TBM), 256, GEMM_SMEM>>>(kvn, w_kvb, kvbuf, NTOK, KVDIM, DKVLAT);
    // 7) RoPE in place
    rope_kernel<<<NTOK, 512>>>(qbuf, ckv, cosb, sinb);
    // 8) flash attention
    flash_tf32_kernel<<<dim3(SEQ / FM, HEADS, BATCH), 256, FLASH_SMEM>>>(qbuf, kvbuf, ckv, attn);
    // 9) out = attn @ o_W^T
    gemm_tf32<<<dim3(DMODEL / TBN, NTOK / TBM), 256, GEMM_SMEM>>>(attn, o_W, out, NTOK, DMODEL, ODIM);
}

// round 10
// speedup vs baseline: 5.6560x; 1.0053x over previous
#include <cuda_runtime.h>
#include <cuda_bf16.h>
#include <math.h>
#include <stdint.h>

// ---------------- problem constants ----------------
#define BATCH   2
#define SEQ     2048
#define NTOK    (BATCH * SEQ)        // 4096
#define DMODEL  2048
#define HEADS   16
#define DQK     192
#define DNOPE   128
#define DROPE   64
#define DV      128
#define DQA     1536
#define DKVA    576
#define DKVLAT  512
#define QDIM    (HEADS * DQK)        // 3072
#define KVDIM   (HEADS * (DNOPE + DV)) // 4096
#define ODIM    (HEADS * DV)         // 2048
#define ATT_SCALE 0.07216878364870322f

// ---------------- scratch ----------------
__device__ float g_qa  [(size_t)NTOK * DQA];
__device__ float g_ckv [(size_t)NTOK * DKVA];
__device__ float g_kvn [(size_t)NTOK * DKVLAT];
__device__ float g_q   [(size_t)NTOK * QDIM];
__device__ float g_kv  [(size_t)NTOK * KVDIM];
__device__ float g_attn[(size_t)NTOK * ODIM];
// tf32-rounded copies (GEMM inner loop consumes raw bits; round upstream)
__device__ float g_hid_r [(size_t)NTOK * DMODEL];
__device__ float g_w_qa  [(size_t)DQA * DMODEL];
__device__ float g_w_kva [(size_t)DKVA * DMODEL];
__device__ float g_w_qb  [(size_t)QDIM * DQA];
__device__ float g_w_kvb [(size_t)KVDIM * DKVLAT];
__device__ float g_w_o   [(size_t)DMODEL * ODIM];

// ---------------- helpers ----------------
__device__ __forceinline__ float to_tf32(float x) {
    float y;
    asm("cvt.rna.tf32.f32 %0, %1;" : "=f"(y) : "f"(x));
    return y;
}

__device__ __forceinline__ uint32_t smem_u32(const void* p) {
    uint32_t a;
    asm("{ .reg .u64 t; cvta.to.shared.u64 t, %1; cvt.u32.u64 %0, t; }" : "=r"(a) : "l"(p));
    return a;
}

__device__ __forceinline__ void mma_tf32(float c[4], const uint32_t a[4], const uint32_t b[2]) {
    asm volatile(
        "mma.sync.aligned.m16n8k8.row.col.f32.tf32.tf32.f32 "
        "{%0,%1,%2,%3}, {%4,%5,%6,%7}, {%8,%9}, {%0,%1,%2,%3};\n"
        : "+f"(c[0]), "+f"(c[1]), "+f"(c[2]), "+f"(c[3])
        : "r"(a[0]), "r"(a[1]), "r"(a[2]), "r"(a[3]), "r"(b[0]), "r"(b[1]));
}

__device__ __forceinline__ void ldsm_x4(uint32_t r[4], uint32_t addr) {
    asm volatile("ldmatrix.sync.aligned.m8n8.x4.shared.b16 {%0,%1,%2,%3}, [%4];"
        : "=r"(r[0]), "=r"(r[1]), "=r"(r[2]), "=r"(r[3]) : "r"(addr));
}

// ---------------- unified dynamic smem ----------------
extern __shared__ char dynsm[];

// ============================================================================
// TF32 GEMM (mma.sync + ldmatrix) with 3-stage cp.async pipeline
// C[M,N] = A[M,K] @ B[N,K]^T, tile 128x128, K-chunk 32
// Inputs MUST be pre-rounded to tf32 (rna).
// ============================================================================
#define TBM 128
#define TBN 128
#define TBK 32
#define ASTR 36                          // row stride 144B -> ldmatrix conflict-free
#define NSTG 3
#define STG_FLOATS (TBM * ASTR + TBN * ASTR)   // 9216 floats per stage
#define GEMM_SMEM (NSTG * STG_FLOATS * (int)sizeof(float))  // 110592 B

__global__ __launch_bounds__(256) void gemm_tf32(
    const float* __restrict__ A, const float* __restrict__ Bw,
    float* __restrict__ C, int M, int N, int K)
{
    float* sm = (float*)dynsm;
    const int tid = threadIdx.x;
    const int wid = tid >> 5, lane = tid & 31;
    const int g = lane >> 2, tg = lane & 3;
    const int wm = (wid >> 2) * 64, wn = (wid & 3) * 32;
    const int bm = blockIdx.y * TBM, bn = blockIdx.x * TBN;
    const int NK = K / TBK;

    const int aRowOff = (wm + ((lane >> 3) & 1) * 8 + (lane & 7)) * ASTR + (lane >> 4) * 4;
    const int bRowOff = (wn + (lane >> 4) * 8 + (lane & 7)) * ASTR + ((lane >> 3) & 1) * 4;

#define LOAD_STAGE(c)                                                             \
    {                                                                             \
        const int s_ = (c) % NSTG;                                                \
        float* as_ = sm + s_ * STG_FLOATS;                                        \
        float* bs_ = as_ + TBM * ASTR;                                            \
        _Pragma("unroll")                                                         \
        for (int t_ = 0; t_ < 4; t_++) {                                          \
            int idx_ = tid + t_ * 256;                                            \
            int row_ = idx_ >> 3;                                                 \
            int c4_ = (idx_ & 7) * 4;                                             \
            uint32_t d_ = smem_u32(as_ + row_ * ASTR + c4_);                      \
            const float* s1_ = A + (size_t)(bm + row_) * K + (size_t)(c) * TBK + c4_; \
            asm volatile("cp.async.cg.shared.global [%0], [%1], 16;"              \
                         :: "r"(d_), "l"(s1_));                                   \
        }                                                                         \
        _Pragma("unroll")                                                         \
        for (int t_ = 0; t_ < 4; t_++) {                                          \
            int idx_ = tid + t_ * 256;                                            \
            int row_ = idx_ >> 3;                                                 \
            int c4_ = (idx_ & 7) * 4;                                             \
            int nr_ = bn + row_;                                                  \
            uint32_t d_ = smem_u32(bs_ + row_ * ASTR + c4_);                      \
            const float* s1_ = Bw + (size_t)(nr_ < N ? nr_ : 0) * K + (size_t)(c) * TBK + c4_; \
            unsigned sz_ = (nr_ < N) ? 16u : 0u;                                  \
            asm volatile("cp.async.cg.shared.global [%0], [%1], 16, %2;"          \
                         :: "r"(d_), "l"(s1_), "r"(sz_));                         \
        }                                                                         \
        asm volatile("cp.async.commit_group;" ::: "memory");                      \
    }

    float acc[4][4][4];
#pragma unroll
    for (int mt = 0; mt < 4; mt++)
#pragma unroll
        for (int nt = 0; nt < 4; nt++)
#pragma unroll
            for (int i = 0; i < 4; i++) acc[mt][nt][i] = 0.f;

    LOAD_STAGE(0);
    LOAD_STAGE(1);

    for (int cc = 0; cc < NK; cc++) {
        asm volatile("cp.async.wait_group 1;" ::: "memory");
        __syncthreads();
        if (cc + 2 < NK) LOAD_STAGE(cc + 2);

        const int s = cc % NSTG;
        float* as_ = sm + s * STG_FLOATS;
        float* bs_ = as_ + TBM * ASTR;
        const uint32_t aBase = smem_u32(as_ + aRowOff);
        const uint32_t bBase = smem_u32(bs_ + bRowOff);

#pragma unroll
        for (int ks = 0; ks < 4; ks++) {
            const uint32_t kOff = ks * 32;
            uint32_t a[4][4], b[8];
#pragma unroll
            for (int mt = 0; mt < 4; mt++)
                ldsm_x4(a[mt], aBase + mt * (16 * ASTR * 4) + kOff);
            ldsm_x4(&b[0], bBase + kOff);
            ldsm_x4(&b[4], bBase + 16 * ASTR * 4 + kOff);
#pragma unroll
            for (int mt = 0; mt < 4; mt++)
#pragma unroll
                for (int nt = 0; nt < 4; nt++)
                    mma_tf32(acc[mt][nt], a[mt], &b[nt * 2]);
        }
    }

#pragma unroll
    for (int mt = 0; mt < 4; mt++) {
        int r0 = bm + wm + mt * 16 + g;
#pragma unroll
        for (int nt = 0; nt < 4; nt++) {
            int cc = bn + wn + nt * 8 + 2 * tg;
            if (cc < N) {
                *(float2*)(C + (size_t)r0 * N + cc)       = make_float2(acc[mt][nt][0], acc[mt][nt][1]);
                *(float2*)(C + (size_t)(r0 + 8) * N + cc) = make_float2(acc[mt][nt][2], acc[mt][nt][3]);
            }
        }
    }
}

// ---------------- tf32 pre-rounding pass ----------------
__global__ __launch_bounds__(256) void round_tf32_kernel(
    const float* __restrict__ in, float* __restrict__ out, int n4)
{
    int i = blockIdx.x * 256 + threadIdx.x;
    if (i < n4) {
        float4 v = ((const float4*)in)[i];
        v.x = to_tf32(v.x); v.y = to_tf32(v.y);
        v.z = to_tf32(v.z); v.w = to_tf32(v.w);
        ((float4*)out)[i] = v;
    }
}

// ---------------- RMSNorm (tf32-rounded output: feeds GEMM) ----------------
__global__ __launch_bounds__(256) void rmsnorm_kernel(
    const float* __restrict__ in, float* __restrict__ out,
    const float* __restrict__ w, int N, int in_stride, int out_stride)
{
    const int row = blockIdx.x;
    const float* x = in + (size_t)row * in_stride;
    const int cnt = N >> 8;
    float v[6];
    float ss = 0.f;
    for (int i = 0; i < cnt; i++) {
        v[i] = x[threadIdx.x + (i << 8)];
        ss += v[i] * v[i];
    }
#pragma unroll
    for (int o = 16; o > 0; o >>= 1) ss += __shfl_xor_sync(0xffffffffu, ss, o);
    __shared__ float red[8];
    if ((threadIdx.x & 31) == 0) red[threadIdx.x >> 5] = ss;
    __syncthreads();
    float tot = 0.f;
#pragma unroll
    for (int i = 0; i < 8; i++) tot += red[i];
    const float r = rsqrtf(tot / (float)N + 1e-6f);
    float* y = out + (size_t)row * out_stride;
    for (int i = 0; i < cnt; i++) {
        int c = threadIdx.x + (i << 8);
        y[c] = to_tf32(w[c] * v[i] * r);
    }
}

// ---------------- RoPE ----------------
__global__ __launch_bounds__(512) void rope_kernel(
    float* __restrict__ q, float* __restrict__ ckv,
    const float* __restrict__ cosb, const float* __restrict__ sinb)
{
    const int tok = blockIdx.x;
    const int t = threadIdx.x;
    const int h = t >> 5;
    const int d = t & 31;
    const float c0 = cosb[(size_t)tok * DROPE + d];
    const float s0 = sinb[(size_t)tok * DROPE + d];
    const float c1 = cosb[(size_t)tok * DROPE + d + 32];
    const float s1 = sinb[(size_t)tok * DROPE + d + 32];
    {
        float* qr = q + (size_t)tok * QDIM + h * DQK + DNOPE;
        float a = qr[d], b = qr[d + 32];
        qr[d]      = a * c0 - b * s0;
        qr[d + 32] = b * c1 + a * s1;
    }
    if (t < 32) {
        float* kr = ckv + (size_t)tok * DKVA + DKVLAT;
        float a = kr[d], b = kr[d + 32];
        kr[d]      = a * c0 - b * s0;
        kr[d + 32] = b * c1 + a * s1;
    }
}

// ---------------- Flash attention (tf32 mma.sync + ldmatrix, causal) ------
#define FM 128
#define FN 64
#define SQ_STR 196   // %32 == 4
#define SK_STR 196   // %32 == 4
#define VT_STR 68    // transposed V: [DV][FN], %32 == 4
#define SP_STR 68    // %32 == 4
#define FLASH_SMEM ((FM * SQ_STR + FN * SK_STR + DV * VT_STR + FM * SP_STR) * (int)sizeof(float))

__global__ __launch_bounds__(256) void flash_tf32_kernel(
    const float* __restrict__ q, const float* __restrict__ kvbuf,
    const float* __restrict__ ckv, float* __restrict__ attn_out)
{
    float* fsmem = (float*)dynsm;
    float* sQ  = fsmem;                   // 128 x 196
    float* sK  = sQ + FM * SQ_STR;        // 64 x 196
    float* sVt = sK + FN * SK_STR;        // 128 x 68 (transposed: [dv][k])
    float* sP  = sVt + DV * VT_STR;       // 128 x 68

    // longest tiles first: trims the multi-wave straggler tail (work ∝ bq+1)
    const int bq = gridDim.x - 1 - blockIdx.x;
    const int h  = blockIdx.y;
    const int b  = blockIdx.z;
    const int q0 = bq * FM;
    const int tid = threadIdx.x;
    const int wid = tid >> 5, lane = tid & 31;
    const int g = lane >> 2, tg = lane & 3;
    const int wrow = wid * 16;

    // ldmatrix per-lane offsets (A-pattern / B-pattern, validated in gemm)
    const int aSel = ((lane >> 3) & 1) * 8 + (lane & 7);   // A: row within 16
    const int aCol = (lane >> 4) * 4;                      // A: col within 8
    const int bSel = (lane >> 4) * 8 + (lane & 7);         // B: row within 16
    const int bCol = ((lane >> 3) & 1) * 4;                // B: col within 8

    const uint32_t qBase = smem_u32(sQ  + (wrow + aSel) * SQ_STR + aCol);
    const uint32_t kBase = smem_u32(sK  + bSel * SK_STR + bCol);
    const uint32_t pBase = smem_u32(sP  + (wrow + aSel) * SP_STR + aCol);
    const uint32_t vBase = smem_u32(sVt + bSel * VT_STR + bCol);

    const size_t qbase = ((size_t)(b * SEQ + q0)) * QDIM + (size_t)h * DQK;
    for (int e = tid; e < FM * (DQK / 4); e += 256) {
        int r = e / (DQK / 4), c4 = (e - r * (DQK / 4)) * 4;
        float4 v = *(const float4*)(q + qbase + (size_t)r * QDIM + c4);
        sQ[r * SQ_STR + c4 + 0] = to_tf32(v.x * ATT_SCALE);
        sQ[r * SQ_STR + c4 + 1] = to_tf32(v.y * ATT_SCALE);
        sQ[r * SQ_STR + c4 + 2] = to_tf32(v.z * ATT_SCALE);
        sQ[r * SQ_STR + c4 + 3] = to_tf32(v.w * ATT_SCALE);
    }

    float o[16][4];
#pragma unroll
    for (int nt = 0; nt < 16; nt++)
#pragma unroll
        for (int i = 0; i < 4; i++) o[nt][i] = 0.f;
    float m0 = -1e30f, m1 = -1e30f, l0 = 0.f, l1 = 0.f;

    const int nkt = (q0 + FM) / FN;
    for (int kt = 0; kt < nkt; kt++) {
        __syncthreads();
        const size_t kvb = ((size_t)(b * SEQ + kt * FN)) * KVDIM + (size_t)h * (DNOPE + DV);
        const size_t ckb = ((size_t)(b * SEQ + kt * FN)) * DKVA + DKVLAT;
        // K tile: [64][192] = kv_nope(128) | roped rot(64)
        for (int e = tid; e < FN * (DQK / 4); e += 256) {
            int r = e / (DQK / 4), c4 = (e - r * (DQK / 4)) * 4;
            float4 v;
            if (c4 < DNOPE) v = *(const float4*)(kvbuf + kvb + (size_t)r * KVDIM + c4);
            else            v = *(const float4*)(ckv + ckb + (size_t)r * DKVA + (c4 - DNOPE));
            sK[r * SK_STR + c4 + 0] = to_tf32(v.x);
            sK[r * SK_STR + c4 + 1] = to_tf32(v.y);
            sK[r * SK_STR + c4 + 2] = to_tf32(v.z);
            sK[r * SK_STR + c4 + 3] = to_tf32(v.w);
        }
        // V tile, TRANSPOSED into sVt[dv][k]  (dv = 0..127, k = 0..63)
        for (int e = tid; e < DV * (FN / 4); e += 256) {
            int c  = e & 127;          // dv column
            int rg = e >> 7;           // k row-group (4 rows)
            const float* src = kvbuf + kvb + (size_t)(rg * 4) * KVDIM + DNOPE + c;
            float4 w;
            w.x = to_tf32(src[0]);
            w.y = to_tf32(src[KVDIM]);
            w.z = to_tf32(src[2 * KVDIM]);
            w.w = to_tf32(src[3 * KVDIM]);
            *(float4*)(sVt + c * VT_STR + rg * 4) = w;
        }
        __syncthreads();

        // ---- S = Q K^T : warp computes 16 x 64 (8 n-tiles), ldmatrix ----
        float s[8][4];
#pragma unroll
        for (int nt = 0; nt < 8; nt++)
#pragma unroll
            for (int i = 0; i < 4; i++) s[nt][i] = 0.f;

#pragma unroll 4
        for (int ks = 0; ks < DQK / 8; ks++) {
            const uint32_t kOff = ks * 32;
            uint32_t a[4];
            ldsm_x4(a, qBase + kOff);
#pragma unroll
            for (int nt2 = 0; nt2 < 4; nt2++) {
                uint32_t b4[4];
                ldsm_x4(b4, kBase + nt2 * (16 * SK_STR * 4) + kOff);
                mma_tf32(s[nt2 * 2],     a, &b4[0]);
                mma_tf32(s[nt2 * 2 + 1], a, &b4[2]);
            }
        }

        if (kt * FN + FN - 1 > q0) {
            const int gr0 = q0 + wrow + g;
            const int gr1 = gr0 + 8;
#pragma unroll
            for (int nt = 0; nt < 8; nt++) {
                int gc = kt * FN + nt * 8 + 2 * tg;
                if (gc     > gr0) s[nt][0] = -1e30f;
                if (gc + 1 > gr0) s[nt][1] = -1e30f;
                if (gc     > gr1) s[nt][2] = -1e30f;
                if (gc + 1 > gr1) s[nt][3] = -1e30f;
            }
        }

        // ---- online softmax (rows g, g+8; reduce over 4 tg lanes) ----
        float mx0 = -1e30f, mx1 = -1e30f;
#pragma unroll
        for (int nt = 0; nt < 8; nt++) {
            mx0 = fmaxf(mx0, fmaxf(s[nt][0], s[nt][1]));
            mx1 = fmaxf(mx1, fmaxf(s[nt][2], s[nt][3]));
        }
#pragma unroll
        for (int o_ = 1; o_ < 4; o_ <<= 1) {
            mx0 = fmaxf(mx0, __shfl_xor_sync(0xffffffffu, mx0, o_));
            mx1 = fmaxf(mx1, __shfl_xor_sync(0xffffffffu, mx1, o_));
        }
        const float mn0 = fmaxf(m0, mx0);
        const float mn1 = fmaxf(m1, mx1);
        const float sc0 = __expf(m0 - mn0);
        const float sc1 = __expf(m1 - mn1);
        float rs0 = 0.f, rs1 = 0.f;
#pragma unroll
        for (int nt = 0; nt < 8; nt++) {
            s[nt][0] = __expf(s[nt][0] - mn0);
            s[nt][1] = __expf(s[nt][1] - mn0);
            s[nt][2] = __expf(s[nt][2] - mn1);
            s[nt][3] = __expf(s[nt][3] - mn1);
            rs0 += s[nt][0] + s[nt][1];
            rs1 += s[nt][2] + s[nt][3];
        }
#pragma unroll
        for (int o_ = 1; o_ < 4; o_ <<= 1) {
            rs0 += __shfl_xor_sync(0xffffffffu, rs0, o_);
            rs1 += __shfl_xor_sync(0xffffffffu, rs1, o_);
        }
        l0 = l0 * sc0 + rs0;  m0 = mn0;
        l1 = l1 * sc1 + rs1;  m1 = mn1;
#pragma unroll
        for (int nt = 0; nt < 16; nt++) {
            o[nt][0] *= sc0; o[nt][1] *= sc0;
            o[nt][2] *= sc1; o[nt][3] *= sc1;
        }
#pragma unroll
        for (int nt = 0; nt < 8; nt++) {
            int col = nt * 8 + 2 * tg;
            sP[(wrow + g    ) * SP_STR + col]     = to_tf32(s[nt][0]);
            sP[(wrow + g    ) * SP_STR + col + 1] = to_tf32(s[nt][1]);
            sP[(wrow + g + 8) * SP_STR + col]     = to_tf32(s[nt][2]);
            sP[(wrow + g + 8) * SP_STR + col + 1] = to_tf32(s[nt][3]);
        }
        __syncwarp();

        // ---- O += P V : 16 n-tiles over DV, ldmatrix for both operands ----
#pragma unroll 2
        for (int ks = 0; ks < FN / 8; ks++) {
            const uint32_t kOff = ks * 32;
            uint32_t a[4];
            ldsm_x4(a, pBase + kOff);
#pragma unroll
            for (int nt2 = 0; nt2 < 8; nt2++) {
                uint32_t b4[4];
                ldsm_x4(b4, vBase + nt2 * (16 * VT_STR * 4) + kOff);
                mma_tf32(o[nt2 * 2],     a, &b4[0]);
                mma_tf32(o[nt2 * 2 + 1], a, &b4[2]);
            }
        }
    }

    // epilogue: tf32-rounded (feeds o-proj GEMM which consumes raw bits)
    const float inv0 = 1.f / l0, inv1 = 1.f / l1;
    const size_t obase = ((size_t)(b * SEQ + q0)) * ODIM + (size_t)h * DV;
    const size_t r0 = obase + (size_t)(wrow + g) * ODIM;
    const size_t r1 = obase + (size_t)(wrow + g + 8) * ODIM;
#pragma unroll
    for (int nt = 0; nt < 16; nt++) {
        int col = nt * 8 + 2 * tg;
        *(float2*)(attn_out + r0 + col) = make_float2(to_tf32(o[nt][0] * inv0), to_tf32(o[nt][1] * inv0));
        *(float2*)(attn_out + r1 + col) = make_float2(to_tf32(o[nt][2] * inv1), to_tf32(o[nt][3] * inv1));
    }
}

// ---------------- launch ----------------
static inline void round_buf(const float* in, float* out, size_t n) {
    int n4 = (int)(n / 4);
    round_tf32_kernel<<<(n4 + 255) / 256, 256>>>(in, out, n4);
}

extern "C" void kernel_launch(void* const* d_in, const int* in_sizes, int n_in,
                              void* d_out, int out_size)
{
    (void)in_sizes; (void)n_in; (void)out_size;
    const float* hidden  = (const float*)d_in[0];
    const float* cosb    = (const float*)d_in[1];
    const float* sinb    = (const float*)d_in[2];
    const float* q_a_W   = (const float*)d_in[3];
    const float* q_a_nw  = (const float*)d_in[4];
    const float* q_b_W   = (const float*)d_in[5];
    const float* kv_a_W  = (const float*)d_in[6];
    const float* kv_a_nw = (const float*)d_in[7];
    const float* kv_b_W  = (const float*)d_in[8];
    const float* o_W     = (const float*)d_in[9];
    float* out = (float*)d_out;

    float *qa, *ckv, *kvn, *qbuf, *kvbuf, *attn;
    float *hid_r, *w_qa, *w_kva, *w_qb, *w_kvb, *w_o;
    cudaGetSymbolAddress((void**)&qa,    g_qa);
    cudaGetSymbolAddress((void**)&ckv,   g_ckv);
    cudaGetSymbolAddress((void**)&kvn,   g_kvn);
    cudaGetSymbolAddress((void**)&qbuf,  g_q);
    cudaGetSymbolAddress((void**)&kvbuf, g_kv);
    cudaGetSymbolAddress((void**)&attn,  g_attn);
    cudaGetSymbolAddress((void**)&hid_r, g_hid_r);
    cudaGetSymbolAddress((void**)&w_qa,  g_w_qa);
    cudaGetSymbolAddress((void**)&w_kva, g_w_kva);
    cudaGetSymbolAddress((void**)&w_qb,  g_w_qb);
    cudaGetSymbolAddress((void**)&w_kvb, g_w_kvb);
    cudaGetSymbolAddress((void**)&w_o,   g_w_o);

    cudaFuncSetAttribute(gemm_tf32, cudaFuncAttributeMaxDynamicSharedMemorySize, GEMM_SMEM);
    cudaFuncSetAttribute(flash_tf32_kernel, cudaFuncAttributeMaxDynamicSharedMemorySize, FLASH_SMEM);

    // one-time tf32 rna-rounding of GEMM inputs
    round_buf(hidden, hid_r, (size_t)NTOK * DMODEL);
    round_buf(q_a_W,  w_qa,  (size_t)DQA * DMODEL);
    round_buf(kv_a_W, w_kva, (size_t)DKVA * DMODEL);
    round_buf(q_b_W,  w_qb,  (size_t)QDIM * DQA);
    round_buf(kv_b_W, w_kvb, (size_t)KVDIM * DKVLAT);
    round_buf(o_W,    w_o,   (size_t)DMODEL * ODIM);

    // 1) q_a = hidden @ q_a_W^T
    gemm_tf32<<<dim3(DQA / TBN, NTOK / TBM), 256, GEMM_SMEM>>>(hid_r, w_qa, qa, NTOK, DQA, DMODEL);
    // 2) ckv = hidden @ kv_a_W^T  (N=576, edge tile guarded)
    gemm_tf32<<<dim3((DKVA + TBN - 1) / TBN, NTOK / TBM), 256, GEMM_SMEM>>>(hid_r, w_kva, ckv, NTOK, DKVA, DMODEL);
    // 3) rmsnorm q_a (in place, tf32-rounded out)
    rmsnorm_kernel<<<NTOK, 256>>>(qa, qa, q_a_nw, DQA, DQA, DQA);
    // 4) rmsnorm kv latent (tf32-rounded out)
    rmsnorm_kernel<<<NTOK, 256>>>(ckv, kvn, kv_a_nw, DKVLAT, DKVA, DKVLAT);
    // 5) q = qa_norm @ q_b_W^T
    gemm_tf32<<<dim3(QDIM / TBN, NTOK / TBM), 256, GEMM_SMEM>>>(qa, w_qb, qbuf, NTOK, QDIM, DQA);
    // 6) kv = kvn @ kv_b_W^T
    gemm_tf32<<<dim3(KVDIM / TBN, NTOK / TBM), 256, GEMM_SMEM>>>(kvn, w_kvb, kvbuf, NTOK, KVDIM, DKVLAT);
    // 7) RoPE in place
    rope_kernel<<<NTOK, 512>>>(qbuf, ckv, cosb, sinb);
    // 8) flash attention
    flash_tf32_kernel<<<dim3(SEQ / FM, HEADS, BATCH), 256, FLASH_SMEM>>>(qbuf, kvbuf, ckv, attn);
    // 9) out = attn @ o_W^T
    gemm_tf32<<<dim3(DMODEL / TBN, NTOK / TBM), 256, GEMM_SMEM>>>(attn, o_W, out, NTOK, DMODEL, ODIM);
}

// round 11
// speedup vs baseline: 5.6923x; 1.0064x over previous
#include <cuda_runtime.h>
#include <cuda_bf16.h>
#include <math.h>
#include <stdint.h>

// ---------------- problem constants ----------------
#define BATCH   2
#define SEQ     2048
#define NTOK    (BATCH * SEQ)        // 4096
#define DMODEL  2048
#define HEADS   16
#define DQK     192
#define DNOPE   128
#define DROPE   64
#define DV      128
#define DQA     1536
#define DKVA    576
#define DKVLAT  512
#define QDIM    (HEADS * DQK)        // 3072
#define KVDIM   (HEADS * (DNOPE + DV)) // 4096
#define ODIM    (HEADS * DV)         // 2048
#define ATT_SCALE 0.07216878364870322f

// ---------------- scratch ----------------
__device__ float g_qa  [(size_t)NTOK * DQA];
__device__ float g_ckv [(size_t)NTOK * DKVA];
__device__ float g_kvn [(size_t)NTOK * DKVLAT];
__device__ float g_q   [(size_t)NTOK * QDIM];
__device__ float g_kv  [(size_t)NTOK * KVDIM];
__device__ float g_attn[(size_t)NTOK * ODIM];
// tf32-rounded copies (GEMM inner loop consumes raw bits; round upstream)
__device__ float g_hid_r [(size_t)NTOK * DMODEL];
__device__ float g_w_qa  [(size_t)DQA * DMODEL];
__device__ float g_w_kva [(size_t)DKVA * DMODEL];
__device__ float g_w_qb  [(size_t)QDIM * DQA];
__device__ float g_w_kvb [(size_t)KVDIM * DKVLAT];
__device__ float g_w_o   [(size_t)DMODEL * ODIM];

// ---------------- helpers ----------------
__device__ __forceinline__ float to_tf32(float x) {
    float y;
    asm("cvt.rna.tf32.f32 %0, %1;" : "=f"(y) : "f"(x));
    return y;
}

__device__ __forceinline__ uint32_t smem_u32(const void* p) {
    uint32_t a;
    asm("{ .reg .u64 t; cvta.to.shared.u64 t, %1; cvt.u32.u64 %0, t; }" : "=r"(a) : "l"(p));
    return a;
}

__device__ __forceinline__ void mma_tf32(float c[4], const uint32_t a[4], const uint32_t b[2]) {
    asm volatile(
        "mma.sync.aligned.m16n8k8.row.col.f32.tf32.tf32.f32 "
        "{%0,%1,%2,%3}, {%4,%5,%6,%7}, {%8,%9}, {%0,%1,%2,%3};\n"
        : "+f"(c[0]), "+f"(c[1]), "+f"(c[2]), "+f"(c[3])
        : "r"(a[0]), "r"(a[1]), "r"(a[2]), "r"(a[3]), "r"(b[0]), "r"(b[1]));
}

__device__ __forceinline__ void ldsm_x4(uint32_t r[4], uint32_t addr) {
    asm volatile("ldmatrix.sync.aligned.m8n8.x4.shared.b16 {%0,%1,%2,%3}, [%4];"
        : "=r"(r[0]), "=r"(r[1]), "=r"(r[2]), "=r"(r[3]) : "r"(addr));
}

// ---------------- unified dynamic smem ----------------
extern __shared__ char dynsm[];

// ============================================================================
// TF32 GEMM (mma.sync + ldmatrix) with 3-stage cp.async pipeline
// C[M,N] = A[M,K] @ B[N,K]^T, tile 128x128, K-chunk 32
// Inputs MUST be pre-rounded to tf32 (rna).
// ============================================================================
#define TBM 128
#define TBN 128
#define TBK 32
#define ASTR 36                          // row stride 144B -> ldmatrix conflict-free
#define NSTG 3
#define STG_FLOATS (TBM * ASTR + TBN * ASTR)   // 9216 floats per stage
#define GEMM_SMEM (NSTG * STG_FLOATS * (int)sizeof(float))  // 110592 B

__global__ __launch_bounds__(256, 2) void gemm_tf32(
    const float* __restrict__ A, const float* __restrict__ Bw,
    float* __restrict__ C, int M, int N, int K)
{
    float* sm = (float*)dynsm;
    const int tid = threadIdx.x;
    const int wid = tid >> 5, lane = tid & 31;
    const int g = lane >> 2, tg = lane & 3;
    const int wm = (wid >> 2) * 64, wn = (wid & 3) * 32;
    const int bm = blockIdx.y * TBM, bn = blockIdx.x * TBN;
    const int NK = K / TBK;

    const int aRowOff = (wm + ((lane >> 3) & 1) * 8 + (lane & 7)) * ASTR + (lane >> 4) * 4;
    const int bRowOff = (wn + (lane >> 4) * 8 + (lane & 7)) * ASTR + ((lane >> 3) & 1) * 4;

#define LOAD_STAGE(c)                                                             \
    {                                                                             \
        const int s_ = (c) % NSTG;                                                \
        float* as_ = sm + s_ * STG_FLOATS;                                        \
        float* bs_ = as_ + TBM * ASTR;                                            \
        _Pragma("unroll")                                                         \
        for (int t_ = 0; t_ < 4; t_++) {                                          \
            int idx_ = tid + t_ * 256;                                            \
            int row_ = idx_ >> 3;                                                 \
            int c4_ = (idx_ & 7) * 4;                                             \
            uint32_t d_ = smem_u32(as_ + row_ * ASTR + c4_);                      \
            const float* s1_ = A + (size_t)(bm + row_) * K + (size_t)(c) * TBK + c4_; \
            asm volatile("cp.async.cg.shared.global.L2::256B [%0], [%1], 16;"     \
                         :: "r"(d_), "l"(s1_));                                   \
        }                                                                         \
        _Pragma("unroll")                                                         \
        for (int t_ = 0; t_ < 4; t_++) {                                          \
            int idx_ = tid + t_ * 256;                                            \
            int row_ = idx_ >> 3;                                                 \
            int c4_ = (idx_ & 7) * 4;                                             \
            int nr_ = bn + row_;                                                  \
            uint32_t d_ = smem_u32(bs_ + row_ * ASTR + c4_);                      \
            const float* s1_ = Bw + (size_t)(nr_ < N ? nr_ : 0) * K + (size_t)(c) * TBK + c4_; \
            unsigned sz_ = (nr_ < N) ? 16u : 0u;                                  \
            asm volatile("cp.async.cg.shared.global.L2::256B [%0], [%1], 16, %2;" \
                         :: "r"(d_), "l"(s1_), "r"(sz_));                         \
        }                                                                         \
        asm volatile("cp.async.commit_group;" ::: "memory");                      \
    }

    float acc[4][4][4];
#pragma unroll
    for (int mt = 0; mt < 4; mt++)
#pragma unroll
        for (int nt = 0; nt < 4; nt++)
#pragma unroll
            for (int i = 0; i < 4; i++) acc[mt][nt][i] = 0.f;

    LOAD_STAGE(0);
    LOAD_STAGE(1);

    for (int cc = 0; cc < NK; cc++) {
        asm volatile("cp.async.wait_group 1;" ::: "memory");
        __syncthreads();
        if (cc + 2 < NK) LOAD_STAGE(cc + 2);

        const int s = cc % NSTG;
        float* as_ = sm + s * STG_FLOATS;
        float* bs_ = as_ + TBM * ASTR;
        const uint32_t aBase = smem_u32(as_ + aRowOff);
        const uint32_t bBase = smem_u32(bs_ + bRowOff);

#pragma unroll
        for (int ks = 0; ks < 4; ks++) {
            const uint32_t kOff = ks * 32;
            uint32_t a[4][4], b[8];
#pragma unroll
            for (int mt = 0; mt < 4; mt++)
                ldsm_x4(a[mt], aBase + mt * (16 * ASTR * 4) + kOff);
            ldsm_x4(&b[0], bBase + kOff);
            ldsm_x4(&b[4], bBase + 16 * ASTR * 4 + kOff);
#pragma unroll
            for (int mt = 0; mt < 4; mt++)
#pragma unroll
                for (int nt = 0; nt < 4; nt++)
                    mma_tf32(acc[mt][nt], a[mt], &b[nt * 2]);
        }
    }

#pragma unroll
    for (int mt = 0; mt < 4; mt++) {
        int r0 = bm + wm + mt * 16 + g;
#pragma unroll
        for (int nt = 0; nt < 4; nt++) {
            int cc = bn + wn + nt * 8 + 2 * tg;
            if (cc < N) {
                *(float2*)(C + (size_t)r0 * N + cc)       = make_float2(acc[mt][nt][0], acc[mt][nt][1]);
                *(float2*)(C + (size_t)(r0 + 8) * N + cc) = make_float2(acc[mt][nt][2], acc[mt][nt][3]);
            }
        }
    }
}

// ---------------- fused tf32 pre-rounding pass (ALL buffers, one launch) ---
__device__ __forceinline__ void round4(const float* in, float* out, int i) {
    float4 v = ((const float4*)in)[i];
    v.x = to_tf32(v.x); v.y = to_tf32(v.y);
    v.z = to_tf32(v.z); v.w = to_tf32(v.w);
    ((float4*)out)[i] = v;
}

__global__ __launch_bounds__(256) void round_all_kernel(
    const float* s0, float* d0, int n0,
    const float* s1, float* d1, int n1,
    const float* s2, float* d2, int n2,
    const float* s3, float* d3, int n3,
    const float* s4, float* d4, int n4,
    const float* s5, float* d5, int n5)
{
    int i = blockIdx.x * 256 + threadIdx.x;
    if (i < n0) { round4(s0, d0, i); return; }  i -= n0;
    if (i < n1) { round4(s1, d1, i); return; }  i -= n1;
    if (i < n2) { round4(s2, d2, i); return; }  i -= n2;
    if (i < n3) { round4(s3, d3, i); return; }  i -= n3;
    if (i < n4) { round4(s4, d4, i); return; }  i -= n4;
    if (i < n5) { round4(s5, d5, i); }
}

// ---------------- RMSNorm (tf32-rounded output: feeds GEMM) ----------------
__global__ __launch_bounds__(256) void rmsnorm_kernel(
    const float* __restrict__ in, float* __restrict__ out,
    const float* __restrict__ w, int N, int in_stride, int out_stride)
{
    const int row = blockIdx.x;
    const float* x = in + (size_t)row * in_stride;
    const int cnt = N >> 8;
    float v[6];
    float ss = 0.f;
    for (int i = 0; i < cnt; i++) {
        v[i] = x[threadIdx.x + (i << 8)];
        ss += v[i] * v[i];
    }
#pragma unroll
    for (int o = 16; o > 0; o >>= 1) ss += __shfl_xor_sync(0xffffffffu, ss, o);
    __shared__ float red[8];
    if ((threadIdx.x & 31) == 0) red[threadIdx.x >> 5] = ss;
    __syncthreads();
    float tot = 0.f;
#pragma unroll
    for (int i = 0; i < 8; i++) tot += red[i];
    const float r = rsqrtf(tot / (float)N + 1e-6f);
    float* y = out + (size_t)row * out_stride;
    for (int i = 0; i < cnt; i++) {
        int c = threadIdx.x + (i << 8);
        y[c] = to_tf32(w[c] * v[i] * r);
    }
}

// ---------------- RoPE ----------------
__global__ __launch_bounds__(512) void rope_kernel(
    float* __restrict__ q, float* __restrict__ ckv,
    const float* __restrict__ cosb, const float* __restrict__ sinb)
{
    const int tok = blockIdx.x;
    const int t = threadIdx.x;
    const int h = t >> 5;
    const int d = t & 31;
    const float c0 = cosb[(size_t)tok * DROPE + d];
    const float s0 = sinb[(size_t)tok * DROPE + d];
    const float c1 = cosb[(size_t)tok * DROPE + d + 32];
    const float s1 = sinb[(size_t)tok * DROPE + d + 32];
    {
        float* qr = q + (size_t)tok * QDIM + h * DQK + DNOPE;
        float a = qr[d], b = qr[d + 32];
        qr[d]      = a * c0 - b * s0;
        qr[d + 32] = b * c1 + a * s1;
    }
    if (t < 32) {
        float* kr = ckv + (size_t)tok * DKVA + DKVLAT;
        float a = kr[d], b = kr[d + 32];
        kr[d]      = a * c0 - b * s0;
        kr[d + 32] = b * c1 + a * s1;
    }
}

// ---------------- Flash attention (tf32 mma.sync + ldmatrix, causal) ------
#define FM 128
#define FN 64
#define SQ_STR 196   // %32 == 4
#define SK_STR 196   // %32 == 4
#define VT_STR 68    // transposed V: [DV][FN], %32 == 4
#define SP_STR 68    // %32 == 4
#define FLASH_SMEM ((FM * SQ_STR + FN * SK_STR + DV * VT_STR + FM * SP_STR) * (int)sizeof(float))

__global__ __launch_bounds__(256) void flash_tf32_kernel(
    const float* __restrict__ q, const float* __restrict__ kvbuf,
    const float* __restrict__ ckv, float* __restrict__ attn_out)
{
    float* fsmem = (float*)dynsm;
    float* sQ  = fsmem;                   // 128 x 196
    float* sK  = sQ + FM * SQ_STR;        // 64 x 196
    float* sVt = sK + FN * SK_STR;        // 128 x 68 (transposed: [dv][k])
    float* sP  = sVt + DV * VT_STR;       // 128 x 68

    const int bq = gridDim.x - 1 - blockIdx.x;
    const int h  = blockIdx.y;
    const int b  = blockIdx.z;
    const int q0 = bq * FM;
    const int tid = threadIdx.x;
    const int wid = tid >> 5, lane = tid & 31;
    const int g = lane >> 2, tg = lane & 3;
    const int wrow = wid * 16;

    const int aSel = ((lane >> 3) & 1) * 8 + (lane & 7);
    const int aCol = (lane >> 4) * 4;
    const int bSel = (lane >> 4) * 8 + (lane & 7);
    const int bCol = ((lane >> 3) & 1) * 4;

    const uint32_t qBase = smem_u32(sQ  + (wrow + aSel) * SQ_STR + aCol);
    const uint32_t kBase = smem_u32(sK  + bSel * SK_STR + bCol);
    const uint32_t pBase = smem_u32(sP  + (wrow + aSel) * SP_STR + aCol);
    const uint32_t vBase = smem_u32(sVt + bSel * VT_STR + bCol);

    const size_t qbase = ((size_t)(b * SEQ + q0)) * QDIM + (size_t)h * DQK;
    for (int e = tid; e < FM * (DQK / 4); e += 256) {
        int r = e / (DQK / 4), c4 = (e - r * (DQK / 4)) * 4;
        float4 v = *(const float4*)(q + qbase + (size_t)r * QDIM + c4);
        sQ[r * SQ_STR + c4 + 0] = to_tf32(v.x * ATT_SCALE);
        sQ[r * SQ_STR + c4 + 1] = to_tf32(v.y * ATT_SCALE);
        sQ[r * SQ_STR + c4 + 2] = to_tf32(v.z * ATT_SCALE);
        sQ[r * SQ_STR + c4 + 3] = to_tf32(v.w * ATT_SCALE);
    }

    float o[16][4];
#pragma unroll
    for (int nt = 0; nt < 16; nt++)
#pragma unroll
        for (int i = 0; i < 4; i++) o[nt][i] = 0.f;
    float m0 = -1e30f, m1 = -1e30f, l0 = 0.f, l1 = 0.f;

    const int nkt = (q0 + FM) / FN;
    for (int kt = 0; kt < nkt; kt++) {
        __syncthreads();
        const size_t kvb = ((size_t)(b * SEQ + kt * FN)) * KVDIM + (size_t)h * (DNOPE + DV);
        const size_t ckb = ((size_t)(b * SEQ + kt * FN)) * DKVA + DKVLAT;
        for (int e = tid; e < FN * (DQK / 4); e += 256) {
            int r = e / (DQK / 4), c4 = (e - r * (DQK / 4)) * 4;
            float4 v;
            if (c4 < DNOPE) v = *(const float4*)(kvbuf + kvb + (size_t)r * KVDIM + c4);
            else            v = *(const float4*)(ckv + ckb + (size_t)r * DKVA + (c4 - DNOPE));
            sK[r * SK_STR + c4 + 0] = to_tf32(v.x);
            sK[r * SK_STR + c4 + 1] = to_tf32(v.y);
            sK[r * SK_STR + c4 + 2] = to_tf32(v.z);
            sK[r * SK_STR + c4 + 3] = to_tf32(v.w);
        }
        for (int e = tid; e < DV * (FN / 4); e += 256) {
            int c  = e & 127;
            int rg = e >> 7;
            const float* src = kvbuf + kvb + (size_t)(rg * 4) * KVDIM + DNOPE + c;
            float4 w;
            w.x = to_tf32(src[0]);
            w.y = to_tf32(src[KVDIM]);
            w.z = to_tf32(src[2 * KVDIM]);
            w.w = to_tf32(src[3 * KVDIM]);
            *(float4*)(sVt + c * VT_STR + rg * 4) = w;
        }
        __syncthreads();

        float s[8][4];
#pragma unroll
        for (int nt = 0; nt < 8; nt++)
#pragma unroll
            for (int i = 0; i < 4; i++) s[nt][i] = 0.f;

#pragma unroll 4
        for (int ks = 0; ks < DQK / 8; ks++) {
            const uint32_t kOff = ks * 32;
            uint32_t a[4];
            ldsm_x4(a, qBase + kOff);
#pragma unroll
            for (int nt2 = 0; nt2 < 4; nt2++) {
                uint32_t b4[4];
                ldsm_x4(b4, kBase + nt2 * (16 * SK_STR * 4) + kOff);
                mma_tf32(s[nt2 * 2],     a, &b4[0]);
                mma_tf32(s[nt2 * 2 + 1], a, &b4[2]);
            }
        }

        if (kt * FN + FN - 1 > q0) {
            const int gr0 = q0 + wrow + g;
            const int gr1 = gr0 + 8;
#pragma unroll
            for (int nt = 0; nt < 8; nt++) {
                int gc = kt * FN + nt * 8 + 2 * tg;
                if (gc     > gr0) s[nt][0] = -1e30f;
                if (gc + 1 > gr0) s[nt][1] = -1e30f;
                if (gc     > gr1) s[nt][2] = -1e30f;
                if (gc + 1 > gr1) s[nt][3] = -1e30f;
            }
        }

        float mx0 = -1e30f, mx1 = -1e30f;
#pragma unroll
        for (int nt = 0; nt < 8; nt++) {
            mx0 = fmaxf(mx0, fmaxf(s[nt][0], s[nt][1]));
            mx1 = fmaxf(mx1, fmaxf(s[nt][2], s[nt][3]));
        }
#pragma unroll
        for (int o_ = 1; o_ < 4; o_ <<= 1) {
            mx0 = fmaxf(mx0, __shfl_xor_sync(0xffffffffu, mx0, o_));
            mx1 = fmaxf(mx1, __shfl_xor_sync(0xffffffffu, mx1, o_));
        }
        const float mn0 = fmaxf(m0, mx0);
        const float mn1 = fmaxf(m1, mx1);
        const float sc0 = __expf(m0 - mn0);
        const float sc1 = __expf(m1 - mn1);
        float rs0 = 0.f, rs1 = 0.f;
#pragma unroll
        for (int nt = 0; nt < 8; nt++) {
            s[nt][0] = __expf(s[nt][0] - mn0);
            s[nt][1] = __expf(s[nt][1] - mn0);
            s[nt][2] = __expf(s[nt][2] - mn1);
            s[nt][3] = __expf(s[nt][3] - mn1);
            rs0 += s[nt][0] + s[nt][1];
            rs1 += s[nt][2] + s[nt][3];
        }
#pragma unroll
        for (int o_ = 1; o_ < 4; o_ <<= 1) {
            rs0 += __shfl_xor_sync(0xffffffffu, rs0, o_);
            rs1 += __shfl_xor_sync(0xffffffffu, rs1, o_);
        }
        l0 = l0 * sc0 + rs0;  m0 = mn0;
        l1 = l1 * sc1 + rs1;  m1 = mn1;
#pragma unroll
        for (int nt = 0; nt < 16; nt++) {
            o[nt][0] *= sc0; o[nt][1] *= sc0;
            o[nt][2] *= sc1; o[nt][3] *= sc1;
        }
#pragma unroll
        for (int nt = 0; nt < 8; nt++) {
            int col = nt * 8 + 2 * tg;
            sP[(wrow + g    ) * SP_STR + col]     = to_tf32(s[nt][0]);
            sP[(wrow + g    ) * SP_STR + col + 1] = to_tf32(s[nt][1]);
            sP[(wrow + g + 8) * SP_STR + col]     = to_tf32(s[nt][2]);
            sP[(wrow + g + 8) * SP_STR + col + 1] = to_tf32(s[nt][3]);
        }
        __syncwarp();

#pragma unroll 2
        for (int ks = 0; ks < FN / 8; ks++) {
            const uint32_t kOff = ks * 32;
            uint32_t a[4];
            ldsm_x4(a, pBase + kOff);
#pragma unroll
            for (int nt2 = 0; nt2 < 8; nt2++) {
                uint32_t b4[4];
                ldsm_x4(b4, vBase + nt2 * (16 * VT_STR * 4) + kOff);
                mma_tf32(o[nt2 * 2],     a, &b4[0]);
                mma_tf32(o[nt2 * 2 + 1], a, &b4[2]);
            }
        }
    }

    const float inv0 = 1.f / l0, inv1 = 1.f / l1;
    const size_t obase = ((size_t)(b * SEQ + q0)) * ODIM + (size_t)h * DV;
    const size_t r0 = obase + (size_t)(wrow + g) * ODIM;
    const size_t r1 = obase + (size_t)(wrow + g + 8) * ODIM;
#pragma unroll
    for (int nt = 0; nt < 16; nt++) {
        int col = nt * 8 + 2 * tg;
        *(float2*)(attn_out + r0 + col) = make_float2(to_tf32(o[nt][0] * inv0), to_tf32(o[nt][1] * inv0));
        *(float2*)(attn_out + r1 + col) = make_float2(to_tf32(o[nt][2] * inv1), to_tf32(o[nt][3] * inv1));
    }
}

// ---------------- launch ----------------
extern "C" void kernel_launch(void* const* d_in, const int* in_sizes, int n_in,
                              void* d_out, int out_size)
{
    (void)in_sizes; (void)n_in; (void)out_size;
    const float* hidden  = (const float*)d_in[0];
    const float* cosb    = (const float*)d_in[1];
    const float* sinb    = (const float*)d_in[2];
    const float* q_a_W   = (const float*)d_in[3];
    const float* q_a_nw  = (const float*)d_in[4];
    const float* q_b_W   = (const float*)d_in[5];
    const float* kv_a_W  = (const float*)d_in[6];
    const float* kv_a_nw = (const float*)d_in[7];
    const float* kv_b_W  = (const float*)d_in[8];
    const float* o_W     = (const float*)d_in[9];
    float* out = (float*)d_out;

    float *qa, *ckv, *kvn, *qbuf, *kvbuf, *attn;
    float *hid_r, *w_qa, *w_kva, *w_qb, *w_kvb, *w_o;
    cudaGetSymbolAddress((void**)&qa,    g_qa);
    cudaGetSymbolAddress((void**)&ckv,   g_ckv);
    cudaGetSymbolAddress((void**)&kvn,   g_kvn);
    cudaGetSymbolAddress((void**)&qbuf,  g_q);
    cudaGetSymbolAddress((void**)&kvbuf, g_kv);
    cudaGetSymbolAddress((void**)&attn,  g_attn);
    cudaGetSymbolAddress((void**)&hid_r, g_hid_r);
    cudaGetSymbolAddress((void**)&w_qa,  g_w_qa);
    cudaGetSymbolAddress((void**)&w_kva, g_w_kva);
    cudaGetSymbolAddress((void**)&w_qb,  g_w_qb);
    cudaGetSymbolAddress((void**)&w_kvb, g_w_kvb);
    cudaGetSymbolAddress((void**)&w_o,   g_w_o);

    cudaFuncSetAttribute(gemm_tf32, cudaFuncAttributeMaxDynamicSharedMemorySize, GEMM_SMEM);
    cudaFuncSetAttribute(flash_tf32_kernel, cudaFuncAttributeMaxDynamicSharedMemorySize, FLASH_SMEM);

    // launch 0: ONE fused tf32 rna-rounding pass over all GEMM inputs
    {
        const int n0 = (int)((size_t)NTOK * DMODEL / 4);
        const int n1 = (int)((size_t)DQA * DMODEL / 4);
        const int n2 = (int)((size_t)DKVA * DMODEL / 4);
        const int n3 = (int)((size_t)QDIM * DQA / 4);
        const int n4 = (int)((size_t)KVDIM * DKVLAT / 4);
        const int n5 = (int)((size_t)DMODEL * ODIM / 4);
        const int total = n0 + n1 + n2 + n3 + n4 + n5;
        round_all_kernel<<<(total + 255) / 256, 256>>>(
            hidden, hid_r, n0,  q_a_W, w_qa, n1,  kv_a_W, w_kva, n2,
            q_b_W,  w_qb, n3,   kv_b_W, w_kvb, n4, o_W,    w_o,  n5);
    }

    // launch 1: q_a = hidden @ q_a_W^T
    gemm_tf32<<<dim3(DQA / TBN, NTOK / TBM), 256, GEMM_SMEM>>>(hid_r, w_qa, qa, NTOK, DQA, DMODEL);
    // launch 2: ckv = hidden @ kv_a_W^T
    gemm_tf32<<<dim3((DKVA + TBN - 1) / TBN, NTOK / TBM), 256, GEMM_SMEM>>>(hid_r, w_kva, ckv, NTOK, DKVA, DMODEL);
    // launch 3: rmsnorm q_a (in place, tf32-rounded out)
    rmsnorm_kernel<<<NTOK, 256>>>(qa, qa, q_a_nw, DQA, DQA, DQA);
    // launch 4: rmsnorm kv latent (tf32-rounded out)
    rmsnorm_kernel<<<NTOK, 256>>>(ckv, kvn, kv_a_nw, DKVLAT, DKVA, DKVLAT);
    // launch 5 (PROFILED by ncu -s 5 -c 1): q = qa_norm @ q_b_W^T
    gemm_tf32<<<dim3(QDIM / TBN, NTOK / TBM), 256, GEMM_SMEM>>>(qa, w_qb, qbuf, NTOK, QDIM, DQA);
    // launch 6: kv = kvn @ kv_b_W^T
    gemm_tf32<<<dim3(KVDIM / TBN, NTOK / TBM), 256, GEMM_SMEM>>>(kvn, w_kvb, kvbuf, NTOK, KVDIM, DKVLAT);
    // launch 7: RoPE in place
    rope_kernel<<<NTOK, 512>>>(qbuf, ckv, cosb, sinb);
    // launch 8: flash attention
    flash_tf32_kernel<<<dim3(SEQ / FM, HEADS, BATCH), 256, FLASH_SMEM>>>(qbuf, kvbuf, ckv, attn);
    // launch 9: out = attn @ o_W^T
    gemm_tf32<<<dim3(DMODEL / TBN, NTOK / TBM), 256, GEMM_SMEM>>>(attn, w_o, out, NTOK, DMODEL, ODIM);
}

// round 13
// speedup vs baseline: 6.1304x; 1.0770x over previous
#include <cuda_runtime.h>
#include <cuda_bf16.h>
#include <math.h>
#include <stdint.h>

// ---------------- problem constants ----------------
#define BATCH   2
#define SEQ     2048
#define NTOK    (BATCH * SEQ)        // 4096
#define DMODEL  2048
#define HEADS   16
#define DQK     192
#define DNOPE   128
#define DROPE   64
#define DV      128
#define DQA     1536
#define DKVA    576
#define DKVLAT  512
#define QDIM    (HEADS * DQK)        // 3072
#define KVDIM   (HEADS * (DNOPE + DV)) // 4096
#define ODIM    (HEADS * DV)         // 2048
#define ATT_SCALE 0.07216878364870322f

// ---------------- scratch ----------------
__device__ float g_qa  [(size_t)NTOK * DQA];
__device__ float g_ckv [(size_t)NTOK * DKVA];
__device__ float g_kvn [(size_t)NTOK * DKVLAT];
__device__ float g_q   [(size_t)NTOK * QDIM];
__device__ float g_kv  [(size_t)NTOK * KVDIM];
__device__ float g_attn[(size_t)NTOK * ODIM];
// tf32-rounded copies (GEMM inner loop consumes raw bits; round upstream)
__device__ float g_hid_r [(size_t)NTOK * DMODEL];
__device__ float g_w_qa  [(size_t)DQA * DMODEL];
__device__ float g_w_kva [(size_t)DKVA * DMODEL];
__device__ float g_w_qb  [(size_t)QDIM * DQA];
__device__ float g_w_kvb [(size_t)KVDIM * DKVLAT];
__device__ float g_w_o   [(size_t)DMODEL * ODIM];

// ---------------- helpers ----------------
__device__ __forceinline__ float to_tf32(float x) {
    float y;
    asm("cvt.rna.tf32.f32 %0, %1;" : "=f"(y) : "f"(x));
    return y;
}

__device__ __forceinline__ uint32_t smem_u32(const void* p) {
    uint32_t a;
    asm("{ .reg .u64 t; cvta.to.shared.u64 t, %1; cvt.u32.u64 %0, t; }" : "=r"(a) : "l"(p));
    return a;
}

__device__ __forceinline__ void mma_tf32(float c[4], const uint32_t a[4], const uint32_t b[2]) {
    asm volatile(
        "mma.sync.aligned.m16n8k8.row.col.f32.tf32.tf32.f32 "
        "{%0,%1,%2,%3}, {%4,%5,%6,%7}, {%8,%9}, {%0,%1,%2,%3};\n"
        : "+f"(c[0]), "+f"(c[1]), "+f"(c[2]), "+f"(c[3])
        : "r"(a[0]), "r"(a[1]), "r"(a[2]), "r"(a[3]), "r"(b[0]), "r"(b[1]));
}

__device__ __forceinline__ void ldsm_x4(uint32_t r[4], uint32_t addr) {
    asm volatile("ldmatrix.sync.aligned.m8n8.x4.shared.b16 {%0,%1,%2,%3}, [%4];"
        : "=r"(r[0]), "=r"(r[1]), "=r"(r[2]), "=r"(r[3]) : "r"(addr));
}

// ---------------- unified dynamic smem ----------------
extern __shared__ char dynsm[];

// ============================================================================
// TF32 GEMM tile body (mma.sync + ldmatrix, 3-stage cp.async pipeline)
// Computes C[bm:bm+128, bn:bn+128] = A[bm:,:K] @ B[bn:,:K]^T
// Inputs MUST be pre-rounded to tf32 (rna).
// ============================================================================
#define TBM 128
#define TBN 128
#define TBK 32
#define ASTR 36                          // row stride 144B -> ldmatrix conflict-free
#define NSTG 3
#define STG_FLOATS (TBM * ASTR + TBN * ASTR)   // 9216 floats per stage
#define GEMM_SMEM (NSTG * STG_FLOATS * (int)sizeof(float))  // 110592 B

__device__ __forceinline__ void gemm_tile_body(
    const float* __restrict__ A, const float* __restrict__ Bw,
    float* __restrict__ C, int N, int K, int bm, int bn)
{
    float* sm = (float*)dynsm;
    const int tid = threadIdx.x;
    const int wid = tid >> 5, lane = tid & 31;
    const int g = lane >> 2, tg = lane & 3;
    const int wm = (wid >> 2) * 64, wn = (wid & 3) * 32;
    const int NK = K / TBK;

    const int aRowOff = (wm + ((lane >> 3) & 1) * 8 + (lane & 7)) * ASTR + (lane >> 4) * 4;
    const int bRowOff = (wn + (lane >> 4) * 8 + (lane & 7)) * ASTR + ((lane >> 3) & 1) * 4;

#define LOAD_STAGE(c)                                                             \
    {                                                                             \
        const int s_ = (c) % NSTG;                                                \
        float* as_ = sm + s_ * STG_FLOATS;                                        \
        float* bs_ = as_ + TBM * ASTR;                                            \
        _Pragma("unroll")                                                         \
        for (int t_ = 0; t_ < 4; t_++) {                                          \
            int idx_ = tid + t_ * 256;                                            \
            int row_ = idx_ >> 3;                                                 \
            int c4_ = (idx_ & 7) * 4;                                             \
            uint32_t d_ = smem_u32(as_ + row_ * ASTR + c4_);                      \
            const float* s1_ = A + (size_t)(bm + row_) * K + (size_t)(c) * TBK + c4_; \
            asm volatile("cp.async.cg.shared.global.L2::256B [%0], [%1], 16;"     \
                         :: "r"(d_), "l"(s1_));                                   \
        }                                                                         \
        _Pragma("unroll")                                                         \
        for (int t_ = 0; t_ < 4; t_++) {                                          \
            int idx_ = tid + t_ * 256;                                            \
            int row_ = idx_ >> 3;                                                 \
            int c4_ = (idx_ & 7) * 4;                                             \
            int nr_ = bn + row_;                                                  \
            uint32_t d_ = smem_u32(bs_ + row_ * ASTR + c4_);                      \
            const float* s1_ = Bw + (size_t)(nr_ < N ? nr_ : 0) * K + (size_t)(c) * TBK + c4_; \
            unsigned sz_ = (nr_ < N) ? 16u : 0u;                                  \
            asm volatile("cp.async.cg.shared.global.L2::256B [%0], [%1], 16, %2;" \
                         :: "r"(d_), "l"(s1_), "r"(sz_));                         \
        }                                                                         \
        asm volatile("cp.async.commit_group;" ::: "memory");                      \
    }

    float acc[4][4][4];
#pragma unroll
    for (int mt = 0; mt < 4; mt++)
#pragma unroll
        for (int nt = 0; nt < 4; nt++)
#pragma unroll
            for (int i = 0; i < 4; i++) acc[mt][nt][i] = 0.f;

    LOAD_STAGE(0);
    LOAD_STAGE(1);

    for (int cc = 0; cc < NK; cc++) {
        asm volatile("cp.async.wait_group 1;" ::: "memory");
        __syncthreads();
        if (cc + 2 < NK) LOAD_STAGE(cc + 2);

        const int s = cc % NSTG;
        float* as_ = sm + s * STG_FLOATS;
        float* bs_ = as_ + TBM * ASTR;
        const uint32_t aBase = smem_u32(as_ + aRowOff);
        const uint32_t bBase = smem_u32(bs_ + bRowOff);

#pragma unroll
        for (int ks = 0; ks < 4; ks++) {
            const uint32_t kOff = ks * 32;
            uint32_t a[4][4], b[8];
#pragma unroll
            for (int mt = 0; mt < 4; mt++)
                ldsm_x4(a[mt], aBase + mt * (16 * ASTR * 4) + kOff);
            ldsm_x4(&b[0], bBase + kOff);
            ldsm_x4(&b[4], bBase + 16 * ASTR * 4 + kOff);
#pragma unroll
            for (int mt = 0; mt < 4; mt++)
#pragma unroll
                for (int nt = 0; nt < 4; nt++)
                    mma_tf32(acc[mt][nt], a[mt], &b[nt * 2]);
        }
    }

#pragma unroll
    for (int mt = 0; mt < 4; mt++) {
        int r0 = bm + wm + mt * 16 + g;
#pragma unroll
        for (int nt = 0; nt < 4; nt++) {
            int cc = bn + wn + nt * 8 + 2 * tg;
            if (cc < N) {
                *(float2*)(C + (size_t)r0 * N + cc)       = make_float2(acc[mt][nt][0], acc[mt][nt][1]);
                *(float2*)(C + (size_t)(r0 + 8) * N + cc) = make_float2(acc[mt][nt][2], acc[mt][nt][3]);
            }
        }
    }
#undef LOAD_STAGE
}

// single GEMM launch
__global__ __launch_bounds__(256, 2) void gemm_tf32(
    const float* __restrict__ A, const float* __restrict__ Bw,
    float* __restrict__ C, int M, int N, int K)
{
    (void)M;
    gemm_tile_body(A, Bw, C, N, K, blockIdx.y * TBM, blockIdx.x * TBN);
}

// fused dual GEMM: tiles of GEMM1 first (schedule long-K tiles early),
// then GEMM2 tiles. Flattened 1-D grid; blockIdx selects the GEMM + tile.
__global__ __launch_bounds__(256, 2) void gemm_dual(
    const float* __restrict__ A1, const float* __restrict__ B1, float* __restrict__ C1,
    int N1, int K1, int ntiles1, int gx1,
    const float* __restrict__ A2, const float* __restrict__ B2, float* __restrict__ C2,
    int N2, int K2, int gx2)
{
    int t = blockIdx.x;
    const float *A, *Bw;
    float* C;
    int N, K, bm, bn;
    if (t < ntiles1) {
        A = A1; Bw = B1; C = C1; N = N1; K = K1;
        bn = (t % gx1) * TBN; bm = (t / gx1) * TBM;
    } else {
        t -= ntiles1;
        A = A2; Bw = B2; C = C2; N = N2; K = K2;
        bn = (t % gx2) * TBN; bm = (t / gx2) * TBM;
    }
    gemm_tile_body(A, Bw, C, N, K, bm, bn);
}

// ---------------- fused tf32 pre-rounding pass (ALL buffers, one launch) ---
__device__ __forceinline__ void round4(const float* in, float* out, int i) {
    float4 v = ((const float4*)in)[i];
    v.x = to_tf32(v.x); v.y = to_tf32(v.y);
    v.z = to_tf32(v.z); v.w = to_tf32(v.w);
    ((float4*)out)[i] = v;
}

__global__ __launch_bounds__(256) void round_all_kernel(
    const float* s0, float* d0, int n0,
    const float* s1, float* d1, int n1,
    const float* s2, float* d2, int n2,
    const float* s3, float* d3, int n3,
    const float* s4, float* d4, int n4,
    const float* s5, float* d5, int n5)
{
    int i = blockIdx.x * 256 + threadIdx.x;
    if (i < n0) { round4(s0, d0, i); return; }  i -= n0;
    if (i < n1) { round4(s1, d1, i); return; }  i -= n1;
    if (i < n2) { round4(s2, d2, i); return; }  i -= n2;
    if (i < n3) { round4(s3, d3, i); return; }  i -= n3;
    if (i < n4) { round4(s4, d4, i); return; }  i -= n4;
    if (i < n5) { round4(s5, d5, i); }
}

// ---------------- fused dual RMSNorm (tf32-rounded output) -----------------
__global__ __launch_bounds__(256) void rmsnorm_dual_kernel(
    const float* __restrict__ in1, float* __restrict__ out1,
    const float* __restrict__ w1, int N1, int is1, int os1, int rows1,
    const float* __restrict__ in2, float* __restrict__ out2,
    const float* __restrict__ w2, int N2, int is2, int os2)
{
    const float* in;  float* out;  const float* w;
    int N, in_stride, out_stride, row = blockIdx.x;
    if (row < rows1) { in = in1; out = out1; w = w1; N = N1; in_stride = is1; out_stride = os1; }
    else { row -= rows1; in = in2; out = out2; w = w2; N = N2; in_stride = is2; out_stride = os2; }

    const float* x = in + (size_t)row * in_stride;
    const int cnt = N >> 8;
    float v[6];
    float ss = 0.f;
    for (int i = 0; i < cnt; i++) {
        v[i] = x[threadIdx.x + (i << 8)];
        ss += v[i] * v[i];
    }
#pragma unroll
    for (int o = 16; o > 0; o >>= 1) ss += __shfl_xor_sync(0xffffffffu, ss, o);
    __shared__ float red[8];
    if ((threadIdx.x & 31) == 0) red[threadIdx.x >> 5] = ss;
    __syncthreads();
    float tot = 0.f;
#pragma unroll
    for (int i = 0; i < 8; i++) tot += red[i];
    const float r = rsqrtf(tot / (float)N + 1e-6f);
    float* y = out + (size_t)row * out_stride;
    for (int i = 0; i < cnt; i++) {
        int c = threadIdx.x + (i << 8);
        y[c] = to_tf32(w[c] * v[i] * r);
    }
}

// ---------------- RoPE ----------------
__global__ __launch_bounds__(512) void rope_kernel(
    float* __restrict__ q, float* __restrict__ ckv,
    const float* __restrict__ cosb, const float* __restrict__ sinb)
{
    const int tok = blockIdx.x;
    const int t = threadIdx.x;
    const int h = t >> 5;
    const int d = t & 31;
    const float c0 = cosb[(size_t)tok * DROPE + d];
    const float s0 = sinb[(size_t)tok * DROPE + d];
    const float c1 = cosb[(size_t)tok * DROPE + d + 32];
    const float s1 = sinb[(size_t)tok * DROPE + d + 32];
    {
        float* qr = q + (size_t)tok * QDIM + h * DQK + DNOPE;
        float a = qr[d], b = qr[d + 32];
        qr[d]      = a * c0 - b * s0;
        qr[d + 32] = b * c1 + a * s1;
    }
    if (t < 32) {
        float* kr = ckv + (size_t)tok * DKVA + DKVLAT;
        float a = kr[d], b = kr[d + 32];
        kr[d]      = a * c0 - b * s0;
        kr[d + 32] = b * c1 + a * s1;
    }
}

// ---------------- Flash attention (tf32 mma.sync + ldmatrix, causal) ------
#define FM 128
#define FN 64
#define SQ_STR 196   // %32 == 4
#define SK_STR 196   // %32 == 4
#define VT_STR 68    // transposed V: [DV][FN], %32 == 4
#define SP_STR 68    // %32 == 4
#define FLASH_SMEM ((FM * SQ_STR + FN * SK_STR + DV * VT_STR + FM * SP_STR) * (int)sizeof(float))

__global__ __launch_bounds__(256) void flash_tf32_kernel(
    const float* __restrict__ q, const float* __restrict__ kvbuf,
    const float* __restrict__ ckv, float* __restrict__ attn_out)
{
    float* fsmem = (float*)dynsm;
    float* sQ  = fsmem;                   // 128 x 196
    float* sK  = sQ + FM * SQ_STR;        // 64 x 196
    float* sVt = sK + FN * SK_STR;        // 128 x 68 (transposed: [dv][k])
    float* sP  = sVt + DV * VT_STR;       // 128 x 68

    const int bq = gridDim.x - 1 - blockIdx.x;
    const int h  = blockIdx.y;
    const int b  = blockIdx.z;
    const int q0 = bq * FM;
    const int tid = threadIdx.x;
    const int wid = tid >> 5, lane = tid & 31;
    const int g = lane >> 2, tg = lane & 3;
    const int wrow = wid * 16;

    const int aSel = ((lane >> 3) & 1) * 8 + (lane & 7);
    const int aCol = (lane >> 4) * 4;
    const int bSel = (lane >> 4) * 8 + (lane & 7);
    const int bCol = ((lane >> 3) & 1) * 4;

    const uint32_t qBase = smem_u32(sQ  + (wrow + aSel) * SQ_STR + aCol);
    const uint32_t kBase = smem_u32(sK  + bSel * SK_STR + bCol);
    const uint32_t pBase = smem_u32(sP  + (wrow + aSel) * SP_STR + aCol);
    const uint32_t vBase = smem_u32(sVt + bSel * VT_STR + bCol);

    const size_t qbase = ((size_t)(b * SEQ + q0)) * QDIM + (size_t)h * DQK;
    for (int e = tid; e < FM * (DQK / 4); e += 256) {
        int r = e / (DQK / 4), c4 = (e - r * (DQK / 4)) * 4;
        float4 v = *(const float4*)(q + qbase + (size_t)r * QDIM + c4);
        sQ[r * SQ_STR + c4 + 0] = to_tf32(v.x * ATT_SCALE);
        sQ[r * SQ_STR + c4 + 1] = to_tf32(v.y * ATT_SCALE);
        sQ[r * SQ_STR + c4 + 2] = to_tf32(v.z * ATT_SCALE);
        sQ[r * SQ_STR + c4 + 3] = to_tf32(v.w * ATT_SCALE);
    }

    float o[16][4];
#pragma unroll
    for (int nt = 0; nt < 16; nt++)
#pragma unroll
        for (int i = 0; i < 4; i++) o[nt][i] = 0.f;
    float m0 = -1e30f, m1 = -1e30f, l0 = 0.f, l1 = 0.f;

    const int nkt = (q0 + FM) / FN;
    for (int kt = 0; kt < nkt; kt++) {
        __syncthreads();
        const size_t kvb = ((size_t)(b * SEQ + kt * FN)) * KVDIM + (size_t)h * (DNOPE + DV);
        const size_t ckb = ((size_t)(b * SEQ + kt * FN)) * DKVA + DKVLAT;
        for (int e = tid; e < FN * (DQK / 4); e += 256) {
            int r = e / (DQK / 4), c4 = (e - r * (DQK / 4)) * 4;
            float4 v;
            if (c4 < DNOPE) v = *(const float4*)(kvbuf + kvb + (size_t)r * KVDIM + c4);
            else            v = *(const float4*)(ckv + ckb + (size_t)r * DKVA + (c4 - DNOPE));
            sK[r * SK_STR + c4 + 0] = to_tf32(v.x);
            sK[r * SK_STR + c4 + 1] = to_tf32(v.y);
            sK[r * SK_STR + c4 + 2] = to_tf32(v.z);
            sK[r * SK_STR + c4 + 3] = to_tf32(v.w);
        }
        for (int e = tid; e < DV * (FN / 4); e += 256) {
            int c  = e & 127;
            int rg = e >> 7;
            const float* src = kvbuf + kvb + (size_t)(rg * 4) * KVDIM + DNOPE + c;
            float4 w;
            w.x = to_tf32(src[0]);
            w.y = to_tf32(src[KVDIM]);
            w.z = to_tf32(src[2 * KVDIM]);
            w.w = to_tf32(src[3 * KVDIM]);
            *(float4*)(sVt + c * VT_STR + rg * 4) = w;
        }
        __syncthreads();

        float s[8][4];
#pragma unroll
        for (int nt = 0; nt < 8; nt++)
#pragma unroll
            for (int i = 0; i < 4; i++) s[nt][i] = 0.f;

#pragma unroll 4
        for (int ks = 0; ks < DQK / 8; ks++) {
            const uint32_t kOff = ks * 32;
            uint32_t a[4];
            ldsm_x4(a, qBase + kOff);
#pragma unroll
            for (int nt2 = 0; nt2 < 4; nt2++) {
                uint32_t b4[4];
                ldsm_x4(b4, kBase + nt2 * (16 * SK_STR * 4) + kOff);
                mma_tf32(s[nt2 * 2],     a, &b4[0]);
                mma_tf32(s[nt2 * 2 + 1], a, &b4[2]);
            }
        }

        if (kt * FN + FN - 1 > q0) {
            const int gr0 = q0 + wrow + g;
            const int gr1 = gr0 + 8;
#pragma unroll
            for (int nt = 0; nt < 8; nt++) {
                int gc = kt * FN + nt * 8 + 2 * tg;
                if (gc     > gr0) s[nt][0] = -1e30f;
                if (gc + 1 > gr0) s[nt][1] = -1e30f;
                if (gc     > gr1) s[nt][2] = -1e30f;
                if (gc + 1 > gr1) s[nt][3] = -1e30f;
            }
        }

        float mx0 = -1e30f, mx1 = -1e30f;
#pragma unroll
        for (int nt = 0; nt < 8; nt++) {
            mx0 = fmaxf(mx0, fmaxf(s[nt][0], s[nt][1]));
            mx1 = fmaxf(mx1, fmaxf(s[nt][2], s[nt][3]));
        }
#pragma unroll
        for (int o_ = 1; o_ < 4; o_ <<= 1) {
            mx0 = fmaxf(mx0, __shfl_xor_sync(0xffffffffu, mx0, o_));
            mx1 = fmaxf(mx1, __shfl_xor_sync(0xffffffffu, mx1, o_));
        }
        const float mn0 = fmaxf(m0, mx0);
        const float mn1 = fmaxf(m1, mx1);
        const float sc0 = __expf(m0 - mn0);
        const float sc1 = __expf(m1 - mn1);
        float rs0 = 0.f, rs1 = 0.f;
#pragma unroll
        for (int nt = 0; nt < 8; nt++) {
            s[nt][0] = __expf(s[nt][0] - mn0);
            s[nt][1] = __expf(s[nt][1] - mn0);
            s[nt][2] = __expf(s[nt][2] - mn1);
            s[nt][3] = __expf(s[nt][3] - mn1);
            rs0 += s[nt][0] + s[nt][1];
            rs1 += s[nt][2] + s[nt][3];
        }
#pragma unroll
        for (int o_ = 1; o_ < 4; o_ <<= 1) {
            rs0 += __shfl_xor_sync(0xffffffffu, rs0, o_);
            rs1 += __shfl_xor_sync(0xffffffffu, rs1, o_);
        }
        l0 = l0 * sc0 + rs0;  m0 = mn0;
        l1 = l1 * sc1 + rs1;  m1 = mn1;
#pragma unroll
        for (int nt = 0; nt < 16; nt++) {
            o[nt][0] *= sc0; o[nt][1] *= sc0;
            o[nt][2] *= sc1; o[nt][3] *= sc1;
        }
#pragma unroll
        for (int nt = 0; nt < 8; nt++) {
            int col = nt * 8 + 2 * tg;
            sP[(wrow + g    ) * SP_STR + col]     = to_tf32(s[nt][0]);
            sP[(wrow + g    ) * SP_STR + col + 1] = to_tf32(s[nt][1]);
            sP[(wrow + g + 8) * SP_STR + col]     = to_tf32(s[nt][2]);
            sP[(wrow + g + 8) * SP_STR + col + 1] = to_tf32(s[nt][3]);
        }
        __syncwarp();

#pragma unroll 2
        for (int ks = 0; ks < FN / 8; ks++) {
            const uint32_t kOff = ks * 32;
            uint32_t a[4];
            ldsm_x4(a, pBase + kOff);
#pragma unroll
            for (int nt2 = 0; nt2 < 8; nt2++) {
                uint32_t b4[4];
                ldsm_x4(b4, vBase + nt2 * (16 * VT_STR * 4) + kOff);
                mma_tf32(o[nt2 * 2],     a, &b4[0]);
                mma_tf32(o[nt2 * 2 + 1], a, &b4[2]);
            }
        }
    }

    const float inv0 = 1.f / l0, inv1 = 1.f / l1;
    const size_t obase = ((size_t)(b * SEQ + q0)) * ODIM + (size_t)h * DV;
    const size_t r0 = obase + (size_t)(wrow + g) * ODIM;
    const size_t r1 = obase + (size_t)(wrow + g + 8) * ODIM;
#pragma unroll
    for (int nt = 0; nt < 16; nt++) {
        int col = nt * 8 + 2 * tg;
        *(float2*)(attn_out + r0 + col) = make_float2(to_tf32(o[nt][0] * inv0), to_tf32(o[nt][1] * inv0));
        *(float2*)(attn_out + r1 + col) = make_float2(to_tf32(o[nt][2] * inv1), to_tf32(o[nt][3] * inv1));
    }
}

// ---------------- launch ----------------
extern "C" void kernel_launch(void* const* d_in, const int* in_sizes, int n_in,
                              void* d_out, int out_size)
{
    (void)in_sizes; (void)n_in; (void)out_size;
    const float* hidden  = (const float*)d_in[0];
    const float* cosb    = (const float*)d_in[1];
    const float* sinb    = (const float*)d_in[2];
    const float* q_a_W   = (const float*)d_in[3];
    const float* q_a_nw  = (const float*)d_in[4];
    const float* q_b_W   = (const float*)d_in[5];
    const float* kv_a_W  = (const float*)d_in[6];
    const float* kv_a_nw = (const float*)d_in[7];
    const float* kv_b_W  = (const float*)d_in[8];
    const float* o_W     = (const float*)d_in[9];
    float* out = (float*)d_out;

    float *qa, *ckv, *kvn, *qbuf, *kvbuf, *attn;
    float *hid_r, *w_qa, *w_kva, *w_qb, *w_kvb, *w_o;
    cudaGetSymbolAddress((void**)&qa,    g_qa);
    cudaGetSymbolAddress((void**)&ckv,   g_ckv);
    cudaGetSymbolAddress((void**)&kvn,   g_kvn);
    cudaGetSymbolAddress((void**)&qbuf,  g_q);
    cudaGetSymbolAddress((void**)&kvbuf, g_kv);
    cudaGetSymbolAddress((void**)&attn,  g_attn);
    cudaGetSymbolAddress((void**)&hid_r, g_hid_r);
    cudaGetSymbolAddress((void**)&w_qa,  g_w_qa);
    cudaGetSymbolAddress((void**)&w_kva, g_w_kva);
    cudaGetSymbolAddress((void**)&w_qb,  g_w_qb);
    cudaGetSymbolAddress((void**)&w_kvb, g_w_kvb);
    cudaGetSymbolAddress((void**)&w_o,   g_w_o);

    cudaFuncSetAttribute(gemm_tf32, cudaFuncAttributeMaxDynamicSharedMemorySize, GEMM_SMEM);
    cudaFuncSetAttribute(gemm_dual, cudaFuncAttributeMaxDynamicSharedMemorySize, GEMM_SMEM);
    cudaFuncSetAttribute(flash_tf32_kernel, cudaFuncAttributeMaxDynamicSharedMemorySize, FLASH_SMEM);

    // launch 0: ONE fused tf32 rna-rounding pass over all GEMM inputs
    {
        const int n0 = (int)((size_t)NTOK * DMODEL / 4);
        const int n1 = (int)((size_t)DQA * DMODEL / 4);
        const int n2 = (int)((size_t)DKVA * DMODEL / 4);
        const int n3 = (int)((size_t)QDIM * DQA / 4);
        const int n4 = (int)((size_t)KVDIM * DKVLAT / 4);
        const int n5 = (int)((size_t)DMODEL * ODIM / 4);
        const int total = n0 + n1 + n2 + n3 + n4 + n5;
        round_all_kernel<<<(total + 255) / 256, 256>>>(
            hidden, hid_r, n0,  q_a_W, w_qa, n1,  kv_a_W, w_kva, n2,
            q_b_W,  w_qb, n3,   kv_b_W, w_kvb, n4, o_W,    w_o,  n5);
    }

    // launch 1: FUSED q_a ∪ kv_a  (both A=hid_r, K=2048; shares L2 on A)
    {
        const int gx1 = DQA / TBN;                       // 12
        const int nt1 = gx1 * (NTOK / TBM);              // 384
        const int gx2 = (DKVA + TBN - 1) / TBN;          // 5
        const int nt2 = gx2 * (NTOK / TBM);              // 160
        gemm_dual<<<nt1 + nt2, 256, GEMM_SMEM>>>(
            hid_r, w_qa, qa, DQA, DMODEL, nt1, gx1,
            hid_r, w_kva, ckv, DKVA, DMODEL, gx2);
    }

    // launch 2: FUSED rmsnorm (q_a in place) ∪ rmsnorm (kv latent -> kvn)
    rmsnorm_dual_kernel<<<2 * NTOK, 256>>>(
        qa, qa, q_a_nw, DQA, DQA, DQA, NTOK,
        ckv, kvn, kv_a_nw, DKVLAT, DKVA, DKVLAT);

    // launch 3: FUSED q_b ∪ kv_b  (long-K q_b tiles scheduled first)
    {
        const int gx1 = QDIM / TBN;                      // 24
        const int nt1 = gx1 * (NTOK / TBM);              // 768
        const int gx2 = KVDIM / TBN;                     // 32
        const int nt2 = gx2 * (NTOK / TBM);              // 1024
        gemm_dual<<<nt1 + nt2, 256, GEMM_SMEM>>>(
            qa, w_qb, qbuf, QDIM, DQA, nt1, gx1,
            kvn, w_kvb, kvbuf, KVDIM, DKVLAT, gx2);
    }

    // launch 4: RoPE in place
    rope_kernel<<<NTOK, 512>>>(qbuf, ckv, cosb, sinb);
    // launch 5 (profiler window): flash attention
    flash_tf32_kernel<<<dim3(SEQ / FM, HEADS, BATCH), 256, FLASH_SMEM>>>(qbuf, kvbuf, ckv, attn);
    // launch 6: out = attn @ o_W^T
    gemm_tf32<<<dim3(DMODEL / TBN, NTOK / TBM), 256, GEMM_SMEM>>>(attn, w_o, out, NTOK, DMODEL, ODIM);
}

// round 14
// speedup vs baseline: 7.3833x; 1.2044x over previous
#include <cuda_runtime.h>
#include <cuda_bf16.h>
#include <math.h>
#include <stdint.h>

// ---------------- problem constants ----------------
#define BATCH   2
#define SEQ     2048
#define NTOK    (BATCH * SEQ)        // 4096
#define DMODEL  2048
#define HEADS   16
#define DQK     192
#define DNOPE   128
#define DROPE   64
#define DV      128
#define DQA     1536
#define DKVA    576
#define DKVLAT  512
#define QDIM    (HEADS * DQK)        // 3072
#define KVDIM   (HEADS * (DNOPE + DV)) // 4096
#define ODIM    (HEADS * DV)         // 2048
#define ATT_SCALE 0.07216878364870322f

// ---------------- scratch ----------------
__device__ float g_qa  [(size_t)NTOK * DQA];
__device__ float g_ckv [(size_t)NTOK * DKVA];
__device__ float g_kvn [(size_t)NTOK * DKVLAT];
__device__ float g_q   [(size_t)NTOK * QDIM];
__device__ float g_kv  [(size_t)NTOK * KVDIM];
__device__ float g_attn[(size_t)NTOK * ODIM];
// tf32-rounded copies (GEMM inner loop consumes raw bits; round upstream)
__device__ float g_hid_r [(size_t)NTOK * DMODEL];
__device__ float g_w_qa  [(size_t)DQA * DMODEL];
__device__ float g_w_kva [(size_t)DKVA * DMODEL];
__device__ float g_w_qb  [(size_t)QDIM * DQA];
__device__ float g_w_kvb [(size_t)KVDIM * DKVLAT];
__device__ float g_w_o   [(size_t)DMODEL * ODIM];

// ---------------- helpers ----------------
__device__ __forceinline__ float to_tf32(float x) {
    float y;
    asm("cvt.rna.tf32.f32 %0, %1;" : "=f"(y) : "f"(x));
    return y;
}

__device__ __forceinline__ uint32_t smem_u32(const void* p) {
    uint32_t a;
    asm("{ .reg .u64 t; cvta.to.shared.u64 t, %1; cvt.u32.u64 %0, t; }" : "=r"(a) : "l"(p));
    return a;
}

__device__ __forceinline__ void mma_tf32(float c[4], const uint32_t a[4], const uint32_t b[2]) {
    asm volatile(
        "mma.sync.aligned.m16n8k8.row.col.f32.tf32.tf32.f32 "
        "{%0,%1,%2,%3}, {%4,%5,%6,%7}, {%8,%9}, {%0,%1,%2,%3};\n"
        : "+f"(c[0]), "+f"(c[1]), "+f"(c[2]), "+f"(c[3])
        : "r"(a[0]), "r"(a[1]), "r"(a[2]), "r"(a[3]), "r"(b[0]), "r"(b[1]));
}

__device__ __forceinline__ void ldsm_x4(uint32_t r[4], uint32_t addr) {
    asm volatile("ldmatrix.sync.aligned.m8n8.x4.shared.b16 {%0,%1,%2,%3}, [%4];"
        : "=r"(r[0]), "=r"(r[1]), "=r"(r[2]), "=r"(r[3]) : "r"(addr));
}

// ---------------- unified dynamic smem ----------------
extern __shared__ char dynsm[];

// ============================================================================
// TF32 GEMM tile body (mma.sync + ldmatrix, 3-stage cp.async pipeline)
// Computes C[bm:bm+128, bn:bn+128] = A[bm:,:K] @ B[bn:,:K]^T
// Inputs MUST be pre-rounded to tf32 (rna). If do_round, output is rna-rounded.
// ============================================================================
#define TBM 128
#define TBN 128
#define TBK 32
#define ASTR 36                          // row stride 144B -> ldmatrix conflict-free
#define NSTG 3
#define STG_FLOATS (TBM * ASTR + TBN * ASTR)   // 9216 floats per stage
#define GEMM_SMEM (NSTG * STG_FLOATS * (int)sizeof(float))  // 110592 B

__device__ __forceinline__ void gemm_tile_body(
    const float* __restrict__ A, const float* __restrict__ Bw,
    float* __restrict__ C, int N, int K, int bm, int bn, int do_round)
{
    float* sm = (float*)dynsm;
    const int tid = threadIdx.x;
    const int wid = tid >> 5, lane = tid & 31;
    const int g = lane >> 2, tg = lane & 3;
    const int wm = (wid >> 2) * 64, wn = (wid & 3) * 32;
    const int NK = K / TBK;

    const int aRowOff = (wm + ((lane >> 3) & 1) * 8 + (lane & 7)) * ASTR + (lane >> 4) * 4;
    const int bRowOff = (wn + (lane >> 4) * 8 + (lane & 7)) * ASTR + ((lane >> 3) & 1) * 4;

#define LOAD_STAGE(c)                                                             \
    {                                                                             \
        const int s_ = (c) % NSTG;                                                \
        float* as_ = sm + s_ * STG_FLOATS;                                        \
        float* bs_ = as_ + TBM * ASTR;                                            \
        _Pragma("unroll")                                                         \
        for (int t_ = 0; t_ < 4; t_++) {                                          \
            int idx_ = tid + t_ * 256;                                            \
            int row_ = idx_ >> 3;                                                 \
            int c4_ = (idx_ & 7) * 4;                                             \
            uint32_t d_ = smem_u32(as_ + row_ * ASTR + c4_);                      \
            const float* s1_ = A + (size_t)(bm + row_) * K + (size_t)(c) * TBK + c4_; \
            asm volatile("cp.async.cg.shared.global.L2::256B [%0], [%1], 16;"     \
                         :: "r"(d_), "l"(s1_));                                   \
        }                                                                         \
        _Pragma("unroll")                                                         \
        for (int t_ = 0; t_ < 4; t_++) {                                          \
            int idx_ = tid + t_ * 256;                                            \
            int row_ = idx_ >> 3;                                                 \
            int c4_ = (idx_ & 7) * 4;                                             \
            int nr_ = bn + row_;                                                  \
            uint32_t d_ = smem_u32(bs_ + row_ * ASTR + c4_);                      \
            const float* s1_ = Bw + (size_t)(nr_ < N ? nr_ : 0) * K + (size_t)(c) * TBK + c4_; \
            unsigned sz_ = (nr_ < N) ? 16u : 0u;                                  \
            asm volatile("cp.async.cg.shared.global.L2::256B [%0], [%1], 16, %2;" \
                         :: "r"(d_), "l"(s1_), "r"(sz_));                         \
        }                                                                         \
        asm volatile("cp.async.commit_group;" ::: "memory");                      \
    }

    float acc[4][4][4];
#pragma unroll
    for (int mt = 0; mt < 4; mt++)
#pragma unroll
        for (int nt = 0; nt < 4; nt++)
#pragma unroll
            for (int i = 0; i < 4; i++) acc[mt][nt][i] = 0.f;

    LOAD_STAGE(0);
    LOAD_STAGE(1);

    for (int cc = 0; cc < NK; cc++) {
        asm volatile("cp.async.wait_group 1;" ::: "memory");
        __syncthreads();
        if (cc + 2 < NK) LOAD_STAGE(cc + 2);

        const int s = cc % NSTG;
        float* as_ = sm + s * STG_FLOATS;
        float* bs_ = as_ + TBM * ASTR;
        const uint32_t aBase = smem_u32(as_ + aRowOff);
        const uint32_t bBase = smem_u32(bs_ + bRowOff);

#pragma unroll
        for (int ks = 0; ks < 4; ks++) {
            const uint32_t kOff = ks * 32;
            uint32_t a[4][4], b[8];
#pragma unroll
            for (int mt = 0; mt < 4; mt++)
                ldsm_x4(a[mt], aBase + mt * (16 * ASTR * 4) + kOff);
            ldsm_x4(&b[0], bBase + kOff);
            ldsm_x4(&b[4], bBase + 16 * ASTR * 4 + kOff);
#pragma unroll
            for (int mt = 0; mt < 4; mt++)
#pragma unroll
                for (int nt = 0; nt < 4; nt++)
                    mma_tf32(acc[mt][nt], a[mt], &b[nt * 2]);
        }
    }

#pragma unroll
    for (int mt = 0; mt < 4; mt++) {
        int r0 = bm + wm + mt * 16 + g;
#pragma unroll
        for (int nt = 0; nt < 4; nt++) {
            int cc = bn + wn + nt * 8 + 2 * tg;
            if (cc < N) {
                float2 v0 = make_float2(acc[mt][nt][0], acc[mt][nt][1]);
                float2 v1 = make_float2(acc[mt][nt][2], acc[mt][nt][3]);
                if (do_round) {
                    v0.x = to_tf32(v0.x); v0.y = to_tf32(v0.y);
                    v1.x = to_tf32(v1.x); v1.y = to_tf32(v1.y);
                }
                *(float2*)(C + (size_t)r0 * N + cc)       = v0;
                *(float2*)(C + (size_t)(r0 + 8) * N + cc) = v1;
            }
        }
    }
#undef LOAD_STAGE
}

// single GEMM launch
__global__ __launch_bounds__(256, 2) void gemm_tf32(
    const float* __restrict__ A, const float* __restrict__ Bw,
    float* __restrict__ C, int M, int N, int K, int do_round)
{
    (void)M;
    gemm_tile_body(A, Bw, C, N, K, blockIdx.y * TBM, blockIdx.x * TBN, do_round);
}

// fused dual GEMM (flattened 1-D grid; blockIdx selects GEMM + tile)
__global__ __launch_bounds__(256, 2) void gemm_dual(
    const float* __restrict__ A1, const float* __restrict__ B1, float* __restrict__ C1,
    int N1, int K1, int ntiles1, int gx1, int round1,
    const float* __restrict__ A2, const float* __restrict__ B2, float* __restrict__ C2,
    int N2, int K2, int gx2, int round2)
{
    int t = blockIdx.x;
    const float *A, *Bw;
    float* C;
    int N, K, bm, bn, rnd;
    if (t < ntiles1) {
        A = A1; Bw = B1; C = C1; N = N1; K = K1; rnd = round1;
        bn = (t % gx1) * TBN; bm = (t / gx1) * TBM;
    } else {
        t -= ntiles1;
        A = A2; Bw = B2; C = C2; N = N2; K = K2; rnd = round2;
        bn = (t % gx2) * TBN; bm = (t / gx2) * TBM;
    }
    gemm_tile_body(A, Bw, C, N, K, bm, bn, rnd);
}

// ---------------- fused tf32 pre-rounding pass (ALL buffers, one launch) ---
__device__ __forceinline__ void round4(const float* in, float* out, int i) {
    float4 v = ((const float4*)in)[i];
    v.x = to_tf32(v.x); v.y = to_tf32(v.y);
    v.z = to_tf32(v.z); v.w = to_tf32(v.w);
    ((float4*)out)[i] = v;
}

__global__ __launch_bounds__(256) void round_all_kernel(
    const float* s0, float* d0, int n0,
    const float* s1, float* d1, int n1,
    const float* s2, float* d2, int n2,
    const float* s3, float* d3, int n3,
    const float* s4, float* d4, int n4,
    const float* s5, float* d5, int n5)
{
    int i = blockIdx.x * 256 + threadIdx.x;
    if (i < n0) { round4(s0, d0, i); return; }  i -= n0;
    if (i < n1) { round4(s1, d1, i); return; }  i -= n1;
    if (i < n2) { round4(s2, d2, i); return; }  i -= n2;
    if (i < n3) { round4(s3, d3, i); return; }  i -= n3;
    if (i < n4) { round4(s4, d4, i); return; }  i -= n4;
    if (i < n5) { round4(s5, d5, i); }
}

// ---------------- fused dual RMSNorm (tf32-rounded output) -----------------
__global__ __launch_bounds__(256) void rmsnorm_dual_kernel(
    const float* __restrict__ in1, float* __restrict__ out1,
    const float* __restrict__ w1, int N1, int is1, int os1, int rows1,
    const float* __restrict__ in2, float* __restrict__ out2,
    const float* __restrict__ w2, int N2, int is2, int os2)
{
    const float* in;  float* out;  const float* w;
    int N, in_stride, out_stride, row = blockIdx.x;
    if (row < rows1) { in = in1; out = out1; w = w1; N = N1; in_stride = is1; out_stride = os1; }
    else { row -= rows1; in = in2; out = out2; w = w2; N = N2; in_stride = is2; out_stride = os2; }

    const float* x = in + (size_t)row * in_stride;
    const int cnt = N >> 8;
    float v[6];
    float ss = 0.f;
    for (int i = 0; i < cnt; i++) {
        v[i] = x[threadIdx.x + (i << 8)];
        ss += v[i] * v[i];
    }
#pragma unroll
    for (int o = 16; o > 0; o >>= 1) ss += __shfl_xor_sync(0xffffffffu, ss, o);
    __shared__ float red[8];
    if ((threadIdx.x & 31) == 0) red[threadIdx.x >> 5] = ss;
    __syncthreads();
    float tot = 0.f;
#pragma unroll
    for (int i = 0; i < 8; i++) tot += red[i];
    const float r = rsqrtf(tot / (float)N + 1e-6f);
    float* y = out + (size_t)row * out_stride;
    for (int i = 0; i < cnt; i++) {
        int c = threadIdx.x + (i << 8);
        y[c] = to_tf32(w[c] * v[i] * r);
    }
}

// ---------------- RoPE (ckv slice written tf32-rounded; q slice raw) -------
__global__ __launch_bounds__(512) void rope_kernel(
    float* __restrict__ q, float* __restrict__ ckv,
    const float* __restrict__ cosb, const float* __restrict__ sinb)
{
    const int tok = blockIdx.x;
    const int t = threadIdx.x;
    const int h = t >> 5;
    const int d = t & 31;
    const float c0 = cosb[(size_t)tok * DROPE + d];
    const float s0 = sinb[(size_t)tok * DROPE + d];
    const float c1 = cosb[(size_t)tok * DROPE + d + 32];
    const float s1 = sinb[(size_t)tok * DROPE + d + 32];
    {
        float* qr = q + (size_t)tok * QDIM + h * DQK + DNOPE;
        float a = qr[d], b = qr[d + 32];
        qr[d]      = a * c0 - b * s0;
        qr[d + 32] = b * c1 + a * s1;
    }
    if (t < 32) {
        float* kr = ckv + (size_t)tok * DKVA + DKVLAT;
        float a = kr[d], b = kr[d + 32];
        kr[d]      = to_tf32(a * c0 - b * s0);   // consumed raw by flash K (cp.async)
        kr[d + 32] = to_tf32(b * c1 + a * s1);
    }
}

// ---------------- Flash attention v3 -----------------------------------
// FM=128, FN=32, cp.async double-buffered K/V (pre-rounded in gmem),
// Q loaded synchronously (scaled+rounded, unchanged numerics).
#define FM 128
#define FN 32
#define SQ_STR 196   // %32 == 4
#define SK_STR 196   // %32 == 4
#define SV_STR 136   // natural V [k][dv], %32 == 8 (scalar-B conflict-free)
#define SP_STR 36    // %32 == 4
#define FLASH_SMEM ((FM * SQ_STR + 2 * FN * SK_STR + 2 * FN * SV_STR + FM * SP_STR) * (int)sizeof(float))  // 203776

__global__ __launch_bounds__(256) void flash_tf32_kernel(
    const float* __restrict__ q, const float* __restrict__ kvbuf,
    const float* __restrict__ ckv, float* __restrict__ attn_out)
{
    float* fsmem = (float*)dynsm;
    float* sQ = fsmem;                        // 128 x 196
    float* sK = sQ + FM * SQ_STR;             // 2 x 32 x 196
    float* sV = sK + 2 * FN * SK_STR;         // 2 x 32 x 136
    float* sP = sV + 2 * FN * SV_STR;         // 128 x 36

    const int bq = gridDim.x - 1 - blockIdx.x;   // longest tiles first
    const int h  = blockIdx.y;
    const int b  = blockIdx.z;
    const int q0 = bq * FM;
    const int tid = threadIdx.x;
    const int wid = tid >> 5, lane = tid & 31;
    const int g = lane >> 2, tg = lane & 3;
    const int wrow = wid * 16;

    const int aSel = ((lane >> 3) & 1) * 8 + (lane & 7);
    const int aCol = (lane >> 4) * 4;
    const int bSel = (lane >> 4) * 8 + (lane & 7);
    const int bCol = ((lane >> 3) & 1) * 4;

    const uint32_t qBase = smem_u32(sQ + (wrow + aSel) * SQ_STR + aCol);
    const uint32_t pBase = smem_u32(sP + (wrow + aSel) * SP_STR + aCol);
    const int kRowOff = bSel * SK_STR + bCol;

    // K tile (32 x 192 raw) + V tile (32 x 128 raw) via cp.async
#define LOAD_KV(kt, buf)                                                          \
    {                                                                             \
        float* sKb_ = sK + (buf) * (FN * SK_STR);                                 \
        float* sVb_ = sV + (buf) * (FN * SV_STR);                                 \
        const size_t kvb_ = ((size_t)(b * SEQ + (kt) * FN)) * KVDIM + (size_t)h * (DNOPE + DV); \
        const size_t ckb_ = ((size_t)(b * SEQ + (kt) * FN)) * DKVA + DKVLAT;      \
        _Pragma("unroll")                                                         \
        for (int t_ = 0; t_ < 6; t_++) {                                          \
            int idx_ = tid + t_ * 256;                                            \
            int row_ = idx_ / 48;                                                 \
            int c4_ = (idx_ % 48) * 4;                                            \
            uint32_t d_ = smem_u32(sKb_ + row_ * SK_STR + c4_);                   \
            const float* s_ = (c4_ < DNOPE)                                       \
                ? kvbuf + kvb_ + (size_t)row_ * KVDIM + c4_                       \
                : ckv + ckb_ + (size_t)row_ * DKVA + (c4_ - DNOPE);               \
            asm volatile("cp.async.cg.shared.global [%0], [%1], 16;"              \
                         :: "r"(d_), "l"(s_));                                    \
        }                                                                         \
        _Pragma("unroll")                                                         \
        for (int t_ = 0; t_ < 4; t_++) {                                          \
            int idx_ = tid + t_ * 256;                                            \
            int row_ = idx_ >> 5;                                                 \
            int c4_ = (idx_ & 31) * 4;                                            \
            uint32_t d_ = smem_u32(sVb_ + row_ * SV_STR + c4_);                   \
            const float* s_ = kvbuf + kvb_ + (size_t)row_ * KVDIM + DNOPE + c4_;  \
            asm volatile("cp.async.cg.shared.global [%0], [%1], 16;"              \
                         :: "r"(d_), "l"(s_));                                    \
        }                                                                         \
        asm volatile("cp.async.commit_group;" ::: "memory");                      \
    }

    // Q tile (scaled + rounded; numerics unchanged from previous rounds)
    const size_t qbase = ((size_t)(b * SEQ + q0)) * QDIM + (size_t)h * DQK;
    for (int e = tid; e < FM * (DQK / 4); e += 256) {
        int r = e / (DQK / 4), c4 = (e - r * (DQK / 4)) * 4;
        float4 v = *(const float4*)(q + qbase + (size_t)r * QDIM + c4);
        sQ[r * SQ_STR + c4 + 0] = to_tf32(v.x * ATT_SCALE);
        sQ[r * SQ_STR + c4 + 1] = to_tf32(v.y * ATT_SCALE);
        sQ[r * SQ_STR + c4 + 2] = to_tf32(v.z * ATT_SCALE);
        sQ[r * SQ_STR + c4 + 3] = to_tf32(v.w * ATT_SCALE);
    }

    float o[16][4];
#pragma unroll
    for (int nt = 0; nt < 16; nt++)
#pragma unroll
        for (int i = 0; i < 4; i++) o[nt][i] = 0.f;
    float m0 = -1e30f, m1 = -1e30f, l0 = 0.f, l1 = 0.f;

    const int nkt = (q0 + FM) / FN;
    LOAD_KV(0, 0);

    for (int kt = 0; kt < nkt; kt++) {
        __syncthreads();   // all warps done with buffer (kt+1)&1 from iter kt-1
        if (kt + 1 < nkt) {
            LOAD_KV(kt + 1, (kt + 1) & 1);
            asm volatile("cp.async.wait_group 1;" ::: "memory");
        } else {
            asm volatile("cp.async.wait_group 0;" ::: "memory");
        }
        __syncthreads();   // tile kt visible to all warps (and Q on kt==0)

        float* sKb = sK + (kt & 1) * (FN * SK_STR);
        float* sVb = sV + (kt & 1) * (FN * SV_STR);
        const uint32_t kBase = smem_u32(sKb + kRowOff);

        // ---- S = Q K^T : warp 16 x 32 (4 n-tiles) ----
        float s[4][4];
#pragma unroll
        for (int nt = 0; nt < 4; nt++)
#pragma unroll
            for (int i = 0; i < 4; i++) s[nt][i] = 0.f;

#pragma unroll 4
        for (int ks = 0; ks < DQK / 8; ks++) {
            const uint32_t kOff = ks * 32;
            uint32_t a[4];
            ldsm_x4(a, qBase + kOff);
#pragma unroll
            for (int nt2 = 0; nt2 < 2; nt2++) {
                uint32_t b4[4];
                ldsm_x4(b4, kBase + nt2 * (16 * SK_STR * 4) + kOff);
                mma_tf32(s[nt2 * 2],     a, &b4[0]);
                mma_tf32(s[nt2 * 2 + 1], a, &b4[2]);
            }
        }

        if (kt * FN + FN - 1 > q0) {
            const int gr0 = q0 + wrow + g;
            const int gr1 = gr0 + 8;
#pragma unroll
            for (int nt = 0; nt < 4; nt++) {
                int gc = kt * FN + nt * 8 + 2 * tg;
                if (gc     > gr0) s[nt][0] = -1e30f;
                if (gc + 1 > gr0) s[nt][1] = -1e30f;
                if (gc     > gr1) s[nt][2] = -1e30f;
                if (gc + 1 > gr1) s[nt][3] = -1e30f;
            }
        }

        // ---- online softmax ----
        float mx0 = -1e30f, mx1 = -1e30f;
#pragma unroll
        for (int nt = 0; nt < 4; nt++) {
            mx0 = fmaxf(mx0, fmaxf(s[nt][0], s[nt][1]));
            mx1 = fmaxf(mx1, fmaxf(s[nt][2], s[nt][3]));
        }
#pragma unroll
        for (int o_ = 1; o_ < 4; o_ <<= 1) {
            mx0 = fmaxf(mx0, __shfl_xor_sync(0xffffffffu, mx0, o_));
            mx1 = fmaxf(mx1, __shfl_xor_sync(0xffffffffu, mx1, o_));
        }
        const float mn0 = fmaxf(m0, mx0);
        const float mn1 = fmaxf(m1, mx1);
        const float sc0 = __expf(m0 - mn0);
        const float sc1 = __expf(m1 - mn1);
        float rs0 = 0.f, rs1 = 0.f;
#pragma unroll
        for (int nt = 0; nt < 4; nt++) {
            s[nt][0] = __expf(s[nt][0] - mn0);
            s[nt][1] = __expf(s[nt][1] - mn0);
            s[nt][2] = __expf(s[nt][2] - mn1);
            s[nt][3] = __expf(s[nt][3] - mn1);
            rs0 += s[nt][0] + s[nt][1];
            rs1 += s[nt][2] + s[nt][3];
        }
#pragma unroll
        for (int o_ = 1; o_ < 4; o_ <<= 1) {
            rs0 += __shfl_xor_sync(0xffffffffu, rs0, o_);
            rs1 += __shfl_xor_sync(0xffffffffu, rs1, o_);
        }
        l0 = l0 * sc0 + rs0;  m0 = mn0;
        l1 = l1 * sc1 + rs1;  m1 = mn1;
#pragma unroll
        for (int nt = 0; nt < 16; nt++) {
            o[nt][0] *= sc0; o[nt][1] *= sc0;
            o[nt][2] *= sc1; o[nt][3] *= sc1;
        }
#pragma unroll
        for (int nt = 0; nt < 4; nt++) {
            int col = nt * 8 + 2 * tg;
            sP[(wrow + g    ) * SP_STR + col]     = to_tf32(s[nt][0]);
            sP[(wrow + g    ) * SP_STR + col + 1] = to_tf32(s[nt][1]);
            sP[(wrow + g + 8) * SP_STR + col]     = to_tf32(s[nt][2]);
            sP[(wrow + g + 8) * SP_STR + col + 1] = to_tf32(s[nt][3]);
        }
        __syncwarp();

        // ---- O += P V : 16 n-tiles over DV, K=32 (P via ldmatrix, V scalar) ----
#pragma unroll
        for (int ks = 0; ks < FN / 8; ks++) {
            const int kb = ks * 8;
            uint32_t a[4];
            ldsm_x4(a, pBase + ks * 32);
#pragma unroll
            for (int nt = 0; nt < 16; nt++) {
                uint32_t bb[2];
                bb[0] = __float_as_uint(sVb[(kb + tg    ) * SV_STR + nt * 8 + g]);
                bb[1] = __float_as_uint(sVb[(kb + tg + 4) * SV_STR + nt * 8 + g]);
                mma_tf32(o[nt], a, bb);
            }
        }
    }

    // epilogue: tf32-rounded (feeds o-proj GEMM which consumes raw bits)
    const float inv0 = 1.f / l0, inv1 = 1.f / l1;
    const size_t obase = ((size_t)(b * SEQ + q0)) * ODIM + (size_t)h * DV;
    const size_t r0 = obase + (size_t)(wrow + g) * ODIM;
    const size_t r1 = obase + (size_t)(wrow + g + 8) * ODIM;
#pragma unroll
    for (int nt = 0; nt < 16; nt++) {
        int col = nt * 8 + 2 * tg;
        *(float2*)(attn_out + r0 + col) = make_float2(to_tf32(o[nt][0] * inv0), to_tf32(o[nt][1] * inv0));
        *(float2*)(attn_out + r1 + col) = make_float2(to_tf32(o[nt][2] * inv1), to_tf32(o[nt][3] * inv1));
    }
}

// ---------------- launch ----------------
extern "C" void kernel_launch(void* const* d_in, const int* in_sizes, int n_in,
                              void* d_out, int out_size)
{
    (void)in_sizes; (void)n_in; (void)out_size;
    const float* hidden  = (const float*)d_in[0];
    const float* cosb    = (const float*)d_in[1];
    const float* sinb    = (const float*)d_in[2];
    const float* q_a_W   = (const float*)d_in[3];
    const float* q_a_nw  = (const float*)d_in[4];
    const float* q_b_W   = (const float*)d_in[5];
    const float* kv_a_W  = (const float*)d_in[6];
    const float* kv_a_nw = (const float*)d_in[7];
    const float* kv_b_W  = (const float*)d_in[8];
    const float* o_W     = (const float*)d_in[9];
    float* out = (float*)d_out;

    float *qa, *ckv, *kvn, *qbuf, *kvbuf, *attn;
    float *hid_r, *w_qa, *w_kva, *w_qb, *w_kvb, *w_o;
    cudaGetSymbolAddress((void**)&qa,    g_qa);
    cudaGetSymbolAddress((void**)&ckv,   g_ckv);
    cudaGetSymbolAddress((void**)&kvn,   g_kvn);
    cudaGetSymbolAddress((void**)&qbuf,  g_q);
    cudaGetSymbolAddress((void**)&kvbuf, g_kv);
    cudaGetSymbolAddress((void**)&attn,  g_attn);
    cudaGetSymbolAddress((void**)&hid_r, g_hid_r);
    cudaGetSymbolAddress((void**)&w_qa,  g_w_qa);
    cudaGetSymbolAddress((void**)&w_kva, g_w_kva);
    cudaGetSymbolAddress((void**)&w_qb,  g_w_qb);
    cudaGetSymbolAddress((void**)&w_kvb, g_w_kvb);
    cudaGetSymbolAddress((void**)&w_o,   g_w_o);

    cudaFuncSetAttribute(gemm_tf32, cudaFuncAttributeMaxDynamicSharedMemorySize, GEMM_SMEM);
    cudaFuncSetAttribute(gemm_dual, cudaFuncAttributeMaxDynamicSharedMemorySize, GEMM_SMEM);
    cudaFuncSetAttribute(flash_tf32_kernel, cudaFuncAttributeMaxDynamicSharedMemorySize, FLASH_SMEM);

    // launch 0: fused tf32 rna-rounding of all GEMM inputs
    {
        const int n0 = (int)((size_t)NTOK * DMODEL / 4);
        const int n1 = (int)((size_t)DQA * DMODEL / 4);
        const int n2 = (int)((size_t)DKVA * DMODEL / 4);
        const int n3 = (int)((size_t)QDIM * DQA / 4);
        const int n4 = (int)((size_t)KVDIM * DKVLAT / 4);
        const int n5 = (int)((size_t)DMODEL * ODIM / 4);
        const int total = n0 + n1 + n2 + n3 + n4 + n5;
        round_all_kernel<<<(total + 255) / 256, 256>>>(
            hidden, hid_r, n0,  q_a_W, w_qa, n1,  kv_a_W, w_kva, n2,
            q_b_W,  w_qb, n3,   kv_b_W, w_kvb, n4, o_W,    w_o,  n5);
    }

    // launch 1: FUSED q_a ∪ kv_a (outputs raw fp32 -> rmsnorm)
    {
        const int gx1 = DQA / TBN;
        const int nt1 = gx1 * (NTOK / TBM);
        const int gx2 = (DKVA + TBN - 1) / TBN;
        const int nt2 = gx2 * (NTOK / TBM);
        gemm_dual<<<nt1 + nt2, 256, GEMM_SMEM>>>(
            hid_r, w_qa, qa, DQA, DMODEL, nt1, gx1, 0,
            hid_r, w_kva, ckv, DKVA, DMODEL, gx2, 0);
    }

    // launch 2: FUSED dual rmsnorm
    rmsnorm_dual_kernel<<<2 * NTOK, 256>>>(
        qa, qa, q_a_nw, DQA, DQA, DQA, NTOK,
        ckv, kvn, kv_a_nw, DKVLAT, DKVA, DKVLAT);

    // launch 3: FUSED q_b (raw out) ∪ kv_b (tf32-rounded out -> flash cp.async)
    {
        const int gx1 = QDIM / TBN;
        const int nt1 = gx1 * (NTOK / TBM);
        const int gx2 = KVDIM / TBN;
        const int nt2 = gx2 * (NTOK / TBM);
        gemm_dual<<<nt1 + nt2, 256, GEMM_SMEM>>>(
            qa, w_qb, qbuf, QDIM, DQA, nt1, gx1, 0,
            kvn, w_kvb, kvbuf, KVDIM, DKVLAT, gx2, 1);
    }

    // launch 4: RoPE (ckv slice rounded)
    rope_kernel<<<NTOK, 512>>>(qbuf, ckv, cosb, sinb);
    // launch 5 (profiler window): flash attention
    flash_tf32_kernel<<<dim3(SEQ / FM, HEADS, BATCH), 256, FLASH_SMEM>>>(qbuf, kvbuf, ckv, attn);
    // launch 6: out = attn @ o_W^T
    gemm_tf32<<<dim3(DMODEL / TBN, NTOK / TBM), 256, GEMM_SMEM>>>(attn, w_o, out, NTOK, DMODEL, ODIM, 0);
}